// round 7
// baseline (speedup 1.0000x reference)
#include <cuda_runtime.h>
#include <cuda_bf16.h>
#include <cstdint>

// Problem constants
#define B_  2
#define S_  2048
#define E_  1024
#define H_  16
#define DH_ 64
#define HD_ 1024          // H*Dh
#define M_  (B_*S_)       // 4096 rows for all GEMMs
#define K_GEMM 1024
#define N_GEMM 1024

// ---------------------------------------------------------------------------
// Scratch (no cudaMalloc allowed)
// ---------------------------------------------------------------------------
__device__ __nv_bfloat16 g_Zhi[M_ * K_GEMM];          // attention output hi/lo
__device__ __nv_bfloat16 g_Zlo[M_ * K_GEMM];
__device__ __nv_bfloat16 g_W1t[4 * N_GEMM * K_GEMM];  // 4 transposed+split weights [N][K]
__device__ __nv_bfloat16 g_W2t[4 * N_GEMM * K_GEMM];
__device__ __nv_bfloat16 g_Ihi[3 * M_ * K_GEMM];      // split inputs (query/key/value)
__device__ __nv_bfloat16 g_Ilo[3 * M_ * K_GEMM];
__device__ __nv_bfloat16 g_Qhi[M_ * HD_];
__device__ __nv_bfloat16 g_Qlo[M_ * HD_];
__device__ __nv_bfloat16 g_Khi[M_ * HD_];
__device__ __nv_bfloat16 g_Klo[M_ * HD_];
__device__ __nv_bfloat16 g_Vhi[M_ * HD_];
__device__ __nv_bfloat16 g_Vlo[M_ * HD_];

struct QkvArgs {
    const __nv_bfloat16* Ahi[3];
    const __nv_bfloat16* Alo[3];
    const float* bias[3];
    __nv_bfloat16* Ohi[3];
    __nv_bfloat16* Olo[3];
};
struct PrepArgs { const float* W[4]; };
struct SplitArgs {
    const float* x[3];
    __nv_bfloat16* hi[3];
    __nv_bfloat16* lo[3];
};

__device__ __forceinline__ uint32_t smem_u32(const void* p) {
    uint32_t a;
    asm("{ .reg .u64 t; cvta.to.shared.u64 t, %1; cvt.u32.u64 %0, t; }" : "=r"(a) : "l"(p));
    return a;
}
__device__ __forceinline__ float ex2f(float x) {
    float y;
    asm("ex2.approx.ftz.f32 %0, %1;" : "=f"(y) : "f"(x));
    return y;
}
__device__ __forceinline__ uint32_t pack_bf16(float a, float b) {
    __nv_bfloat162 t = __floats2bfloat162_rn(a, b);
    return *reinterpret_cast<uint32_t*>(&t);
}

#define CP_ASYNC16(dst, src) \
    asm volatile("cp.async.cg.shared.global [%0], [%1], 16;" :: "r"(dst), "l"(src))
#define CP_COMMIT() asm volatile("cp.async.commit_group;" ::: "memory")
#define CP_WAIT(n)  asm volatile("cp.async.wait_group %0;" :: "n"(n) : "memory")

#define LDSM4(r0, r1, r2, r3, addr) \
    asm volatile("ldmatrix.sync.aligned.m8n8.x4.shared.b16 {%0,%1,%2,%3}, [%4];" \
                 : "=r"(r0), "=r"(r1), "=r"(r2), "=r"(r3) : "r"(addr))
#define LDSM4T(r0, r1, r2, r3, addr) \
    asm volatile("ldmatrix.sync.aligned.m8n8.x4.trans.shared.b16 {%0,%1,%2,%3}, [%4];" \
                 : "=r"(r0), "=r"(r1), "=r"(r2), "=r"(r3) : "r"(addr))
#define MMA16816(d, a, b) \
    asm volatile("mma.sync.aligned.m16n8k16.row.col.f32.bf16.bf16.f32 " \
                 "{%0,%1,%2,%3}, {%4,%5,%6,%7}, {%8,%9}, {%0,%1,%2,%3};" \
                 : "+f"((d)[0]), "+f"((d)[1]), "+f"((d)[2]), "+f"((d)[3]) \
                 : "r"((a)[0]), "r"((a)[1]), "r"((a)[2]), "r"((a)[3]), \
                   "r"((b)[0]), "r"((b)[1]))

// ---------------------------------------------------------------------------
// Batched split: fp32 inputs -> hi/lo bf16. grid (n4/256, 1, 3)
// ---------------------------------------------------------------------------
__global__ void __launch_bounds__(256)
split_bf16_kernel(SplitArgs sa, int n4)
{
    int z = blockIdx.z;
    int i = blockIdx.x * blockDim.x + threadIdx.x;
    if (i >= n4) return;
    float4 v = ((const float4*)sa.x[z])[i];
    float h0 = __bfloat162float(__float2bfloat16(v.x));
    float h1 = __bfloat162float(__float2bfloat16(v.y));
    float h2 = __bfloat162float(__float2bfloat16(v.z));
    float h3 = __bfloat162float(__float2bfloat16(v.w));
    uint2 hp, lp;
    hp.x = pack_bf16(h0, h1); hp.y = pack_bf16(h2, h3);
    lp.x = pack_bf16(v.x - h0, v.y - h1);
    lp.y = pack_bf16(v.z - h2, v.w - h3);
    ((uint2*)sa.hi[z])[i] = hp;
    ((uint2*)sa.lo[z])[i] = lp;
}

// ---------------------------------------------------------------------------
// Weight prep (batched): W[K][N] fp32 -> W1t/W2t[z] [N][K] bf16
// ---------------------------------------------------------------------------
__global__ void __launch_bounds__(256)
prep_w_kernel(PrepArgs pa,
              __nv_bfloat16* __restrict__ w1t,
              __nv_bfloat16* __restrict__ w2t)
{
    __shared__ float t[32][33];
    const float* W = pa.W[blockIdx.z];
    const size_t zoff = (size_t)blockIdx.z * N_GEMM * K_GEMM;
    int n0 = blockIdx.x * 32, k0 = blockIdx.y * 32;
    int tx = threadIdx.x, ty = threadIdx.y;
    #pragma unroll
    for (int i = 0; i < 4; i++)
        t[ty + 8 * i][tx] = W[(size_t)(k0 + ty + 8 * i) * N_GEMM + n0 + tx];
    __syncthreads();
    #pragma unroll
    for (int i = 0; i < 4; i++) {
        float v = t[tx][ty + 8 * i];
        __nv_bfloat16 h = __float2bfloat16(v);
        __nv_bfloat16 l = __float2bfloat16(v - __bfloat162float(h));
        size_t o = zoff + (size_t)(n0 + ty + 8 * i) * K_GEMM + k0 + tx;
        w1t[o] = h;
        w2t[o] = l;
    }
}

// ---------------------------------------------------------------------------
// HMMA bf16x3 GEMM with 3-stage cp.async pipeline, TERM-MAJOR MMA ordering.
// ---------------------------------------------------------------------------
#define LDP 80
#define TILE_B (128 * LDP)      // 10240
#define STAGE_B (4 * TILE_B)    // 40960
#define NSTAGE 3

template<int MODE>
__global__ void __launch_bounds__(256)
gemm_bf16x3_pipe(QkvArgs qa,
                 const __nv_bfloat16* __restrict__ Ahi_,
                 const __nv_bfloat16* __restrict__ Alo_,
                 const __nv_bfloat16* __restrict__ W1base,
                 const __nv_bfloat16* __restrict__ W2base,
                 const float* __restrict__ biasO,
                 float* __restrict__ Cout)
{
    extern __shared__ __align__(16) char smem[];
    const uint32_t sb = smem_u32(smem);
    const int z = blockIdx.z;
    const int tid = threadIdx.x;
    const int wid = tid >> 5, lane = tid & 31;
    const int n0 = blockIdx.x * 128, m0 = blockIdx.y * 128;
    const int mw = (wid & 3) * 32;
    const int nw = (wid >> 2) * 64;

    const size_t woff = (MODE == 0 ? (size_t)z : (size_t)3) * N_GEMM * K_GEMM;
    const __nv_bfloat16* gW1 = W1base + woff + (size_t)n0 * K_GEMM;
    const __nv_bfloat16* gW2 = W2base + woff + (size_t)n0 * K_GEMM;
    const __nv_bfloat16* gA1 = (MODE == 0 ? qa.Ahi[z] : Ahi_) + (size_t)m0 * K_GEMM;
    const __nv_bfloat16* gA2 = (MODE == 0 ? qa.Alo[z] : Alo_) + (size_t)m0 * K_GEMM;

    float acc[2][8][4];
    #pragma unroll
    for (int mi = 0; mi < 2; mi++)
        #pragma unroll
        for (int ni = 0; ni < 8; ni++)
            #pragma unroll
            for (int r = 0; r < 4; r++) acc[mi][ni][r] = 0.f;

    const int row_[2] = { tid >> 2, (tid + 256) >> 2 };
    const int cc_[2]  = { tid & 3, (tid + 256) & 3 };

    auto issue_chunk = [&](int c) {
        uint32_t base = sb + (c % NSTAGE) * STAGE_B;
        int k0 = c * 32;
        #pragma unroll
        for (int t = 0; t < 2; t++) {
            int row = row_[t], cc = cc_[t];
            uint32_t so = row * LDP + cc * 16;
            size_t go = (size_t)row * K_GEMM + k0 + cc * 8;
            CP_ASYNC16(base + 0 * TILE_B + so, gA1 + go);
            CP_ASYNC16(base + 1 * TILE_B + so, gA2 + go);
            CP_ASYNC16(base + 2 * TILE_B + so, gW1 + go);
            CP_ASYNC16(base + 3 * TILE_B + so, gW2 + go);
        }
    };

    const uint32_t a_row = mw + (lane & 15);
    const uint32_t a_kadd = (lane >> 4) << 4;
    const uint32_t b_rowbase = nw + (lane & 7) + (((lane >> 4) & 1) << 3);
    const uint32_t b_kadd = ((lane >> 3) & 1) << 4;

    const int NCHUNK = K_GEMM / 32;   // 32
    issue_chunk(0); CP_COMMIT();
    issue_chunk(1); CP_COMMIT();

    for (int c = 0; c < NCHUNK; c++) {
        if (c + 1 < NCHUNK) { CP_WAIT(1); } else { CP_WAIT(0); }
        __syncthreads();
        if (c + 2 < NCHUNK) { issue_chunk(c + 2); CP_COMMIT(); }

        const uint32_t stg = sb + (c % NSTAGE) * STAGE_B;
        const uint32_t sA1 = stg, sA2 = stg + TILE_B;
        const uint32_t sW1 = stg + 2 * TILE_B, sW2 = stg + 3 * TILE_B;

        #pragma unroll
        for (int s = 0; s < 2; s++) {
            const uint32_t kb = s * 32;
            uint32_t a1f[2][4], a2f[2][4];
            #pragma unroll
            for (int mi = 0; mi < 2; mi++) {
                uint32_t addr1 = sA1 + (a_row + mi * 16) * LDP + kb + a_kadd;
                uint32_t addr2 = sA2 + (a_row + mi * 16) * LDP + kb + a_kadd;
                LDSM4(a1f[mi][0], a1f[mi][1], a1f[mi][2], a1f[mi][3], addr1);
                LDSM4(a2f[mi][0], a2f[mi][1], a2f[mi][2], a2f[mi][3], addr2);
            }
            uint32_t b1f[8][2], b2f[8][2];
            #pragma unroll
            for (int g = 0; g < 4; g++) {
                uint32_t addr1 = sW1 + (b_rowbase + g * 16) * LDP + kb + b_kadd;
                uint32_t addr2 = sW2 + (b_rowbase + g * 16) * LDP + kb + b_kadd;
                LDSM4(b1f[2*g][0], b1f[2*g][1], b1f[2*g+1][0], b1f[2*g+1][1], addr1);
                LDSM4(b2f[2*g][0], b2f[2*g][1], b2f[2*g+1][0], b2f[2*g+1][1], addr2);
            }
            // TERM-MAJOR: all 16 accs per term -> same-acc reuse is 16 MMAs apart
            #pragma unroll
            for (int mi = 0; mi < 2; mi++)
                #pragma unroll
                for (int ni = 0; ni < 8; ni++)
                    MMA16816(acc[mi][ni], a1f[mi], b1f[ni]);
            #pragma unroll
            for (int mi = 0; mi < 2; mi++)
                #pragma unroll
                for (int ni = 0; ni < 8; ni++)
                    MMA16816(acc[mi][ni], a1f[mi], b2f[ni]);
            #pragma unroll
            for (int mi = 0; mi < 2; mi++)
                #pragma unroll
                for (int ni = 0; ni < 8; ni++)
                    MMA16816(acc[mi][ni], a2f[mi], b1f[ni]);
        }
        __syncthreads();
    }

    // ---- epilogue ----
    const float* bias = (MODE == 0) ? qa.bias[z] : biasO;
    const int erow = m0 + mw + (lane >> 2);
    const int ecol0 = n0 + nw + (lane & 3) * 2;
    #pragma unroll
    for (int mi = 0; mi < 2; mi++) {
        #pragma unroll
        for (int ni = 0; ni < 8; ni++) {
            int col = ecol0 + ni * 8;
            float b0 = bias[col], b1 = bias[col + 1];
            int r0 = erow + mi * 16;
            float v00 = acc[mi][ni][0] + b0, v01 = acc[mi][ni][1] + b1;
            float v10 = acc[mi][ni][2] + b0, v11 = acc[mi][ni][3] + b1;
            if (MODE == 1) {
                float2 w0 = { v00, v01 }, w1 = { v10, v11 };
                *(float2*)&Cout[(size_t)r0 * N_GEMM + col] = w0;
                *(float2*)&Cout[(size_t)(r0 + 8) * N_GEMM + col] = w1;
            } else {
                __nv_bfloat16* Chi = qa.Ohi[z];
                __nv_bfloat16* Clo = qa.Olo[z];
                float h00 = __bfloat162float(__float2bfloat16(v00));
                float h01 = __bfloat162float(__float2bfloat16(v01));
                float h10 = __bfloat162float(__float2bfloat16(v10));
                float h11 = __bfloat162float(__float2bfloat16(v11));
                *(uint32_t*)&Chi[(size_t)r0 * N_GEMM + col] = pack_bf16(h00, h01);
                *(uint32_t*)&Chi[(size_t)(r0 + 8) * N_GEMM + col] = pack_bf16(h10, h11);
                *(uint32_t*)&Clo[(size_t)r0 * N_GEMM + col] = pack_bf16(v00 - h00, v01 - h01);
                *(uint32_t*)&Clo[(size_t)(r0 + 8) * N_GEMM + col] = pack_bf16(v10 - h10, v11 - h11);
            }
        }
    }
}

// ---------------------------------------------------------------------------
// HMMA flash attention, causal, bf16x3, online softmax, 2-stage cp.async K/V,
// TERM-MAJOR MMA ordering.
// ---------------------------------------------------------------------------
#define LDK 144
#define AT_STAGE 36864
#define OF_KHI 0
#define OF_KLO 9216
#define OF_VHI 18432
#define OF_VLO 27648

__global__ void __launch_bounds__(256)
flash_attn_mma(const __nv_bfloat16* __restrict__ Qhi, const __nv_bfloat16* __restrict__ Qlo,
               const __nv_bfloat16* __restrict__ Khi, const __nv_bfloat16* __restrict__ Klo,
               const __nv_bfloat16* __restrict__ Vhi, const __nv_bfloat16* __restrict__ Vlo,
               __nv_bfloat16* __restrict__ Zhi, __nv_bfloat16* __restrict__ Zlo)
{
    extern __shared__ __align__(16) char sm[];
    const uint32_t sb = smem_u32(sm);
    const int tid = threadIdx.x, wid = tid >> 5, lane = tid & 31;
    const int b = blockIdx.z, h = blockIdx.y, qt = blockIdx.x;
    const int q0 = qt * 128;
    const size_t hb = (size_t)b * S_ * HD_ + h * DH_;

    const uint32_t arow = wid * 16 + (lane & 15);
    const uint32_t akadd = (lane >> 4) << 4;

    // Stage Qhi then Qlo through stage-0 area, ldmatrix into registers.
    uint32_t qh[4][4], ql[4][4];
    #pragma unroll
    for (int t = 0; t < 4; t++) {
        int idx = tid + t * 256; int row = idx >> 3, cc = idx & 7;
        *(float4*)(sm + row * LDK + cc * 16) =
            *(const float4*)&Qhi[hb + (size_t)(q0 + row) * HD_ + cc * 8];
    }
    __syncthreads();
    #pragma unroll
    for (int ks = 0; ks < 4; ks++) {
        uint32_t a = sb + arow * LDK + ks * 32 + akadd;
        LDSM4(qh[ks][0], qh[ks][1], qh[ks][2], qh[ks][3], a);
    }
    __syncthreads();
    #pragma unroll
    for (int t = 0; t < 4; t++) {
        int idx = tid + t * 256; int row = idx >> 3, cc = idx & 7;
        *(float4*)(sm + row * LDK + cc * 16) =
            *(const float4*)&Qlo[hb + (size_t)(q0 + row) * HD_ + cc * 8];
    }
    __syncthreads();
    #pragma unroll
    for (int ks = 0; ks < 4; ks++) {
        uint32_t a = sb + arow * LDK + ks * 32 + akadd;
        LDSM4(ql[ks][0], ql[ks][1], ql[ks][2], ql[ks][3], a);
    }
    __syncthreads();   // Q consumed; stage 0 is free for cp.async

    auto issue_tile = [&](int kt) {
        uint32_t base = sb + (kt & 1) * AT_STAGE;
        int k0 = kt * 64;
        #pragma unroll
        for (int t = 0; t < 2; t++) {
            int idx = tid + t * 256; int row = idx >> 3, cc = idx & 7;
            size_t g = hb + (size_t)(k0 + row) * HD_ + cc * 8;
            uint32_t so = row * LDK + cc * 16;
            CP_ASYNC16(base + OF_KHI + so, Khi + g);
            CP_ASYNC16(base + OF_KLO + so, Klo + g);
            CP_ASYNC16(base + OF_VHI + so, Vhi + g);
            CP_ASYNC16(base + OF_VLO + so, Vlo + g);
        }
    };

    float o[8][4];
    #pragma unroll
    for (int i = 0; i < 8; i++)
        #pragma unroll
        for (int j = 0; j < 4; j++) o[i][j] = 0.f;
    float m0 = -1e30f, m1 = -1e30f, l0 = 0.f, l1 = 0.f;

    const uint32_t browbase = (lane & 7) + (((lane >> 4) & 1) << 3);
    const uint32_t bkadd = ((lane >> 3) & 1) << 4;
    const uint32_t vrow = lane & 15;
    const uint32_t vnadd = (lane >> 4) << 4;
    const float alpha = 0.125f * 1.4426950408889634f;
    const int rowg = q0 + wid * 16 + (lane >> 2);

    const int nt = 2 * qt + 2;    // >= 2 always
    issue_tile(0); CP_COMMIT();
    issue_tile(1); CP_COMMIT();

    for (int kt = 0; kt < nt; kt++) {
        if (kt + 1 < nt) { CP_WAIT(1); } else { CP_WAIT(0); }
        __syncthreads();
        const uint32_t stg = sb + (kt & 1) * AT_STAGE;
        const int k0 = kt * 64;

        // S = Q K^T (3-term compensated), term-major per ks slice
        float s[8][4];
        #pragma unroll
        for (int i = 0; i < 8; i++)
            #pragma unroll
            for (int j = 0; j < 4; j++) s[i][j] = 0.f;
        #pragma unroll
        for (int ks = 0; ks < 4; ks++) {
            uint32_t kh[8][2], kl[8][2];
            #pragma unroll
            for (int g = 0; g < 4; g++) {
                uint32_t ah = stg + OF_KHI + (browbase + g * 16) * LDK + ks * 32 + bkadd;
                uint32_t al = stg + OF_KLO + (browbase + g * 16) * LDK + ks * 32 + bkadd;
                LDSM4(kh[2*g][0], kh[2*g][1], kh[2*g+1][0], kh[2*g+1][1], ah);
                LDSM4(kl[2*g][0], kl[2*g][1], kl[2*g+1][0], kl[2*g+1][1], al);
            }
            #pragma unroll
            for (int ni = 0; ni < 8; ni++)
                MMA16816(s[ni], qh[ks], kh[ni]);
            #pragma unroll
            for (int ni = 0; ni < 8; ni++)
                MMA16816(s[ni], qh[ks], kl[ni]);
            #pragma unroll
            for (int ni = 0; ni < 8; ni++)
                MMA16816(s[ni], ql[ks], kh[ni]);
        }

        // scale + causal mask (only warp bands intersecting the diagonal)
        if (k0 + 63 > q0 + wid * 16) {
            #pragma unroll
            for (int ni = 0; ni < 8; ni++) {
                int colg = k0 + ni * 8 + (lane & 3) * 2;
                s[ni][0] = (colg     <= rowg    ) ? s[ni][0] * alpha : -1e30f;
                s[ni][1] = (colg + 1 <= rowg    ) ? s[ni][1] * alpha : -1e30f;
                s[ni][2] = (colg     <= rowg + 8) ? s[ni][2] * alpha : -1e30f;
                s[ni][3] = (colg + 1 <= rowg + 8) ? s[ni][3] * alpha : -1e30f;
            }
        } else {
            #pragma unroll
            for (int ni = 0; ni < 8; ni++)
                #pragma unroll
                for (int j = 0; j < 4; j++) s[ni][j] *= alpha;
        }

        // online softmax
        float mx0 = m0, mx1 = m1;
        #pragma unroll
        for (int ni = 0; ni < 8; ni++) {
            mx0 = fmaxf(mx0, fmaxf(s[ni][0], s[ni][1]));
            mx1 = fmaxf(mx1, fmaxf(s[ni][2], s[ni][3]));
        }
        mx0 = fmaxf(mx0, __shfl_xor_sync(0xffffffffu, mx0, 1));
        mx0 = fmaxf(mx0, __shfl_xor_sync(0xffffffffu, mx0, 2));
        mx1 = fmaxf(mx1, __shfl_xor_sync(0xffffffffu, mx1, 1));
        mx1 = fmaxf(mx1, __shfl_xor_sync(0xffffffffu, mx1, 2));

        float sc0 = ex2f(m0 - mx0), sc1 = ex2f(m1 - mx1);
        l0 *= sc0; l1 *= sc1;
        #pragma unroll
        for (int ni = 0; ni < 8; ni++) {
            o[ni][0] *= sc0; o[ni][1] *= sc0;
            o[ni][2] *= sc1; o[ni][3] *= sc1;
        }
        m0 = mx0; m1 = mx1;

        uint32_t ph[4][4], pl[4][4];
        float rs0 = 0.f, rs1 = 0.f;
        #pragma unroll
        for (int ni = 0; ni < 8; ni++) {
            float p0 = ex2f(s[ni][0] - mx0);
            float p1 = ex2f(s[ni][1] - mx0);
            float p2 = ex2f(s[ni][2] - mx1);
            float p3 = ex2f(s[ni][3] - mx1);
            rs0 += p0 + p1; rs1 += p2 + p3;
            float h0 = __bfloat162float(__float2bfloat16(p0));
            float h1 = __bfloat162float(__float2bfloat16(p1));
            float h2 = __bfloat162float(__float2bfloat16(p2));
            float h3 = __bfloat162float(__float2bfloat16(p3));
            int kf = ni >> 1, hf = (ni & 1) * 2;
            ph[kf][hf + 0] = pack_bf16(h0, h1);
            ph[kf][hf + 1] = pack_bf16(h2, h3);
            pl[kf][hf + 0] = pack_bf16(p0 - h0, p1 - h1);
            pl[kf][hf + 1] = pack_bf16(p2 - h2, p3 - h3);
        }
        l0 += rs0; l1 += rs1;

        // O += P V (3-term), term-major per kf slice; V via ldmatrix.trans
        #pragma unroll
        for (int kf = 0; kf < 4; kf++) {
            uint32_t vh[8][2], vl[8][2];
            #pragma unroll
            for (int g = 0; g < 4; g++) {
                uint32_t ah = stg + OF_VHI + (kf * 16 + vrow) * LDK + g * 32 + vnadd;
                uint32_t al = stg + OF_VLO + (kf * 16 + vrow) * LDK + g * 32 + vnadd;
                LDSM4T(vh[2*g][0], vh[2*g][1], vh[2*g+1][0], vh[2*g+1][1], ah);
                LDSM4T(vl[2*g][0], vl[2*g][1], vl[2*g+1][0], vl[2*g+1][1], al);
            }
            #pragma unroll
            for (int nd = 0; nd < 8; nd++)
                MMA16816(o[nd], ph[kf], vh[nd]);
            #pragma unroll
            for (int nd = 0; nd < 8; nd++)
                MMA16816(o[nd], ph[kf], vl[nd]);
            #pragma unroll
            for (int nd = 0; nd < 8; nd++)
                MMA16816(o[nd], pl[kf], vh[nd]);
        }

        __syncthreads();
        if (kt + 2 < nt) { issue_tile(kt + 2); CP_COMMIT(); }
    }

    // finalize
    l0 += __shfl_xor_sync(0xffffffffu, l0, 1);
    l0 += __shfl_xor_sync(0xffffffffu, l0, 2);
    l1 += __shfl_xor_sync(0xffffffffu, l1, 1);
    l1 += __shfl_xor_sync(0xffffffffu, l1, 2);
    const float inv0 = 1.f / l0, inv1 = 1.f / l1;

    const size_t z0 = hb + (size_t)rowg * HD_;
    const size_t z1 = z0 + (size_t)8 * HD_;
    #pragma unroll
    for (int nd = 0; nd < 8; nd++) {
        int col = nd * 8 + (lane & 3) * 2;
        float a0 = o[nd][0] * inv0, a1 = o[nd][1] * inv0;
        float b0 = o[nd][2] * inv1, b1 = o[nd][3] * inv1;
        float h00 = __bfloat162float(__float2bfloat16(a0));
        float h01 = __bfloat162float(__float2bfloat16(a1));
        float h10 = __bfloat162float(__float2bfloat16(b0));
        float h11 = __bfloat162float(__float2bfloat16(b1));
        *(uint32_t*)&Zhi[z0 + col] = pack_bf16(h00, h01);
        *(uint32_t*)&Zhi[z1 + col] = pack_bf16(h10, h11);
        *(uint32_t*)&Zlo[z0 + col] = pack_bf16(a0 - h00, a1 - h01);
        *(uint32_t*)&Zlo[z1 + col] = pack_bf16(b0 - h10, b1 - h11);
    }
}

// ---------------------------------------------------------------------------
// Launch
// ---------------------------------------------------------------------------
extern "C" void kernel_launch(void* const* d_in, const int* in_sizes, int n_in,
                              void* d_out, int out_size)
{
    const float* query = (const float*)d_in[0];
    const float* key_  = (const float*)d_in[1];
    const float* value = (const float*)d_in[2];
    const float* WQ = (const float*)d_in[4];
    const float* bQ = (const float*)d_in[5];
    const float* WK = (const float*)d_in[6];
    const float* bK = (const float*)d_in[7];
    const float* WV = (const float*)d_in[8];
    const float* bV = (const float*)d_in[9];
    const float* WO = (const float*)d_in[10];
    const float* bO = (const float*)d_in[11];
    float* out = (float*)d_out;

    __nv_bfloat16 *zhi, *zlo, *w1t, *w2t, *ihi, *ilo;
    __nv_bfloat16 *qhi, *qlo, *khi, *klo, *vhi, *vlo;
    cudaGetSymbolAddress((void**)&zhi, g_Zhi);
    cudaGetSymbolAddress((void**)&zlo, g_Zlo);
    cudaGetSymbolAddress((void**)&w1t, g_W1t);
    cudaGetSymbolAddress((void**)&w2t, g_W2t);
    cudaGetSymbolAddress((void**)&ihi, g_Ihi);
    cudaGetSymbolAddress((void**)&ilo, g_Ilo);
    cudaGetSymbolAddress((void**)&qhi, g_Qhi);
    cudaGetSymbolAddress((void**)&qlo, g_Qlo);
    cudaGetSymbolAddress((void**)&khi, g_Khi);
    cudaGetSymbolAddress((void**)&klo, g_Klo);
    cudaGetSymbolAddress((void**)&vhi, g_Vhi);
    cudaGetSymbolAddress((void**)&vlo, g_Vlo);

    const size_t MK = (size_t)M_ * K_GEMM;

    SplitArgs sp;
    sp.x[0] = query; sp.x[1] = key_; sp.x[2] = value;
    sp.hi[0] = ihi;          sp.lo[0] = ilo;
    sp.hi[1] = ihi + MK;     sp.lo[1] = ilo + MK;
    sp.hi[2] = ihi + 2 * MK; sp.lo[2] = ilo + 2 * MK;

    PrepArgs pp;
    pp.W[0] = WQ; pp.W[1] = WK; pp.W[2] = WV; pp.W[3] = WO;

    QkvArgs qa;
    qa.Ahi[0] = ihi;          qa.Alo[0] = ilo;
    qa.Ahi[1] = ihi + MK;     qa.Alo[1] = ilo + MK;
    qa.Ahi[2] = ihi + 2 * MK; qa.Alo[2] = ilo + 2 * MK;
    qa.bias[0] = bQ; qa.bias[1] = bK; qa.bias[2] = bV;
    qa.Ohi[0] = qhi; qa.Ohi[1] = khi; qa.Ohi[2] = vhi;
    qa.Olo[0] = qlo; qa.Olo[1] = klo; qa.Olo[2] = vlo;

    const int GEMM_SMEM = NSTAGE * STAGE_B;   // 122880
    const int ATTN_SMEM = 2 * AT_STAGE;       // 73728
    cudaFuncSetAttribute(gemm_bf16x3_pipe<0>,
                         cudaFuncAttributeMaxDynamicSharedMemorySize, GEMM_SMEM);
    cudaFuncSetAttribute(gemm_bf16x3_pipe<1>,
                         cudaFuncAttributeMaxDynamicSharedMemorySize, GEMM_SMEM);
    cudaFuncSetAttribute(flash_attn_mma,
                         cudaFuncAttributeMaxDynamicSharedMemorySize, ATTN_SMEM);

    const int n4 = M_ * K_GEMM / 4;

    // 1. Split QKV inputs (one launch)
    split_bf16_kernel<<<dim3(n4 / 256, 1, 3), 256>>>(sp, n4);

    // 2. All weight preps (one launch)
    prep_w_kernel<<<dim3(N_GEMM / 32, K_GEMM / 32, 4), dim3(32, 8)>>>(pp, w1t, w2t);

    // 3. QKV projections (one launch, grid.z = 3)
    gemm_bf16x3_pipe<0><<<dim3(N_GEMM / 128, M_ / 128, 3), 256, GEMM_SMEM>>>(
        qa, nullptr, nullptr, w1t, w2t, nullptr, nullptr);

    // 4. Flash attention
    flash_attn_mma<<<dim3(S_ / 128, H_, B_), 256, ATTN_SMEM>>>(
        qhi, qlo, khi, klo, vhi, vlo, zhi, zlo);

    // 5. Output projection -> fp32 out
    gemm_bf16x3_pipe<1><<<dim3(N_GEMM / 128, M_ / 128, 1), 256, GEMM_SMEM>>>(
        qa, zhi, zlo, w1t, w2t, bO, out);
}

// round 8
// speedup vs baseline: 1.0797x; 1.0797x over previous
#include <cuda_runtime.h>
#include <cuda_bf16.h>
#include <cstdint>

// Problem constants
#define B_  2
#define S_  2048
#define E_  1024
#define H_  16
#define DH_ 64
#define HD_ 1024          // H*Dh
#define M_  (B_*S_)       // 4096 rows for all GEMMs
#define K_GEMM 1024
#define N_GEMM 1024

// ---------------------------------------------------------------------------
// Scratch (no cudaMalloc allowed)
// ---------------------------------------------------------------------------
__device__ __nv_bfloat16 g_Zhi[M_ * K_GEMM];          // attention output hi/lo
__device__ __nv_bfloat16 g_Zlo[M_ * K_GEMM];
__device__ __nv_bfloat16 g_W1t[4 * N_GEMM * K_GEMM];  // 4 transposed+split weights [N][K]
__device__ __nv_bfloat16 g_W2t[4 * N_GEMM * K_GEMM];
__device__ __nv_bfloat16 g_Ihi[3 * M_ * K_GEMM];      // split inputs (query/key/value)
__device__ __nv_bfloat16 g_Ilo[3 * M_ * K_GEMM];
__device__ __nv_bfloat16 g_Qhi[M_ * HD_];
__device__ __nv_bfloat16 g_Qlo[M_ * HD_];
__device__ __nv_bfloat16 g_Khi[M_ * HD_];
__device__ __nv_bfloat16 g_Klo[M_ * HD_];
__device__ __nv_bfloat16 g_Vhi[M_ * HD_];
__device__ __nv_bfloat16 g_Vlo[M_ * HD_];

struct QkvArgs {
    const __nv_bfloat16* Ahi[3];
    const __nv_bfloat16* Alo[3];
    const float* bias[3];
    __nv_bfloat16* Ohi[3];
    __nv_bfloat16* Olo[3];
};
struct PrepArgs { const float* W[4]; };
struct SplitArgs {
    const float* x[3];
    __nv_bfloat16* hi[3];
    __nv_bfloat16* lo[3];
};

__device__ __forceinline__ uint32_t smem_u32(const void* p) {
    uint32_t a;
    asm("{ .reg .u64 t; cvta.to.shared.u64 t, %1; cvt.u32.u64 %0, t; }" : "=r"(a) : "l"(p));
    return a;
}
__device__ __forceinline__ float ex2f(float x) {
    float y;
    asm("ex2.approx.ftz.f32 %0, %1;" : "=f"(y) : "f"(x));
    return y;
}
__device__ __forceinline__ uint32_t pack_bf16(float a, float b) {
    __nv_bfloat162 t = __floats2bfloat162_rn(a, b);
    return *reinterpret_cast<uint32_t*>(&t);
}

#define CP_ASYNC16(dst, src) \
    asm volatile("cp.async.cg.shared.global [%0], [%1], 16;" :: "r"(dst), "l"(src))
#define CP_COMMIT() asm volatile("cp.async.commit_group;" ::: "memory")
#define CP_WAIT(n)  asm volatile("cp.async.wait_group %0;" :: "n"(n) : "memory")

#define LDSM4(r0, r1, r2, r3, addr) \
    asm volatile("ldmatrix.sync.aligned.m8n8.x4.shared.b16 {%0,%1,%2,%3}, [%4];" \
                 : "=r"(r0), "=r"(r1), "=r"(r2), "=r"(r3) : "r"(addr))
#define LDSM4T(r0, r1, r2, r3, addr) \
    asm volatile("ldmatrix.sync.aligned.m8n8.x4.trans.shared.b16 {%0,%1,%2,%3}, [%4];" \
                 : "=r"(r0), "=r"(r1), "=r"(r2), "=r"(r3) : "r"(addr))
#define MMA16816(d, a, b) \
    asm volatile("mma.sync.aligned.m16n8k16.row.col.f32.bf16.bf16.f32 " \
                 "{%0,%1,%2,%3}, {%4,%5,%6,%7}, {%8,%9}, {%0,%1,%2,%3};" \
                 : "+f"((d)[0]), "+f"((d)[1]), "+f"((d)[2]), "+f"((d)[3]) \
                 : "r"((a)[0]), "r"((a)[1]), "r"((a)[2]), "r"((a)[3]), \
                   "r"((b)[0]), "r"((b)[1]))

// ---------------------------------------------------------------------------
// Batched split: fp32 inputs -> hi/lo bf16. grid (n4/256, 1, 3)
// ---------------------------------------------------------------------------
__global__ void __launch_bounds__(256)
split_bf16_kernel(SplitArgs sa, int n4)
{
    int z = blockIdx.z;
    int i = blockIdx.x * blockDim.x + threadIdx.x;
    if (i >= n4) return;
    float4 v = ((const float4*)sa.x[z])[i];
    float h0 = __bfloat162float(__float2bfloat16(v.x));
    float h1 = __bfloat162float(__float2bfloat16(v.y));
    float h2 = __bfloat162float(__float2bfloat16(v.z));
    float h3 = __bfloat162float(__float2bfloat16(v.w));
    uint2 hp, lp;
    hp.x = pack_bf16(h0, h1); hp.y = pack_bf16(h2, h3);
    lp.x = pack_bf16(v.x - h0, v.y - h1);
    lp.y = pack_bf16(v.z - h2, v.w - h3);
    ((uint2*)sa.hi[z])[i] = hp;
    ((uint2*)sa.lo[z])[i] = lp;
}

// ---------------------------------------------------------------------------
// Weight prep (batched): W[K][N] fp32 -> W1t/W2t[z] [N][K] bf16
// ---------------------------------------------------------------------------
__global__ void __launch_bounds__(256)
prep_w_kernel(PrepArgs pa,
              __nv_bfloat16* __restrict__ w1t,
              __nv_bfloat16* __restrict__ w2t)
{
    __shared__ float t[32][33];
    const float* W = pa.W[blockIdx.z];
    const size_t zoff = (size_t)blockIdx.z * N_GEMM * K_GEMM;
    int n0 = blockIdx.x * 32, k0 = blockIdx.y * 32;
    int tx = threadIdx.x, ty = threadIdx.y;
    #pragma unroll
    for (int i = 0; i < 4; i++)
        t[ty + 8 * i][tx] = W[(size_t)(k0 + ty + 8 * i) * N_GEMM + n0 + tx];
    __syncthreads();
    #pragma unroll
    for (int i = 0; i < 4; i++) {
        float v = t[tx][ty + 8 * i];
        __nv_bfloat16 h = __float2bfloat16(v);
        __nv_bfloat16 l = __float2bfloat16(v - __bfloat162float(h));
        size_t o = zoff + (size_t)(n0 + ty + 8 * i) * K_GEMM + k0 + tx;
        w1t[o] = h;
        w2t[o] = l;
    }
}

// ---------------------------------------------------------------------------
// HMMA bf16x3 GEMM, 2-stage cp.async pipeline, 2 CTAs/SM.
// ---------------------------------------------------------------------------
#define LDP 80
#define TILE_B (128 * LDP)      // 10240
#define STAGE_B (4 * TILE_B)    // 40960
#define NSTAGE 2

template<int MODE>
__global__ void __launch_bounds__(256, 2)
gemm_bf16x3_pipe(QkvArgs qa,
                 const __nv_bfloat16* __restrict__ Ahi_,
                 const __nv_bfloat16* __restrict__ Alo_,
                 const __nv_bfloat16* __restrict__ W1base,
                 const __nv_bfloat16* __restrict__ W2base,
                 const float* __restrict__ biasO,
                 float* __restrict__ Cout)
{
    extern __shared__ __align__(16) char smem[];
    const uint32_t sb = smem_u32(smem);
    const int z = blockIdx.z;
    const int tid = threadIdx.x;
    const int wid = tid >> 5, lane = tid & 31;
    const int n0 = blockIdx.x * 128, m0 = blockIdx.y * 128;
    const int mw = (wid & 3) * 32;
    const int nw = (wid >> 2) * 64;

    const size_t woff = (MODE == 0 ? (size_t)z : (size_t)3) * N_GEMM * K_GEMM;
    const __nv_bfloat16* gW1 = W1base + woff + (size_t)n0 * K_GEMM;
    const __nv_bfloat16* gW2 = W2base + woff + (size_t)n0 * K_GEMM;
    const __nv_bfloat16* gA1 = (MODE == 0 ? qa.Ahi[z] : Ahi_) + (size_t)m0 * K_GEMM;
    const __nv_bfloat16* gA2 = (MODE == 0 ? qa.Alo[z] : Alo_) + (size_t)m0 * K_GEMM;

    float acc[2][8][4];
    #pragma unroll
    for (int mi = 0; mi < 2; mi++)
        #pragma unroll
        for (int ni = 0; ni < 8; ni++)
            #pragma unroll
            for (int r = 0; r < 4; r++) acc[mi][ni][r] = 0.f;

    const int row_[2] = { tid >> 2, (tid + 256) >> 2 };
    const int cc_[2]  = { tid & 3, (tid + 256) & 3 };

    auto issue_chunk = [&](int c) {
        uint32_t base = sb + (c & 1) * STAGE_B;
        int k0 = c * 32;
        #pragma unroll
        for (int t = 0; t < 2; t++) {
            int row = row_[t], cc = cc_[t];
            uint32_t so = row * LDP + cc * 16;
            size_t go = (size_t)row * K_GEMM + k0 + cc * 8;
            CP_ASYNC16(base + 0 * TILE_B + so, gA1 + go);
            CP_ASYNC16(base + 1 * TILE_B + so, gA2 + go);
            CP_ASYNC16(base + 2 * TILE_B + so, gW1 + go);
            CP_ASYNC16(base + 3 * TILE_B + so, gW2 + go);
        }
    };

    const uint32_t a_row = mw + (lane & 15);
    const uint32_t a_kadd = (lane >> 4) << 4;
    const uint32_t b_rowbase = nw + (lane & 7) + (((lane >> 4) & 1) << 3);
    const uint32_t b_kadd = ((lane >> 3) & 1) << 4;

    const int NCHUNK = K_GEMM / 32;   // 32
    issue_chunk(0); CP_COMMIT();
    issue_chunk(1); CP_COMMIT();

    for (int c = 0; c < NCHUNK; c++) {
        if (c + 1 < NCHUNK) { CP_WAIT(1); } else { CP_WAIT(0); }
        __syncthreads();

        const uint32_t stg = sb + (c & 1) * STAGE_B;
        const uint32_t sA1 = stg, sA2 = stg + TILE_B;
        const uint32_t sW1 = stg + 2 * TILE_B, sW2 = stg + 3 * TILE_B;

        #pragma unroll
        for (int s = 0; s < 2; s++) {
            const uint32_t kb = s * 32;
            uint32_t a1f[2][4], a2f[2][4];
            #pragma unroll
            for (int mi = 0; mi < 2; mi++) {
                uint32_t addr1 = sA1 + (a_row + mi * 16) * LDP + kb + a_kadd;
                uint32_t addr2 = sA2 + (a_row + mi * 16) * LDP + kb + a_kadd;
                LDSM4(a1f[mi][0], a1f[mi][1], a1f[mi][2], a1f[mi][3], addr1);
                LDSM4(a2f[mi][0], a2f[mi][1], a2f[mi][2], a2f[mi][3], addr2);
            }
            uint32_t b1f[8][2], b2f[8][2];
            #pragma unroll
            for (int g = 0; g < 4; g++) {
                uint32_t addr1 = sW1 + (b_rowbase + g * 16) * LDP + kb + b_kadd;
                uint32_t addr2 = sW2 + (b_rowbase + g * 16) * LDP + kb + b_kadd;
                LDSM4(b1f[2*g][0], b1f[2*g][1], b1f[2*g+1][0], b1f[2*g+1][1], addr1);
                LDSM4(b2f[2*g][0], b2f[2*g][1], b2f[2*g+1][0], b2f[2*g+1][1], addr2);
            }
            #pragma unroll
            for (int mi = 0; mi < 2; mi++)
                #pragma unroll
                for (int ni = 0; ni < 8; ni++)
                    MMA16816(acc[mi][ni], a1f[mi], b1f[ni]);
            #pragma unroll
            for (int mi = 0; mi < 2; mi++)
                #pragma unroll
                for (int ni = 0; ni < 8; ni++)
                    MMA16816(acc[mi][ni], a1f[mi], b2f[ni]);
            #pragma unroll
            for (int mi = 0; mi < 2; mi++)
                #pragma unroll
                for (int ni = 0; ni < 8; ni++)
                    MMA16816(acc[mi][ni], a2f[mi], b1f[ni]);
        }
        __syncthreads();
        if (c + 2 < NCHUNK) { issue_chunk(c + 2); CP_COMMIT(); }
    }

    // ---- epilogue ----
    const float* bias = (MODE == 0) ? qa.bias[z] : biasO;
    const int erow = m0 + mw + (lane >> 2);
    const int ecol0 = n0 + nw + (lane & 3) * 2;
    #pragma unroll
    for (int mi = 0; mi < 2; mi++) {
        #pragma unroll
        for (int ni = 0; ni < 8; ni++) {
            int col = ecol0 + ni * 8;
            float b0 = bias[col], b1 = bias[col + 1];
            int r0 = erow + mi * 16;
            float v00 = acc[mi][ni][0] + b0, v01 = acc[mi][ni][1] + b1;
            float v10 = acc[mi][ni][2] + b0, v11 = acc[mi][ni][3] + b1;
            if (MODE == 1) {
                float2 w0 = { v00, v01 }, w1 = { v10, v11 };
                *(float2*)&Cout[(size_t)r0 * N_GEMM + col] = w0;
                *(float2*)&Cout[(size_t)(r0 + 8) * N_GEMM + col] = w1;
            } else {
                __nv_bfloat16* Chi = qa.Ohi[z];
                __nv_bfloat16* Clo = qa.Olo[z];
                float h00 = __bfloat162float(__float2bfloat16(v00));
                float h01 = __bfloat162float(__float2bfloat16(v01));
                float h10 = __bfloat162float(__float2bfloat16(v10));
                float h11 = __bfloat162float(__float2bfloat16(v11));
                *(uint32_t*)&Chi[(size_t)r0 * N_GEMM + col] = pack_bf16(h00, h01);
                *(uint32_t*)&Chi[(size_t)(r0 + 8) * N_GEMM + col] = pack_bf16(h10, h11);
                *(uint32_t*)&Clo[(size_t)r0 * N_GEMM + col] = pack_bf16(v00 - h00, v01 - h01);
                *(uint32_t*)&Clo[(size_t)(r0 + 8) * N_GEMM + col] = pack_bf16(v10 - h10, v11 - h11);
            }
        }
    }
}

// ---------------------------------------------------------------------------
// HMMA flash attention, causal, bf16x3, 2-stage cp.async K/V, 2 CTAs/SM,
// heavy-CTA-first scheduling.
// ---------------------------------------------------------------------------
#define LDK 144
#define AT_STAGE 36864
#define OF_KHI 0
#define OF_KLO 9216
#define OF_VHI 18432
#define OF_VLO 27648

__global__ void __launch_bounds__(256, 2)
flash_attn_mma(const __nv_bfloat16* __restrict__ Qhi, const __nv_bfloat16* __restrict__ Qlo,
               const __nv_bfloat16* __restrict__ Khi, const __nv_bfloat16* __restrict__ Klo,
               const __nv_bfloat16* __restrict__ Vhi, const __nv_bfloat16* __restrict__ Vlo,
               __nv_bfloat16* __restrict__ Zhi, __nv_bfloat16* __restrict__ Zlo)
{
    extern __shared__ __align__(16) char sm[];
    const uint32_t sb = smem_u32(sm);
    const int tid = threadIdx.x, wid = tid >> 5, lane = tid & 31;
    const int b = blockIdx.z, h = blockIdx.y;
    const int qt = gridDim.x - 1 - blockIdx.x;      // heavy CTAs first
    const int q0 = qt * 128;
    const size_t hb = (size_t)b * S_ * HD_ + h * DH_;

    const uint32_t arow = wid * 16 + (lane & 15);
    const uint32_t akadd = (lane >> 4) << 4;

    // Stage Qhi then Qlo through stage-0 area, ldmatrix into registers.
    uint32_t qh[4][4], ql[4][4];
    #pragma unroll
    for (int t = 0; t < 4; t++) {
        int idx = tid + t * 256; int row = idx >> 3, cc = idx & 7;
        *(float4*)(sm + row * LDK + cc * 16) =
            *(const float4*)&Qhi[hb + (size_t)(q0 + row) * HD_ + cc * 8];
    }
    __syncthreads();
    #pragma unroll
    for (int ks = 0; ks < 4; ks++) {
        uint32_t a = sb + arow * LDK + ks * 32 + akadd;
        LDSM4(qh[ks][0], qh[ks][1], qh[ks][2], qh[ks][3], a);
    }
    __syncthreads();
    #pragma unroll
    for (int t = 0; t < 4; t++) {
        int idx = tid + t * 256; int row = idx >> 3, cc = idx & 7;
        *(float4*)(sm + row * LDK + cc * 16) =
            *(const float4*)&Qlo[hb + (size_t)(q0 + row) * HD_ + cc * 8];
    }
    __syncthreads();
    #pragma unroll
    for (int ks = 0; ks < 4; ks++) {
        uint32_t a = sb + arow * LDK + ks * 32 + akadd;
        LDSM4(ql[ks][0], ql[ks][1], ql[ks][2], ql[ks][3], a);
    }
    __syncthreads();   // Q consumed; stage 0 is free for cp.async

    auto issue_tile = [&](int kt) {
        uint32_t base = sb + (kt & 1) * AT_STAGE;
        int k0 = kt * 64;
        #pragma unroll
        for (int t = 0; t < 2; t++) {
            int idx = tid + t * 256; int row = idx >> 3, cc = idx & 7;
            size_t g = hb + (size_t)(k0 + row) * HD_ + cc * 8;
            uint32_t so = row * LDK + cc * 16;
            CP_ASYNC16(base + OF_KHI + so, Khi + g);
            CP_ASYNC16(base + OF_KLO + so, Klo + g);
            CP_ASYNC16(base + OF_VHI + so, Vhi + g);
            CP_ASYNC16(base + OF_VLO + so, Vlo + g);
        }
    };

    float o[8][4];
    #pragma unroll
    for (int i = 0; i < 8; i++)
        #pragma unroll
        for (int j = 0; j < 4; j++) o[i][j] = 0.f;
    float m0 = -1e30f, m1 = -1e30f, l0 = 0.f, l1 = 0.f;

    const uint32_t browbase = (lane & 7) + (((lane >> 4) & 1) << 3);
    const uint32_t bkadd = ((lane >> 3) & 1) << 4;
    const uint32_t vrow = lane & 15;
    const uint32_t vnadd = (lane >> 4) << 4;
    const float alpha = 0.125f * 1.4426950408889634f;
    const int rowg = q0 + wid * 16 + (lane >> 2);

    const int nt = 2 * qt + 2;    // >= 2 always
    issue_tile(0); CP_COMMIT();
    issue_tile(1); CP_COMMIT();

    for (int kt = 0; kt < nt; kt++) {
        if (kt + 1 < nt) { CP_WAIT(1); } else { CP_WAIT(0); }
        __syncthreads();
        const uint32_t stg = sb + (kt & 1) * AT_STAGE;
        const int k0 = kt * 64;

        // S = Q K^T (3-term compensated)
        float s[8][4];
        #pragma unroll
        for (int i = 0; i < 8; i++)
            #pragma unroll
            for (int j = 0; j < 4; j++) s[i][j] = 0.f;
        #pragma unroll
        for (int ks = 0; ks < 4; ks++) {
            uint32_t kh[8][2], kl[8][2];
            #pragma unroll
            for (int g = 0; g < 4; g++) {
                uint32_t ah = stg + OF_KHI + (browbase + g * 16) * LDK + ks * 32 + bkadd;
                uint32_t al = stg + OF_KLO + (browbase + g * 16) * LDK + ks * 32 + bkadd;
                LDSM4(kh[2*g][0], kh[2*g][1], kh[2*g+1][0], kh[2*g+1][1], ah);
                LDSM4(kl[2*g][0], kl[2*g][1], kl[2*g+1][0], kl[2*g+1][1], al);
            }
            #pragma unroll
            for (int ni = 0; ni < 8; ni++)
                MMA16816(s[ni], qh[ks], kh[ni]);
            #pragma unroll
            for (int ni = 0; ni < 8; ni++)
                MMA16816(s[ni], qh[ks], kl[ni]);
            #pragma unroll
            for (int ni = 0; ni < 8; ni++)
                MMA16816(s[ni], ql[ks], kh[ni]);
        }

        // scale + causal mask (only warp bands intersecting the diagonal)
        if (k0 + 63 > q0 + wid * 16) {
            #pragma unroll
            for (int ni = 0; ni < 8; ni++) {
                int colg = k0 + ni * 8 + (lane & 3) * 2;
                s[ni][0] = (colg     <= rowg    ) ? s[ni][0] * alpha : -1e30f;
                s[ni][1] = (colg + 1 <= rowg    ) ? s[ni][1] * alpha : -1e30f;
                s[ni][2] = (colg     <= rowg + 8) ? s[ni][2] * alpha : -1e30f;
                s[ni][3] = (colg + 1 <= rowg + 8) ? s[ni][3] * alpha : -1e30f;
            }
        } else {
            #pragma unroll
            for (int ni = 0; ni < 8; ni++)
                #pragma unroll
                for (int j = 0; j < 4; j++) s[ni][j] *= alpha;
        }

        // online softmax
        float mx0 = m0, mx1 = m1;
        #pragma unroll
        for (int ni = 0; ni < 8; ni++) {
            mx0 = fmaxf(mx0, fmaxf(s[ni][0], s[ni][1]));
            mx1 = fmaxf(mx1, fmaxf(s[ni][2], s[ni][3]));
        }
        mx0 = fmaxf(mx0, __shfl_xor_sync(0xffffffffu, mx0, 1));
        mx0 = fmaxf(mx0, __shfl_xor_sync(0xffffffffu, mx0, 2));
        mx1 = fmaxf(mx1, __shfl_xor_sync(0xffffffffu, mx1, 1));
        mx1 = fmaxf(mx1, __shfl_xor_sync(0xffffffffu, mx1, 2));

        float sc0 = ex2f(m0 - mx0), sc1 = ex2f(m1 - mx1);
        l0 *= sc0; l1 *= sc1;
        #pragma unroll
        for (int ni = 0; ni < 8; ni++) {
            o[ni][0] *= sc0; o[ni][1] *= sc0;
            o[ni][2] *= sc1; o[ni][3] *= sc1;
        }
        m0 = mx0; m1 = mx1;

        uint32_t ph[4][4], pl[4][4];
        float rs0 = 0.f, rs1 = 0.f;
        #pragma unroll
        for (int ni = 0; ni < 8; ni++) {
            float p0 = ex2f(s[ni][0] - mx0);
            float p1 = ex2f(s[ni][1] - mx0);
            float p2 = ex2f(s[ni][2] - mx1);
            float p3 = ex2f(s[ni][3] - mx1);
            rs0 += p0 + p1; rs1 += p2 + p3;
            float h0 = __bfloat162float(__float2bfloat16(p0));
            float h1 = __bfloat162float(__float2bfloat16(p1));
            float h2 = __bfloat162float(__float2bfloat16(p2));
            float h3 = __bfloat162float(__float2bfloat16(p3));
            int kf = ni >> 1, hf = (ni & 1) * 2;
            ph[kf][hf + 0] = pack_bf16(h0, h1);
            ph[kf][hf + 1] = pack_bf16(h2, h3);
            pl[kf][hf + 0] = pack_bf16(p0 - h0, p1 - h1);
            pl[kf][hf + 1] = pack_bf16(p2 - h2, p3 - h3);
        }
        l0 += rs0; l1 += rs1;

        // O += P V (3-term); V via ldmatrix.trans
        #pragma unroll
        for (int kf = 0; kf < 4; kf++) {
            uint32_t vh[8][2], vl[8][2];
            #pragma unroll
            for (int g = 0; g < 4; g++) {
                uint32_t ah = stg + OF_VHI + (kf * 16 + vrow) * LDK + g * 32 + vnadd;
                uint32_t al = stg + OF_VLO + (kf * 16 + vrow) * LDK + g * 32 + vnadd;
                LDSM4T(vh[2*g][0], vh[2*g][1], vh[2*g+1][0], vh[2*g+1][1], ah);
                LDSM4T(vl[2*g][0], vl[2*g][1], vl[2*g+1][0], vl[2*g+1][1], al);
            }
            #pragma unroll
            for (int nd = 0; nd < 8; nd++)
                MMA16816(o[nd], ph[kf], vh[nd]);
            #pragma unroll
            for (int nd = 0; nd < 8; nd++)
                MMA16816(o[nd], ph[kf], vl[nd]);
            #pragma unroll
            for (int nd = 0; nd < 8; nd++)
                MMA16816(o[nd], pl[kf], vh[nd]);
        }

        __syncthreads();
        if (kt + 2 < nt) { issue_tile(kt + 2); CP_COMMIT(); }
    }

    // finalize
    l0 += __shfl_xor_sync(0xffffffffu, l0, 1);
    l0 += __shfl_xor_sync(0xffffffffu, l0, 2);
    l1 += __shfl_xor_sync(0xffffffffu, l1, 1);
    l1 += __shfl_xor_sync(0xffffffffu, l1, 2);
    const float inv0 = 1.f / l0, inv1 = 1.f / l1;

    const size_t z0 = hb + (size_t)rowg * HD_;
    const size_t z1 = z0 + (size_t)8 * HD_;
    #pragma unroll
    for (int nd = 0; nd < 8; nd++) {
        int col = nd * 8 + (lane & 3) * 2;
        float a0 = o[nd][0] * inv0, a1 = o[nd][1] * inv0;
        float b0 = o[nd][2] * inv1, b1 = o[nd][3] * inv1;
        float h00 = __bfloat162float(__float2bfloat16(a0));
        float h01 = __bfloat162float(__float2bfloat16(a1));
        float h10 = __bfloat162float(__float2bfloat16(b0));
        float h11 = __bfloat162float(__float2bfloat16(b1));
        *(uint32_t*)&Zhi[z0 + col] = pack_bf16(h00, h01);
        *(uint32_t*)&Zhi[z1 + col] = pack_bf16(h10, h11);
        *(uint32_t*)&Zlo[z0 + col] = pack_bf16(a0 - h00, a1 - h01);
        *(uint32_t*)&Zlo[z1 + col] = pack_bf16(b0 - h10, b1 - h11);
    }
}

// ---------------------------------------------------------------------------
// Launch
// ---------------------------------------------------------------------------
extern "C" void kernel_launch(void* const* d_in, const int* in_sizes, int n_in,
                              void* d_out, int out_size)
{
    const float* query = (const float*)d_in[0];
    const float* key_  = (const float*)d_in[1];
    const float* value = (const float*)d_in[2];
    const float* WQ = (const float*)d_in[4];
    const float* bQ = (const float*)d_in[5];
    const float* WK = (const float*)d_in[6];
    const float* bK = (const float*)d_in[7];
    const float* WV = (const float*)d_in[8];
    const float* bV = (const float*)d_in[9];
    const float* WO = (const float*)d_in[10];
    const float* bO = (const float*)d_in[11];
    float* out = (float*)d_out;

    __nv_bfloat16 *zhi, *zlo, *w1t, *w2t, *ihi, *ilo;
    __nv_bfloat16 *qhi, *qlo, *khi, *klo, *vhi, *vlo;
    cudaGetSymbolAddress((void**)&zhi, g_Zhi);
    cudaGetSymbolAddress((void**)&zlo, g_Zlo);
    cudaGetSymbolAddress((void**)&w1t, g_W1t);
    cudaGetSymbolAddress((void**)&w2t, g_W2t);
    cudaGetSymbolAddress((void**)&ihi, g_Ihi);
    cudaGetSymbolAddress((void**)&ilo, g_Ilo);
    cudaGetSymbolAddress((void**)&qhi, g_Qhi);
    cudaGetSymbolAddress((void**)&qlo, g_Qlo);
    cudaGetSymbolAddress((void**)&khi, g_Khi);
    cudaGetSymbolAddress((void**)&klo, g_Klo);
    cudaGetSymbolAddress((void**)&vhi, g_Vhi);
    cudaGetSymbolAddress((void**)&vlo, g_Vlo);

    const size_t MK = (size_t)M_ * K_GEMM;

    SplitArgs sp;
    sp.x[0] = query; sp.x[1] = key_; sp.x[2] = value;
    sp.hi[0] = ihi;          sp.lo[0] = ilo;
    sp.hi[1] = ihi + MK;     sp.lo[1] = ilo + MK;
    sp.hi[2] = ihi + 2 * MK; sp.lo[2] = ilo + 2 * MK;

    PrepArgs pp;
    pp.W[0] = WQ; pp.W[1] = WK; pp.W[2] = WV; pp.W[3] = WO;

    QkvArgs qa;
    qa.Ahi[0] = ihi;          qa.Alo[0] = ilo;
    qa.Ahi[1] = ihi + MK;     qa.Alo[1] = ilo + MK;
    qa.Ahi[2] = ihi + 2 * MK; qa.Alo[2] = ilo + 2 * MK;
    qa.bias[0] = bQ; qa.bias[1] = bK; qa.bias[2] = bV;
    qa.Ohi[0] = qhi; qa.Ohi[1] = khi; qa.Ohi[2] = vhi;
    qa.Olo[0] = qlo; qa.Olo[1] = klo; qa.Olo[2] = vlo;

    const int GEMM_SMEM = NSTAGE * STAGE_B;   // 81920
    const int ATTN_SMEM = 2 * AT_STAGE;       // 73728
    cudaFuncSetAttribute(gemm_bf16x3_pipe<0>,
                         cudaFuncAttributeMaxDynamicSharedMemorySize, GEMM_SMEM);
    cudaFuncSetAttribute(gemm_bf16x3_pipe<1>,
                         cudaFuncAttributeMaxDynamicSharedMemorySize, GEMM_SMEM);
    cudaFuncSetAttribute(flash_attn_mma,
                         cudaFuncAttributeMaxDynamicSharedMemorySize, ATTN_SMEM);

    const int n4 = M_ * K_GEMM / 4;

    // 1. Split QKV inputs (one launch)
    split_bf16_kernel<<<dim3(n4 / 256, 1, 3), 256>>>(sp, n4);

    // 2. All weight preps (one launch)
    prep_w_kernel<<<dim3(N_GEMM / 32, K_GEMM / 32, 4), dim3(32, 8)>>>(pp, w1t, w2t);

    // 3. QKV projections (one launch, grid.z = 3)
    gemm_bf16x3_pipe<0><<<dim3(N_GEMM / 128, M_ / 128, 3), 256, GEMM_SMEM>>>(
        qa, nullptr, nullptr, w1t, w2t, nullptr, nullptr);

    // 4. Flash attention
    flash_attn_mma<<<dim3(S_ / 128, H_, B_), 256, ATTN_SMEM>>>(
        qhi, qlo, khi, klo, vhi, vlo, zhi, zlo);

    // 5. Output projection -> fp32 out
    gemm_bf16x3_pipe<1><<<dim3(N_GEMM / 128, M_ / 128, 1), 256, GEMM_SMEM>>>(
        qa, zhi, zlo, w1t, w2t, bO, out);
}

// round 9
// speedup vs baseline: 1.0950x; 1.0141x over previous
#include <cuda_runtime.h>
#include <cuda_bf16.h>
#include <cstdint>

// Problem constants
#define B_  2
#define S_  2048
#define E_  1024
#define H_  16
#define DH_ 64
#define HD_ 1024          // H*Dh
#define M_  (B_*S_)       // 4096 rows for all GEMMs
#define K_GEMM 1024
#define N_GEMM 1024

// ---------------------------------------------------------------------------
// Scratch (no cudaMalloc allowed)
// ---------------------------------------------------------------------------
__device__ __nv_bfloat16 g_Zhi[M_ * K_GEMM];          // attention output hi/lo
__device__ __nv_bfloat16 g_Zlo[M_ * K_GEMM];
__device__ __nv_bfloat16 g_W1t[4 * N_GEMM * K_GEMM];  // 4 transposed+split weights [N][K]
__device__ __nv_bfloat16 g_W2t[4 * N_GEMM * K_GEMM];
__device__ __nv_bfloat16 g_Ihi[3 * M_ * K_GEMM];      // split inputs (query/key/value)
__device__ __nv_bfloat16 g_Ilo[3 * M_ * K_GEMM];
__device__ __nv_bfloat16 g_Qhi[M_ * HD_];
__device__ __nv_bfloat16 g_Qlo[M_ * HD_];
__device__ __nv_bfloat16 g_Khi[M_ * HD_];
__device__ __nv_bfloat16 g_Klo[M_ * HD_];
__device__ __nv_bfloat16 g_Vhi[M_ * HD_];
__device__ __nv_bfloat16 g_Vlo[M_ * HD_];

struct QkvArgs {
    const __nv_bfloat16* Ahi[3];
    const __nv_bfloat16* Alo[3];
    const float* bias[3];
    __nv_bfloat16* Ohi[3];
    __nv_bfloat16* Olo[3];
};
struct PrepArgs { const float* W[4]; };
struct SplitArgs {
    const float* x[3];
    __nv_bfloat16* hi[3];
    __nv_bfloat16* lo[3];
};

__device__ __forceinline__ uint32_t smem_u32(const void* p) {
    uint32_t a;
    asm("{ .reg .u64 t; cvta.to.shared.u64 t, %1; cvt.u32.u64 %0, t; }" : "=r"(a) : "l"(p));
    return a;
}
__device__ __forceinline__ float ex2f(float x) {
    float y;
    asm("ex2.approx.ftz.f32 %0, %1;" : "=f"(y) : "f"(x));
    return y;
}
__device__ __forceinline__ uint32_t pack_bf16(float a, float b) {
    __nv_bfloat162 t = __floats2bfloat162_rn(a, b);
    return *reinterpret_cast<uint32_t*>(&t);
}

#define CP_ASYNC16(dst, src) \
    asm volatile("cp.async.cg.shared.global [%0], [%1], 16;" :: "r"(dst), "l"(src))
#define CP_COMMIT() asm volatile("cp.async.commit_group;" ::: "memory")
#define CP_WAIT(n)  asm volatile("cp.async.wait_group %0;" :: "n"(n) : "memory")

#define LDSM4(r0, r1, r2, r3, addr) \
    asm volatile("ldmatrix.sync.aligned.m8n8.x4.shared.b16 {%0,%1,%2,%3}, [%4];" \
                 : "=r"(r0), "=r"(r1), "=r"(r2), "=r"(r3) : "r"(addr))
#define LDSM4T(r0, r1, r2, r3, addr) \
    asm volatile("ldmatrix.sync.aligned.m8n8.x4.trans.shared.b16 {%0,%1,%2,%3}, [%4];" \
                 : "=r"(r0), "=r"(r1), "=r"(r2), "=r"(r3) : "r"(addr))
#define MMA16816(d, a, b) \
    asm volatile("mma.sync.aligned.m16n8k16.row.col.f32.bf16.bf16.f32 " \
                 "{%0,%1,%2,%3}, {%4,%5,%6,%7}, {%8,%9}, {%0,%1,%2,%3};" \
                 : "+f"((d)[0]), "+f"((d)[1]), "+f"((d)[2]), "+f"((d)[3]) \
                 : "r"((a)[0]), "r"((a)[1]), "r"((a)[2]), "r"((a)[3]), \
                   "r"((b)[0]), "r"((b)[1]))

// ---------------------------------------------------------------------------
// Batched split: fp32 inputs -> hi/lo bf16. grid (n4/256, 1, 3)
// ---------------------------------------------------------------------------
__global__ void __launch_bounds__(256)
split_bf16_kernel(SplitArgs sa, int n4)
{
    int z = blockIdx.z;
    int i = blockIdx.x * blockDim.x + threadIdx.x;
    if (i >= n4) return;
    float4 v = ((const float4*)sa.x[z])[i];
    float h0 = __bfloat162float(__float2bfloat16(v.x));
    float h1 = __bfloat162float(__float2bfloat16(v.y));
    float h2 = __bfloat162float(__float2bfloat16(v.z));
    float h3 = __bfloat162float(__float2bfloat16(v.w));
    uint2 hp, lp;
    hp.x = pack_bf16(h0, h1); hp.y = pack_bf16(h2, h3);
    lp.x = pack_bf16(v.x - h0, v.y - h1);
    lp.y = pack_bf16(v.z - h2, v.w - h3);
    ((uint2*)sa.hi[z])[i] = hp;
    ((uint2*)sa.lo[z])[i] = lp;
}

// ---------------------------------------------------------------------------
// Weight prep (batched): W[K][N] fp32 -> W1t/W2t[z] [N][K] bf16
// ---------------------------------------------------------------------------
__global__ void __launch_bounds__(256)
prep_w_kernel(PrepArgs pa,
              __nv_bfloat16* __restrict__ w1t,
              __nv_bfloat16* __restrict__ w2t)
{
    __shared__ float t[32][33];
    const float* W = pa.W[blockIdx.z];
    const size_t zoff = (size_t)blockIdx.z * N_GEMM * K_GEMM;
    int n0 = blockIdx.x * 32, k0 = blockIdx.y * 32;
    int tx = threadIdx.x, ty = threadIdx.y;
    #pragma unroll
    for (int i = 0; i < 4; i++)
        t[ty + 8 * i][tx] = W[(size_t)(k0 + ty + 8 * i) * N_GEMM + n0 + tx];
    __syncthreads();
    #pragma unroll
    for (int i = 0; i < 4; i++) {
        float v = t[tx][ty + 8 * i];
        __nv_bfloat16 h = __float2bfloat16(v);
        __nv_bfloat16 l = __float2bfloat16(v - __bfloat162float(h));
        size_t o = zoff + (size_t)(n0 + ty + 8 * i) * K_GEMM + k0 + tx;
        w1t[o] = h;
        w2t[o] = l;
    }
}

// ---------------------------------------------------------------------------
// HMMA bf16x3 GEMM, 2-stage cp.async pipeline, 2 CTAs/SM. (unchanged from R8)
// ---------------------------------------------------------------------------
#define LDP 80
#define TILE_B (128 * LDP)      // 10240
#define STAGE_B (4 * TILE_B)    // 40960
#define NSTAGE 2

template<int MODE>
__global__ void __launch_bounds__(256, 2)
gemm_bf16x3_pipe(QkvArgs qa,
                 const __nv_bfloat16* __restrict__ Ahi_,
                 const __nv_bfloat16* __restrict__ Alo_,
                 const __nv_bfloat16* __restrict__ W1base,
                 const __nv_bfloat16* __restrict__ W2base,
                 const float* __restrict__ biasO,
                 float* __restrict__ Cout)
{
    extern __shared__ __align__(16) char smem[];
    const uint32_t sb = smem_u32(smem);
    const int z = blockIdx.z;
    const int tid = threadIdx.x;
    const int wid = tid >> 5, lane = tid & 31;
    const int n0 = blockIdx.x * 128, m0 = blockIdx.y * 128;
    const int mw = (wid & 3) * 32;
    const int nw = (wid >> 2) * 64;

    const size_t woff = (MODE == 0 ? (size_t)z : (size_t)3) * N_GEMM * K_GEMM;
    const __nv_bfloat16* gW1 = W1base + woff + (size_t)n0 * K_GEMM;
    const __nv_bfloat16* gW2 = W2base + woff + (size_t)n0 * K_GEMM;
    const __nv_bfloat16* gA1 = (MODE == 0 ? qa.Ahi[z] : Ahi_) + (size_t)m0 * K_GEMM;
    const __nv_bfloat16* gA2 = (MODE == 0 ? qa.Alo[z] : Alo_) + (size_t)m0 * K_GEMM;

    float acc[2][8][4];
    #pragma unroll
    for (int mi = 0; mi < 2; mi++)
        #pragma unroll
        for (int ni = 0; ni < 8; ni++)
            #pragma unroll
            for (int r = 0; r < 4; r++) acc[mi][ni][r] = 0.f;

    const int row_[2] = { tid >> 2, (tid + 256) >> 2 };
    const int cc_[2]  = { tid & 3, (tid + 256) & 3 };

    auto issue_chunk = [&](int c) {
        uint32_t base = sb + (c & 1) * STAGE_B;
        int k0 = c * 32;
        #pragma unroll
        for (int t = 0; t < 2; t++) {
            int row = row_[t], cc = cc_[t];
            uint32_t so = row * LDP + cc * 16;
            size_t go = (size_t)row * K_GEMM + k0 + cc * 8;
            CP_ASYNC16(base + 0 * TILE_B + so, gA1 + go);
            CP_ASYNC16(base + 1 * TILE_B + so, gA2 + go);
            CP_ASYNC16(base + 2 * TILE_B + so, gW1 + go);
            CP_ASYNC16(base + 3 * TILE_B + so, gW2 + go);
        }
    };

    const uint32_t a_row = mw + (lane & 15);
    const uint32_t a_kadd = (lane >> 4) << 4;
    const uint32_t b_rowbase = nw + (lane & 7) + (((lane >> 4) & 1) << 3);
    const uint32_t b_kadd = ((lane >> 3) & 1) << 4;

    const int NCHUNK = K_GEMM / 32;   // 32
    issue_chunk(0); CP_COMMIT();
    issue_chunk(1); CP_COMMIT();

    for (int c = 0; c < NCHUNK; c++) {
        if (c + 1 < NCHUNK) { CP_WAIT(1); } else { CP_WAIT(0); }
        __syncthreads();

        const uint32_t stg = sb + (c & 1) * STAGE_B;
        const uint32_t sA1 = stg, sA2 = stg + TILE_B;
        const uint32_t sW1 = stg + 2 * TILE_B, sW2 = stg + 3 * TILE_B;

        #pragma unroll
        for (int s = 0; s < 2; s++) {
            const uint32_t kb = s * 32;
            uint32_t a1f[2][4], a2f[2][4];
            #pragma unroll
            for (int mi = 0; mi < 2; mi++) {
                uint32_t addr1 = sA1 + (a_row + mi * 16) * LDP + kb + a_kadd;
                uint32_t addr2 = sA2 + (a_row + mi * 16) * LDP + kb + a_kadd;
                LDSM4(a1f[mi][0], a1f[mi][1], a1f[mi][2], a1f[mi][3], addr1);
                LDSM4(a2f[mi][0], a2f[mi][1], a2f[mi][2], a2f[mi][3], addr2);
            }
            uint32_t b1f[8][2], b2f[8][2];
            #pragma unroll
            for (int g = 0; g < 4; g++) {
                uint32_t addr1 = sW1 + (b_rowbase + g * 16) * LDP + kb + b_kadd;
                uint32_t addr2 = sW2 + (b_rowbase + g * 16) * LDP + kb + b_kadd;
                LDSM4(b1f[2*g][0], b1f[2*g][1], b1f[2*g+1][0], b1f[2*g+1][1], addr1);
                LDSM4(b2f[2*g][0], b2f[2*g][1], b2f[2*g+1][0], b2f[2*g+1][1], addr2);
            }
            #pragma unroll
            for (int mi = 0; mi < 2; mi++)
                #pragma unroll
                for (int ni = 0; ni < 8; ni++)
                    MMA16816(acc[mi][ni], a1f[mi], b1f[ni]);
            #pragma unroll
            for (int mi = 0; mi < 2; mi++)
                #pragma unroll
                for (int ni = 0; ni < 8; ni++)
                    MMA16816(acc[mi][ni], a1f[mi], b2f[ni]);
            #pragma unroll
            for (int mi = 0; mi < 2; mi++)
                #pragma unroll
                for (int ni = 0; ni < 8; ni++)
                    MMA16816(acc[mi][ni], a2f[mi], b1f[ni]);
        }
        __syncthreads();
        if (c + 2 < NCHUNK) { issue_chunk(c + 2); CP_COMMIT(); }
    }

    // ---- epilogue ----
    const float* bias = (MODE == 0) ? qa.bias[z] : biasO;
    const int erow = m0 + mw + (lane >> 2);
    const int ecol0 = n0 + nw + (lane & 3) * 2;
    #pragma unroll
    for (int mi = 0; mi < 2; mi++) {
        #pragma unroll
        for (int ni = 0; ni < 8; ni++) {
            int col = ecol0 + ni * 8;
            float b0 = bias[col], b1 = bias[col + 1];
            int r0 = erow + mi * 16;
            float v00 = acc[mi][ni][0] + b0, v01 = acc[mi][ni][1] + b1;
            float v10 = acc[mi][ni][2] + b0, v11 = acc[mi][ni][3] + b1;
            if (MODE == 1) {
                float2 w0 = { v00, v01 }, w1 = { v10, v11 };
                *(float2*)&Cout[(size_t)r0 * N_GEMM + col] = w0;
                *(float2*)&Cout[(size_t)(r0 + 8) * N_GEMM + col] = w1;
            } else {
                __nv_bfloat16* Chi = qa.Ohi[z];
                __nv_bfloat16* Clo = qa.Olo[z];
                float h00 = __bfloat162float(__float2bfloat16(v00));
                float h01 = __bfloat162float(__float2bfloat16(v01));
                float h10 = __bfloat162float(__float2bfloat16(v10));
                float h11 = __bfloat162float(__float2bfloat16(v11));
                *(uint32_t*)&Chi[(size_t)r0 * N_GEMM + col] = pack_bf16(h00, h01);
                *(uint32_t*)&Chi[(size_t)(r0 + 8) * N_GEMM + col] = pack_bf16(h10, h11);
                *(uint32_t*)&Clo[(size_t)r0 * N_GEMM + col] = pack_bf16(v00 - h00, v01 - h01);
                *(uint32_t*)&Clo[(size_t)(r0 + 8) * N_GEMM + col] = pack_bf16(v10 - h10, v11 - h11);
            }
        }
    }
}

// ---------------------------------------------------------------------------
// HMMA flash attention, causal, bf16x3, 2-stage cp.async K/V, 2 CTAs/SM.
// Q lives in SMEM (not registers); P built per-kf slice. Low register pressure.
// SMEM/CTA: Q (36864) + 2 KV stages (2x36864) = 110592.
// ---------------------------------------------------------------------------
#define LDK 144
#define AT_STAGE 36864
#define SQ_HI 0
#define SQ_LO 18432
#define KV_BASE 36864
#define OF_KHI 0
#define OF_KLO 9216
#define OF_VHI 18432
#define OF_VLO 27648

__global__ void __launch_bounds__(256, 2)
flash_attn_mma(const __nv_bfloat16* __restrict__ Qhi, const __nv_bfloat16* __restrict__ Qlo,
               const __nv_bfloat16* __restrict__ Khi, const __nv_bfloat16* __restrict__ Klo,
               const __nv_bfloat16* __restrict__ Vhi, const __nv_bfloat16* __restrict__ Vlo,
               __nv_bfloat16* __restrict__ Zhi, __nv_bfloat16* __restrict__ Zlo)
{
    extern __shared__ __align__(16) char sm[];
    const uint32_t sb = smem_u32(sm);
    const int tid = threadIdx.x, wid = tid >> 5, lane = tid & 31;
    const int b = blockIdx.z, h = blockIdx.y;
    const int qt = gridDim.x - 1 - blockIdx.x;      // heavy CTAs first
    const int q0 = qt * 128;
    const size_t hb = (size_t)b * S_ * HD_ + h * DH_;

    // Stage Q hi/lo into dedicated SMEM region (persistent for whole kernel).
    #pragma unroll
    for (int t = 0; t < 4; t++) {
        int idx = tid + t * 256; int row = idx >> 3, cc = idx & 7;
        size_t g = hb + (size_t)(q0 + row) * HD_ + cc * 8;
        uint32_t so = row * LDK + cc * 16;
        *(float4*)(sm + SQ_HI + so) = *(const float4*)&Qhi[g];
        *(float4*)(sm + SQ_LO + so) = *(const float4*)&Qlo[g];
    }

    auto issue_tile = [&](int kt) {
        uint32_t base = sb + KV_BASE + (kt & 1) * AT_STAGE;
        int k0 = kt * 64;
        #pragma unroll
        for (int t = 0; t < 2; t++) {
            int idx = tid + t * 256; int row = idx >> 3, cc = idx & 7;
            size_t g = hb + (size_t)(k0 + row) * HD_ + cc * 8;
            uint32_t so = row * LDK + cc * 16;
            CP_ASYNC16(base + OF_KHI + so, Khi + g);
            CP_ASYNC16(base + OF_KLO + so, Klo + g);
            CP_ASYNC16(base + OF_VHI + so, Vhi + g);
            CP_ASYNC16(base + OF_VLO + so, Vlo + g);
        }
    };

    float o[8][4];
    #pragma unroll
    for (int i = 0; i < 8; i++)
        #pragma unroll
        for (int j = 0; j < 4; j++) o[i][j] = 0.f;
    float m0 = -1e30f, m1 = -1e30f, l0 = 0.f, l1 = 0.f;

    const uint32_t arow = wid * 16 + (lane & 15);
    const uint32_t akadd = (lane >> 4) << 4;
    const uint32_t browbase = (lane & 7) + (((lane >> 4) & 1) << 3);
    const uint32_t bkadd = ((lane >> 3) & 1) << 4;
    const uint32_t vrow = lane & 15;
    const uint32_t vnadd = (lane >> 4) << 4;
    const float alpha = 0.125f * 1.4426950408889634f;
    const int rowg = q0 + wid * 16 + (lane >> 2);

    const int nt = 2 * qt + 2;    // >= 2 always
    issue_tile(0); CP_COMMIT();
    issue_tile(1); CP_COMMIT();
    __syncthreads();              // Q staging visible before first use

    for (int kt = 0; kt < nt; kt++) {
        if (kt + 1 < nt) { CP_WAIT(1); } else { CP_WAIT(0); }
        __syncthreads();
        const uint32_t stg = sb + KV_BASE + (kt & 1) * AT_STAGE;
        const int k0 = kt * 64;

        // S = Q K^T (3-term compensated); Q frags loaded from SMEM per slice
        float s[8][4];
        #pragma unroll
        for (int i = 0; i < 8; i++)
            #pragma unroll
            for (int j = 0; j < 4; j++) s[i][j] = 0.f;
        #pragma unroll
        for (int ks = 0; ks < 4; ks++) {
            uint32_t qh[4], ql[4];
            LDSM4(qh[0], qh[1], qh[2], qh[3], sb + SQ_HI + arow * LDK + ks * 32 + akadd);
            LDSM4(ql[0], ql[1], ql[2], ql[3], sb + SQ_LO + arow * LDK + ks * 32 + akadd);
            uint32_t kh[8][2], kl[8][2];
            #pragma unroll
            for (int g = 0; g < 4; g++) {
                uint32_t ah = stg + OF_KHI + (browbase + g * 16) * LDK + ks * 32 + bkadd;
                uint32_t al = stg + OF_KLO + (browbase + g * 16) * LDK + ks * 32 + bkadd;
                LDSM4(kh[2*g][0], kh[2*g][1], kh[2*g+1][0], kh[2*g+1][1], ah);
                LDSM4(kl[2*g][0], kl[2*g][1], kl[2*g+1][0], kl[2*g+1][1], al);
            }
            #pragma unroll
            for (int ni = 0; ni < 8; ni++)
                MMA16816(s[ni], qh, kh[ni]);
            #pragma unroll
            for (int ni = 0; ni < 8; ni++)
                MMA16816(s[ni], qh, kl[ni]);
            #pragma unroll
            for (int ni = 0; ni < 8; ni++)
                MMA16816(s[ni], ql, kh[ni]);
        }

        // scale + causal mask (only warp bands intersecting the diagonal)
        if (k0 + 63 > q0 + wid * 16) {
            #pragma unroll
            for (int ni = 0; ni < 8; ni++) {
                int colg = k0 + ni * 8 + (lane & 3) * 2;
                s[ni][0] = (colg     <= rowg    ) ? s[ni][0] * alpha : -1e30f;
                s[ni][1] = (colg + 1 <= rowg    ) ? s[ni][1] * alpha : -1e30f;
                s[ni][2] = (colg     <= rowg + 8) ? s[ni][2] * alpha : -1e30f;
                s[ni][3] = (colg + 1 <= rowg + 8) ? s[ni][3] * alpha : -1e30f;
            }
        } else {
            #pragma unroll
            for (int ni = 0; ni < 8; ni++)
                #pragma unroll
                for (int j = 0; j < 4; j++) s[ni][j] *= alpha;
        }

        // online softmax
        float mx0 = m0, mx1 = m1;
        #pragma unroll
        for (int ni = 0; ni < 8; ni++) {
            mx0 = fmaxf(mx0, fmaxf(s[ni][0], s[ni][1]));
            mx1 = fmaxf(mx1, fmaxf(s[ni][2], s[ni][3]));
        }
        mx0 = fmaxf(mx0, __shfl_xor_sync(0xffffffffu, mx0, 1));
        mx0 = fmaxf(mx0, __shfl_xor_sync(0xffffffffu, mx0, 2));
        mx1 = fmaxf(mx1, __shfl_xor_sync(0xffffffffu, mx1, 1));
        mx1 = fmaxf(mx1, __shfl_xor_sync(0xffffffffu, mx1, 2));

        float sc0 = ex2f(m0 - mx0), sc1 = ex2f(m1 - mx1);
        l0 *= sc0; l1 *= sc1;
        #pragma unroll
        for (int ni = 0; ni < 8; ni++) {
            o[ni][0] *= sc0; o[ni][1] *= sc0;
            o[ni][2] *= sc1; o[ni][3] *= sc1;
        }
        m0 = mx0; m1 = mx1;

        // PV: build P fragments per kf slice (8 regs), then 3-term MMAs
        float rs0 = 0.f, rs1 = 0.f;
        #pragma unroll
        for (int kf = 0; kf < 4; kf++) {
            uint32_t ph[4], pl[4];
            #pragma unroll
            for (int j = 0; j < 2; j++) {
                int ni = 2 * kf + j;
                float p0 = ex2f(s[ni][0] - mx0);
                float p1 = ex2f(s[ni][1] - mx0);
                float p2 = ex2f(s[ni][2] - mx1);
                float p3 = ex2f(s[ni][3] - mx1);
                rs0 += p0 + p1; rs1 += p2 + p3;
                float h0 = __bfloat162float(__float2bfloat16(p0));
                float h1 = __bfloat162float(__float2bfloat16(p1));
                float h2 = __bfloat162float(__float2bfloat16(p2));
                float h3 = __bfloat162float(__float2bfloat16(p3));
                ph[j * 2 + 0] = pack_bf16(h0, h1);
                ph[j * 2 + 1] = pack_bf16(h2, h3);
                pl[j * 2 + 0] = pack_bf16(p0 - h0, p1 - h1);
                pl[j * 2 + 1] = pack_bf16(p2 - h2, p3 - h3);
            }
            uint32_t vh[8][2], vl[8][2];
            #pragma unroll
            for (int g = 0; g < 4; g++) {
                uint32_t ah = stg + OF_VHI + (kf * 16 + vrow) * LDK + g * 32 + vnadd;
                uint32_t al = stg + OF_VLO + (kf * 16 + vrow) * LDK + g * 32 + vnadd;
                LDSM4T(vh[2*g][0], vh[2*g][1], vh[2*g+1][0], vh[2*g+1][1], ah);
                LDSM4T(vl[2*g][0], vl[2*g][1], vl[2*g+1][0], vl[2*g+1][1], al);
            }
            #pragma unroll
            for (int nd = 0; nd < 8; nd++)
                MMA16816(o[nd], ph, vh[nd]);
            #pragma unroll
            for (int nd = 0; nd < 8; nd++)
                MMA16816(o[nd], ph, vl[nd]);
            #pragma unroll
            for (int nd = 0; nd < 8; nd++)
                MMA16816(o[nd], pl, vh[nd]);
        }
        l0 += rs0; l1 += rs1;

        __syncthreads();
        if (kt + 2 < nt) { issue_tile(kt + 2); CP_COMMIT(); }
    }

    // finalize
    l0 += __shfl_xor_sync(0xffffffffu, l0, 1);
    l0 += __shfl_xor_sync(0xffffffffu, l0, 2);
    l1 += __shfl_xor_sync(0xffffffffu, l1, 1);
    l1 += __shfl_xor_sync(0xffffffffu, l1, 2);
    const float inv0 = 1.f / l0, inv1 = 1.f / l1;

    const size_t z0 = hb + (size_t)rowg * HD_;
    const size_t z1 = z0 + (size_t)8 * HD_;
    #pragma unroll
    for (int nd = 0; nd < 8; nd++) {
        int col = nd * 8 + (lane & 3) * 2;
        float a0 = o[nd][0] * inv0, a1 = o[nd][1] * inv0;
        float b0 = o[nd][2] * inv1, b1 = o[nd][3] * inv1;
        float h00 = __bfloat162float(__float2bfloat16(a0));
        float h01 = __bfloat162float(__float2bfloat16(a1));
        float h10 = __bfloat162float(__float2bfloat16(b0));
        float h11 = __bfloat162float(__float2bfloat16(b1));
        *(uint32_t*)&Zhi[z0 + col] = pack_bf16(h00, h01);
        *(uint32_t*)&Zhi[z1 + col] = pack_bf16(h10, h11);
        *(uint32_t*)&Zlo[z0 + col] = pack_bf16(a0 - h00, a1 - h01);
        *(uint32_t*)&Zlo[z1 + col] = pack_bf16(b0 - h10, b1 - h11);
    }
}

// ---------------------------------------------------------------------------
// Launch
// ---------------------------------------------------------------------------
extern "C" void kernel_launch(void* const* d_in, const int* in_sizes, int n_in,
                              void* d_out, int out_size)
{
    const float* query = (const float*)d_in[0];
    const float* key_  = (const float*)d_in[1];
    const float* value = (const float*)d_in[2];
    const float* WQ = (const float*)d_in[4];
    const float* bQ = (const float*)d_in[5];
    const float* WK = (const float*)d_in[6];
    const float* bK = (const float*)d_in[7];
    const float* WV = (const float*)d_in[8];
    const float* bV = (const float*)d_in[9];
    const float* WO = (const float*)d_in[10];
    const float* bO = (const float*)d_in[11];
    float* out = (float*)d_out;

    __nv_bfloat16 *zhi, *zlo, *w1t, *w2t, *ihi, *ilo;
    __nv_bfloat16 *qhi, *qlo, *khi, *klo, *vhi, *vlo;
    cudaGetSymbolAddress((void**)&zhi, g_Zhi);
    cudaGetSymbolAddress((void**)&zlo, g_Zlo);
    cudaGetSymbolAddress((void**)&w1t, g_W1t);
    cudaGetSymbolAddress((void**)&w2t, g_W2t);
    cudaGetSymbolAddress((void**)&ihi, g_Ihi);
    cudaGetSymbolAddress((void**)&ilo, g_Ilo);
    cudaGetSymbolAddress((void**)&qhi, g_Qhi);
    cudaGetSymbolAddress((void**)&qlo, g_Qlo);
    cudaGetSymbolAddress((void**)&khi, g_Khi);
    cudaGetSymbolAddress((void**)&klo, g_Klo);
    cudaGetSymbolAddress((void**)&vhi, g_Vhi);
    cudaGetSymbolAddress((void**)&vlo, g_Vlo);

    const size_t MK = (size_t)M_ * K_GEMM;

    SplitArgs sp;
    sp.x[0] = query; sp.x[1] = key_; sp.x[2] = value;
    sp.hi[0] = ihi;          sp.lo[0] = ilo;
    sp.hi[1] = ihi + MK;     sp.lo[1] = ilo + MK;
    sp.hi[2] = ihi + 2 * MK; sp.lo[2] = ilo + 2 * MK;

    PrepArgs pp;
    pp.W[0] = WQ; pp.W[1] = WK; pp.W[2] = WV; pp.W[3] = WO;

    QkvArgs qa;
    qa.Ahi[0] = ihi;          qa.Alo[0] = ilo;
    qa.Ahi[1] = ihi + MK;     qa.Alo[1] = ilo + MK;
    qa.Ahi[2] = ihi + 2 * MK; qa.Alo[2] = ilo + 2 * MK;
    qa.bias[0] = bQ; qa.bias[1] = bK; qa.bias[2] = bV;
    qa.Ohi[0] = qhi; qa.Ohi[1] = khi; qa.Ohi[2] = vhi;
    qa.Olo[0] = qlo; qa.Olo[1] = klo; qa.Olo[2] = vlo;

    const int GEMM_SMEM = NSTAGE * STAGE_B;          // 81920
    const int ATTN_SMEM = KV_BASE + 2 * AT_STAGE;    // 110592
    cudaFuncSetAttribute(gemm_bf16x3_pipe<0>,
                         cudaFuncAttributeMaxDynamicSharedMemorySize, GEMM_SMEM);
    cudaFuncSetAttribute(gemm_bf16x3_pipe<1>,
                         cudaFuncAttributeMaxDynamicSharedMemorySize, GEMM_SMEM);
    cudaFuncSetAttribute(flash_attn_mma,
                         cudaFuncAttributeMaxDynamicSharedMemorySize, ATTN_SMEM);

    const int n4 = M_ * K_GEMM / 4;

    // 1. Split QKV inputs (one launch)
    split_bf16_kernel<<<dim3(n4 / 256, 1, 3), 256>>>(sp, n4);

    // 2. All weight preps (one launch)
    prep_w_kernel<<<dim3(N_GEMM / 32, K_GEMM / 32, 4), dim3(32, 8)>>>(pp, w1t, w2t);

    // 3. QKV projections (one launch, grid.z = 3)
    gemm_bf16x3_pipe<0><<<dim3(N_GEMM / 128, M_ / 128, 3), 256, GEMM_SMEM>>>(
        qa, nullptr, nullptr, w1t, w2t, nullptr, nullptr);

    // 4. Flash attention
    flash_attn_mma<<<dim3(S_ / 128, H_, B_), 256, ATTN_SMEM>>>(
        qhi, qlo, khi, klo, vhi, vlo, zhi, zlo);

    // 5. Output projection -> fp32 out
    gemm_bf16x3_pipe<1><<<dim3(N_GEMM / 128, M_ / 128, 1), 256, GEMM_SMEM>>>(
        qa, zhi, zlo, w1t, w2t, bO, out);
}

// round 10
// speedup vs baseline: 2.4409x; 2.2292x over previous
#include <cuda_runtime.h>
#include <cuda_fp16.h>
#include <cstdint>

// Problem constants
#define B_  2
#define S_  2048
#define E_  1024
#define H_  16
#define DH_ 64
#define HD_ 1024          // H*Dh
#define M_  (B_*S_)       // 4096 rows for all GEMMs
#define K_GEMM 1024
#define N_GEMM 1024

// ---------------------------------------------------------------------------
// Scratch (no cudaMalloc allowed) — all single fp16 now
// ---------------------------------------------------------------------------
__device__ __half g_Zh[M_ * K_GEMM];            // attention output
__device__ __half g_Wt[4 * N_GEMM * K_GEMM];    // 4 transposed weights [N][K]
__device__ __half g_Ih[3 * M_ * K_GEMM];        // converted inputs (q/k/v)
__device__ __half g_Qh[M_ * HD_];
__device__ __half g_Kh[M_ * HD_];
__device__ __half g_Vh[M_ * HD_];

struct QkvArgs {
    const __half* A[3];
    const float* bias[3];
    __half* O[3];
};
struct PrepArgs { const float* W[4]; };
struct SplitArgs {
    const float* x[3];
    __half* o[3];
};

__device__ __forceinline__ uint32_t smem_u32(const void* p) {
    uint32_t a;
    asm("{ .reg .u64 t; cvta.to.shared.u64 t, %1; cvt.u32.u64 %0, t; }" : "=r"(a) : "l"(p));
    return a;
}
__device__ __forceinline__ float ex2f(float x) {
    float y;
    asm("ex2.approx.ftz.f32 %0, %1;" : "=f"(y) : "f"(x));
    return y;
}
__device__ __forceinline__ uint32_t pack_h2(float a, float b) {
    __half2 t = __floats2half2_rn(a, b);
    return *reinterpret_cast<uint32_t*>(&t);
}

#define CP_ASYNC16(dst, src) \
    asm volatile("cp.async.cg.shared.global [%0], [%1], 16;" :: "r"(dst), "l"(src))
#define CP_COMMIT() asm volatile("cp.async.commit_group;" ::: "memory")
#define CP_WAIT(n)  asm volatile("cp.async.wait_group %0;" :: "n"(n) : "memory")

#define LDSM4(r0, r1, r2, r3, addr) \
    asm volatile("ldmatrix.sync.aligned.m8n8.x4.shared.b16 {%0,%1,%2,%3}, [%4];" \
                 : "=r"(r0), "=r"(r1), "=r"(r2), "=r"(r3) : "r"(addr))
#define LDSM4T(r0, r1, r2, r3, addr) \
    asm volatile("ldmatrix.sync.aligned.m8n8.x4.trans.shared.b16 {%0,%1,%2,%3}, [%4];" \
                 : "=r"(r0), "=r"(r1), "=r"(r2), "=r"(r3) : "r"(addr))
#define MMAH(d, a, b) \
    asm volatile("mma.sync.aligned.m16n8k16.row.col.f32.f16.f16.f32 " \
                 "{%0,%1,%2,%3}, {%4,%5,%6,%7}, {%8,%9}, {%0,%1,%2,%3};" \
                 : "+f"((d)[0]), "+f"((d)[1]), "+f"((d)[2]), "+f"((d)[3]) \
                 : "r"((a)[0]), "r"((a)[1]), "r"((a)[2]), "r"((a)[3]), \
                   "r"((b)[0]), "r"((b)[1]))

// ---------------------------------------------------------------------------
// Batched convert: fp32 inputs -> fp16. grid (n4/256, 1, 3)
// ---------------------------------------------------------------------------
__global__ void __launch_bounds__(256)
cvt_h_kernel(SplitArgs sa, int n4)
{
    int z = blockIdx.z;
    int i = blockIdx.x * blockDim.x + threadIdx.x;
    if (i >= n4) return;
    float4 v = ((const float4*)sa.x[z])[i];
    uint2 o;
    o.x = pack_h2(v.x, v.y);
    o.y = pack_h2(v.z, v.w);
    ((uint2*)sa.o[z])[i] = o;
}

// ---------------------------------------------------------------------------
// Weight prep (batched): W[K][N] fp32 -> Wt[z] [N][K] fp16 (transpose)
// ---------------------------------------------------------------------------
__global__ void __launch_bounds__(256)
prep_w_kernel(PrepArgs pa, __half* __restrict__ wt)
{
    __shared__ float t[32][33];
    const float* W = pa.W[blockIdx.z];
    const size_t zoff = (size_t)blockIdx.z * N_GEMM * K_GEMM;
    int n0 = blockIdx.x * 32, k0 = blockIdx.y * 32;
    int tx = threadIdx.x, ty = threadIdx.y;
    #pragma unroll
    for (int i = 0; i < 4; i++)
        t[ty + 8 * i][tx] = W[(size_t)(k0 + ty + 8 * i) * N_GEMM + n0 + tx];
    __syncthreads();
    #pragma unroll
    for (int i = 0; i < 4; i++) {
        float v = t[tx][ty + 8 * i];
        wt[zoff + (size_t)(n0 + ty + 8 * i) * K_GEMM + k0 + tx] = __float2half_rn(v);
    }
}

// ---------------------------------------------------------------------------
// HMMA fp16 single-term GEMM, 4-stage cp.async pipeline, 2 CTAs/SM.
//  MODE 0 (QKV, grid.z=3): A = qa.A[z], out fp16 qa.O[z] + bias
//  MODE 1 (O-proj): A = Ah_, out fp32 + biasO
// CTA 128x128, BK=32, 8 warps (4M x 2N).
// ---------------------------------------------------------------------------
#define LDP 80
#define TILE_B (128 * LDP)      // 10240
#define STAGE_B (2 * TILE_B)    // 20480 (A | W)
#define NSTAGE 4

template<int MODE>
__global__ void __launch_bounds__(256, 2)
gemm_h_pipe(QkvArgs qa,
            const __half* __restrict__ Ah_,
            const __half* __restrict__ Wbase,
            const float* __restrict__ biasO,
            float* __restrict__ Cout)
{
    extern __shared__ __align__(16) char smem[];
    const uint32_t sb = smem_u32(smem);
    const int z = blockIdx.z;
    const int tid = threadIdx.x;
    const int wid = tid >> 5, lane = tid & 31;
    const int n0 = blockIdx.x * 128, m0 = blockIdx.y * 128;
    const int mw = (wid & 3) * 32;
    const int nw = (wid >> 2) * 64;

    const size_t woff = (MODE == 0 ? (size_t)z : (size_t)3) * N_GEMM * K_GEMM;
    const __half* gW = Wbase + woff + (size_t)n0 * K_GEMM;
    const __half* gA = (MODE == 0 ? qa.A[z] : Ah_) + (size_t)m0 * K_GEMM;

    float acc[2][8][4];
    #pragma unroll
    for (int mi = 0; mi < 2; mi++)
        #pragma unroll
        for (int ni = 0; ni < 8; ni++)
            #pragma unroll
            for (int r = 0; r < 4; r++) acc[mi][ni][r] = 0.f;

    const int row_[2] = { tid >> 2, (tid + 256) >> 2 };
    const int cc_[2]  = { tid & 3, (tid + 256) & 3 };

    auto issue_chunk = [&](int c) {
        uint32_t base = sb + (c & (NSTAGE - 1)) * STAGE_B;
        int k0 = c * 32;
        #pragma unroll
        for (int t = 0; t < 2; t++) {
            int row = row_[t], cc = cc_[t];
            uint32_t so = row * LDP + cc * 16;
            size_t go = (size_t)row * K_GEMM + k0 + cc * 8;
            CP_ASYNC16(base + 0 * TILE_B + so, gA + go);
            CP_ASYNC16(base + 1 * TILE_B + so, gW + go);
        }
    };

    const uint32_t a_row = mw + (lane & 15);
    const uint32_t a_kadd = (lane >> 4) << 4;
    const uint32_t b_rowbase = nw + (lane & 7) + (((lane >> 4) & 1) << 3);
    const uint32_t b_kadd = ((lane >> 3) & 1) << 4;

    const int NCHUNK = K_GEMM / 32;   // 32
    issue_chunk(0); CP_COMMIT();
    issue_chunk(1); CP_COMMIT();
    issue_chunk(2); CP_COMMIT();

    for (int c = 0; c < NCHUNK; c++) {
        if (c + 3 <= NCHUNK - 1) { CP_WAIT(2); }
        else if (c + 2 <= NCHUNK - 1) { CP_WAIT(1); }
        else { CP_WAIT(0); }
        __syncthreads();

        const uint32_t stg = sb + (c & (NSTAGE - 1)) * STAGE_B;
        const uint32_t sA = stg, sW = stg + TILE_B;

        #pragma unroll
        for (int s = 0; s < 2; s++) {
            const uint32_t kb = s * 32;
            uint32_t af[2][4];
            #pragma unroll
            for (int mi = 0; mi < 2; mi++)
                LDSM4(af[mi][0], af[mi][1], af[mi][2], af[mi][3],
                      sA + (a_row + mi * 16) * LDP + kb + a_kadd);
            uint32_t bf[8][2];
            #pragma unroll
            for (int g = 0; g < 4; g++)
                LDSM4(bf[2*g][0], bf[2*g][1], bf[2*g+1][0], bf[2*g+1][1],
                      sW + (b_rowbase + g * 16) * LDP + kb + b_kadd);
            #pragma unroll
            for (int mi = 0; mi < 2; mi++)
                #pragma unroll
                for (int ni = 0; ni < 8; ni++)
                    MMAH(acc[mi][ni], af[mi], bf[ni]);
        }
        __syncthreads();
        if (c + 3 < NCHUNK) { issue_chunk(c + 3); CP_COMMIT(); }
    }

    // ---- epilogue ----
    const float* bias = (MODE == 0) ? qa.bias[z] : biasO;
    const int erow = m0 + mw + (lane >> 2);
    const int ecol0 = n0 + nw + (lane & 3) * 2;
    #pragma unroll
    for (int mi = 0; mi < 2; mi++) {
        #pragma unroll
        for (int ni = 0; ni < 8; ni++) {
            int col = ecol0 + ni * 8;
            float b0 = bias[col], b1 = bias[col + 1];
            int r0 = erow + mi * 16;
            float v00 = acc[mi][ni][0] + b0, v01 = acc[mi][ni][1] + b1;
            float v10 = acc[mi][ni][2] + b0, v11 = acc[mi][ni][3] + b1;
            if (MODE == 1) {
                float2 w0 = { v00, v01 }, w1 = { v10, v11 };
                *(float2*)&Cout[(size_t)r0 * N_GEMM + col] = w0;
                *(float2*)&Cout[(size_t)(r0 + 8) * N_GEMM + col] = w1;
            } else {
                __half* Co = qa.O[z];
                *(uint32_t*)&Co[(size_t)r0 * N_GEMM + col] = pack_h2(v00, v01);
                *(uint32_t*)&Co[(size_t)(r0 + 8) * N_GEMM + col] = pack_h2(v10, v11);
            }
        }
    }
}

// ---------------------------------------------------------------------------
// HMMA fp16 flash attention, causal, single-term, online softmax (ex2),
// 2-stage cp.async K/V, 2 CTAs/SM, heavy-CTA-first. Q in registers.
// SMEM/CTA = 2 stages x 18432 = 36864. Q staged through stage 0.
// ---------------------------------------------------------------------------
#define LDK 144
#define AT_STAGE 18432
#define OF_K 0
#define OF_V 9216

__global__ void __launch_bounds__(256, 2)
flash_attn_mma(const __half* __restrict__ Qh, const __half* __restrict__ Kh,
               const __half* __restrict__ Vh, __half* __restrict__ Zh)
{
    extern __shared__ __align__(16) char sm[];
    const uint32_t sb = smem_u32(sm);
    const int tid = threadIdx.x, wid = tid >> 5, lane = tid & 31;
    const int b = blockIdx.z, h = blockIdx.y;
    const int qt = gridDim.x - 1 - blockIdx.x;      // heavy CTAs first
    const int q0 = qt * 128;
    const size_t hb = (size_t)b * S_ * HD_ + h * DH_;

    const uint32_t arow = wid * 16 + (lane & 15);
    const uint32_t akadd = (lane >> 4) << 4;

    // Stage Q (128 rows x 128B) through stage-0 region via cp.async, then
    // ldmatrix into registers.
    #pragma unroll
    for (int t = 0; t < 4; t++) {
        int idx = tid + t * 256; int row = idx >> 3, cc = idx & 7;
        CP_ASYNC16(sb + row * LDK + cc * 16,
                   Qh + hb + (size_t)(q0 + row) * HD_ + cc * 8);
    }
    CP_COMMIT(); CP_WAIT(0);
    __syncthreads();
    uint32_t q[4][4];
    #pragma unroll
    for (int ks = 0; ks < 4; ks++)
        LDSM4(q[ks][0], q[ks][1], q[ks][2], q[ks][3],
              sb + arow * LDK + ks * 32 + akadd);
    __syncthreads();   // all warps done reading Q; stage 0 free

    auto issue_tile = [&](int kt) {
        uint32_t base = sb + (kt & 1) * AT_STAGE;
        int k0 = kt * 64;
        #pragma unroll
        for (int t = 0; t < 2; t++) {
            int idx = tid + t * 256; int row = idx >> 3, cc = idx & 7;
            size_t g = hb + (size_t)(k0 + row) * HD_ + cc * 8;
            uint32_t so = row * LDK + cc * 16;
            CP_ASYNC16(base + OF_K + so, Kh + g);
            CP_ASYNC16(base + OF_V + so, Vh + g);
        }
    };

    float o[8][4];
    #pragma unroll
    for (int i = 0; i < 8; i++)
        #pragma unroll
        for (int j = 0; j < 4; j++) o[i][j] = 0.f;
    float m0 = -1e30f, m1 = -1e30f, l0 = 0.f, l1 = 0.f;

    const uint32_t browbase = (lane & 7) + (((lane >> 4) & 1) << 3);
    const uint32_t bkadd = ((lane >> 3) & 1) << 4;
    const uint32_t vrow = lane & 15;
    const uint32_t vnadd = (lane >> 4) << 4;
    const float alpha = 0.125f * 1.4426950408889634f;
    const int rowg = q0 + wid * 16 + (lane >> 2);

    const int nt = 2 * qt + 2;    // >= 2 always
    issue_tile(0); CP_COMMIT();
    issue_tile(1); CP_COMMIT();

    for (int kt = 0; kt < nt; kt++) {
        if (kt + 1 < nt) { CP_WAIT(1); } else { CP_WAIT(0); }
        __syncthreads();
        const uint32_t stg = sb + (kt & 1) * AT_STAGE;
        const int k0 = kt * 64;

        // S = Q K^T (single term)
        float s[8][4];
        #pragma unroll
        for (int i = 0; i < 8; i++)
            #pragma unroll
            for (int j = 0; j < 4; j++) s[i][j] = 0.f;
        #pragma unroll
        for (int ks = 0; ks < 4; ks++) {
            uint32_t kf_[8][2];
            #pragma unroll
            for (int g = 0; g < 4; g++)
                LDSM4(kf_[2*g][0], kf_[2*g][1], kf_[2*g+1][0], kf_[2*g+1][1],
                      stg + OF_K + (browbase + g * 16) * LDK + ks * 32 + bkadd);
            #pragma unroll
            for (int ni = 0; ni < 8; ni++)
                MMAH(s[ni], q[ks], kf_[ni]);
        }

        // scale + causal mask (only warp bands intersecting the diagonal)
        if (k0 + 63 > q0 + wid * 16) {
            #pragma unroll
            for (int ni = 0; ni < 8; ni++) {
                int colg = k0 + ni * 8 + (lane & 3) * 2;
                s[ni][0] = (colg     <= rowg    ) ? s[ni][0] * alpha : -1e30f;
                s[ni][1] = (colg + 1 <= rowg    ) ? s[ni][1] * alpha : -1e30f;
                s[ni][2] = (colg     <= rowg + 8) ? s[ni][2] * alpha : -1e30f;
                s[ni][3] = (colg + 1 <= rowg + 8) ? s[ni][3] * alpha : -1e30f;
            }
        } else {
            #pragma unroll
            for (int ni = 0; ni < 8; ni++)
                #pragma unroll
                for (int j = 0; j < 4; j++) s[ni][j] *= alpha;
        }

        // online softmax
        float mx0 = m0, mx1 = m1;
        #pragma unroll
        for (int ni = 0; ni < 8; ni++) {
            mx0 = fmaxf(mx0, fmaxf(s[ni][0], s[ni][1]));
            mx1 = fmaxf(mx1, fmaxf(s[ni][2], s[ni][3]));
        }
        mx0 = fmaxf(mx0, __shfl_xor_sync(0xffffffffu, mx0, 1));
        mx0 = fmaxf(mx0, __shfl_xor_sync(0xffffffffu, mx0, 2));
        mx1 = fmaxf(mx1, __shfl_xor_sync(0xffffffffu, mx1, 1));
        mx1 = fmaxf(mx1, __shfl_xor_sync(0xffffffffu, mx1, 2));

        float sc0 = ex2f(m0 - mx0), sc1 = ex2f(m1 - mx1);
        l0 *= sc0; l1 *= sc1;
        #pragma unroll
        for (int ni = 0; ni < 8; ni++) {
            o[ni][0] *= sc0; o[ni][1] *= sc0;
            o[ni][2] *= sc1; o[ni][3] *= sc1;
        }
        m0 = mx0; m1 = mx1;

        // PV: P built per kf slice, single term
        float rs0 = 0.f, rs1 = 0.f;
        #pragma unroll
        for (int kf = 0; kf < 4; kf++) {
            uint32_t p[4];
            #pragma unroll
            for (int j = 0; j < 2; j++) {
                int ni = 2 * kf + j;
                float p0 = ex2f(s[ni][0] - mx0);
                float p1 = ex2f(s[ni][1] - mx0);
                float p2 = ex2f(s[ni][2] - mx1);
                float p3 = ex2f(s[ni][3] - mx1);
                rs0 += p0 + p1; rs1 += p2 + p3;
                p[j * 2 + 0] = pack_h2(p0, p1);
                p[j * 2 + 1] = pack_h2(p2, p3);
            }
            uint32_t vf[8][2];
            #pragma unroll
            for (int g = 0; g < 4; g++)
                LDSM4T(vf[2*g][0], vf[2*g][1], vf[2*g+1][0], vf[2*g+1][1],
                       stg + OF_V + (kf * 16 + vrow) * LDK + g * 32 + vnadd);
            #pragma unroll
            for (int nd = 0; nd < 8; nd++)
                MMAH(o[nd], p, vf[nd]);
        }
        l0 += rs0; l1 += rs1;

        __syncthreads();
        if (kt + 2 < nt) { issue_tile(kt + 2); CP_COMMIT(); }
    }

    // finalize
    l0 += __shfl_xor_sync(0xffffffffu, l0, 1);
    l0 += __shfl_xor_sync(0xffffffffu, l0, 2);
    l1 += __shfl_xor_sync(0xffffffffu, l1, 1);
    l1 += __shfl_xor_sync(0xffffffffu, l1, 2);
    const float inv0 = 1.f / l0, inv1 = 1.f / l1;

    const size_t z0 = hb + (size_t)rowg * HD_;
    const size_t z1 = z0 + (size_t)8 * HD_;
    #pragma unroll
    for (int nd = 0; nd < 8; nd++) {
        int col = nd * 8 + (lane & 3) * 2;
        *(uint32_t*)&Zh[z0 + col] = pack_h2(o[nd][0] * inv0, o[nd][1] * inv0);
        *(uint32_t*)&Zh[z1 + col] = pack_h2(o[nd][2] * inv1, o[nd][3] * inv1);
    }
}

// ---------------------------------------------------------------------------
// Launch
// ---------------------------------------------------------------------------
extern "C" void kernel_launch(void* const* d_in, const int* in_sizes, int n_in,
                              void* d_out, int out_size)
{
    const float* query = (const float*)d_in[0];
    const float* key_  = (const float*)d_in[1];
    const float* value = (const float*)d_in[2];
    const float* WQ = (const float*)d_in[4];
    const float* bQ = (const float*)d_in[5];
    const float* WK = (const float*)d_in[6];
    const float* bK = (const float*)d_in[7];
    const float* WV = (const float*)d_in[8];
    const float* bV = (const float*)d_in[9];
    const float* WO = (const float*)d_in[10];
    const float* bO = (const float*)d_in[11];
    float* out = (float*)d_out;

    __half *zh, *wt, *ih, *qh, *kh, *vh;
    cudaGetSymbolAddress((void**)&zh, g_Zh);
    cudaGetSymbolAddress((void**)&wt, g_Wt);
    cudaGetSymbolAddress((void**)&ih, g_Ih);
    cudaGetSymbolAddress((void**)&qh, g_Qh);
    cudaGetSymbolAddress((void**)&kh, g_Kh);
    cudaGetSymbolAddress((void**)&vh, g_Vh);

    const size_t MK = (size_t)M_ * K_GEMM;

    SplitArgs sp;
    sp.x[0] = query; sp.x[1] = key_; sp.x[2] = value;
    sp.o[0] = ih; sp.o[1] = ih + MK; sp.o[2] = ih + 2 * MK;

    PrepArgs pp;
    pp.W[0] = WQ; pp.W[1] = WK; pp.W[2] = WV; pp.W[3] = WO;

    QkvArgs qa;
    qa.A[0] = ih; qa.A[1] = ih + MK; qa.A[2] = ih + 2 * MK;
    qa.bias[0] = bQ; qa.bias[1] = bK; qa.bias[2] = bV;
    qa.O[0] = qh; qa.O[1] = kh; qa.O[2] = vh;

    const int GEMM_SMEM = NSTAGE * STAGE_B;   // 81920
    const int ATTN_SMEM = 2 * AT_STAGE;       // 36864
    cudaFuncSetAttribute(gemm_h_pipe<0>,
                         cudaFuncAttributeMaxDynamicSharedMemorySize, GEMM_SMEM);
    cudaFuncSetAttribute(gemm_h_pipe<1>,
                         cudaFuncAttributeMaxDynamicSharedMemorySize, GEMM_SMEM);
    cudaFuncSetAttribute(flash_attn_mma,
                         cudaFuncAttributeMaxDynamicSharedMemorySize, ATTN_SMEM);

    const int n4 = M_ * K_GEMM / 4;

    // 1. Convert QKV inputs to fp16 (one launch)
    cvt_h_kernel<<<dim3(n4 / 256, 1, 3), 256>>>(sp, n4);

    // 2. All weight preps (one launch)
    prep_w_kernel<<<dim3(N_GEMM / 32, K_GEMM / 32, 4), dim3(32, 8)>>>(pp, wt);

    // 3. QKV projections (one launch, grid.z = 3)
    gemm_h_pipe<0><<<dim3(N_GEMM / 128, M_ / 128, 3), 256, GEMM_SMEM>>>(
        qa, nullptr, wt, nullptr, nullptr);

    // 4. Flash attention
    flash_attn_mma<<<dim3(S_ / 128, H_, B_), 256, ATTN_SMEM>>>(
        qh, kh, vh, zh);

    // 5. Output projection -> fp32 out
    gemm_h_pipe<1><<<dim3(N_GEMM / 128, M_ / 128, 1), 256, GEMM_SMEM>>>(
        qa, zh, wt, bO, out);
}

// round 11
// speedup vs baseline: 2.5222x; 1.0333x over previous
#include <cuda_runtime.h>
#include <cuda_fp16.h>
#include <cstdint>

// Problem constants
#define B_  2
#define S_  2048
#define E_  1024
#define H_  16
#define DH_ 64
#define HD_ 1024          // H*Dh
#define M_  (B_*S_)       // 4096 rows for all GEMMs
#define K_GEMM 1024
#define N_GEMM 1024

// ---------------------------------------------------------------------------
// Scratch (no cudaMalloc allowed) — all single fp16
// ---------------------------------------------------------------------------
__device__ __half g_Zh[M_ * K_GEMM];            // attention output
__device__ __half g_Wt[4 * N_GEMM * K_GEMM];    // 4 transposed weights [N][K]
__device__ __half g_Ih[3 * M_ * K_GEMM];        // converted inputs (q/k/v)
__device__ __half g_Qh[M_ * HD_];
__device__ __half g_Kh[M_ * HD_];
__device__ __half g_Vh[M_ * HD_];

struct QkvArgs {
    const __half* A[3];
    const float* bias[3];
    __half* O[3];
};
struct PrepCvtArgs {
    const float* x[3];    // cvt inputs
    __half* o[3];         // cvt outputs
    const float* W[4];    // prep inputs
    __half* wt;           // prep output base
};

__device__ __forceinline__ uint32_t smem_u32(const void* p) {
    uint32_t a;
    asm("{ .reg .u64 t; cvta.to.shared.u64 t, %1; cvt.u32.u64 %0, t; }" : "=r"(a) : "l"(p));
    return a;
}
__device__ __forceinline__ float ex2f(float x) {
    float y;
    asm("ex2.approx.ftz.f32 %0, %1;" : "=f"(y) : "f"(x));
    return y;
}
__device__ __forceinline__ uint32_t pack_h2(float a, float b) {
    __half2 t = __floats2half2_rn(a, b);
    return *reinterpret_cast<uint32_t*>(&t);
}

#define CP_ASYNC16(dst, src) \
    asm volatile("cp.async.cg.shared.global [%0], [%1], 16;" :: "r"(dst), "l"(src))
#define CP_COMMIT() asm volatile("cp.async.commit_group;" ::: "memory")
#define CP_WAIT(n)  asm volatile("cp.async.wait_group %0;" :: "n"(n) : "memory")

#define LDSM4(r0, r1, r2, r3, addr) \
    asm volatile("ldmatrix.sync.aligned.m8n8.x4.shared.b16 {%0,%1,%2,%3}, [%4];" \
                 : "=r"(r0), "=r"(r1), "=r"(r2), "=r"(r3) : "r"(addr))
#define LDSM4T(r0, r1, r2, r3, addr) \
    asm volatile("ldmatrix.sync.aligned.m8n8.x4.trans.shared.b16 {%0,%1,%2,%3}, [%4];" \
                 : "=r"(r0), "=r"(r1), "=r"(r2), "=r"(r3) : "r"(addr))
#define MMAH(d, a, b) \
    asm volatile("mma.sync.aligned.m16n8k16.row.col.f32.f16.f16.f32 " \
                 "{%0,%1,%2,%3}, {%4,%5,%6,%7}, {%8,%9}, {%0,%1,%2,%3};" \
                 : "+f"((d)[0]), "+f"((d)[1]), "+f"((d)[2]), "+f"((d)[3]) \
                 : "r"((a)[0]), "r"((a)[1]), "r"((a)[2]), "r"((a)[3]), \
                   "r"((b)[0]), "r"((b)[1]))

// ---------------------------------------------------------------------------
// Fused prep: blocks [0, 12288) convert q/k/v fp32->fp16; blocks [12288, 16384)
// transpose+convert the 4 weight matrices. One launch.
// ---------------------------------------------------------------------------
#define CVT_BLOCKS (3 * 4096)
__global__ void __launch_bounds__(256)
prep_all_kernel(PrepCvtArgs pa)
{
    __shared__ float t[32][33];
    const int bid = blockIdx.x;
    const int tid = threadIdx.x;
    if (bid < CVT_BLOCKS) {
        int z = bid >> 12;                 // /4096
        int i = (bid & 4095) * 256 + tid;  // element/4 index
        float4 v = ((const float4*)pa.x[z])[i];
        uint2 o;
        o.x = pack_h2(v.x, v.y);
        o.y = pack_h2(v.z, v.w);
        ((uint2*)pa.o[z])[i] = o;
    } else {
        int pid = bid - CVT_BLOCKS;        // 0..4095
        int z = pid >> 10;                 // /1024
        int idx = pid & 1023;
        int n0 = (idx & 31) * 32, k0 = (idx >> 5) * 32;
        int tx = tid & 31, ty = tid >> 5;  // 32 x 8
        const float* W = pa.W[z];
        const size_t zoff = (size_t)z * N_GEMM * K_GEMM;
        #pragma unroll
        for (int i = 0; i < 4; i++)
            t[ty + 8 * i][tx] = W[(size_t)(k0 + ty + 8 * i) * N_GEMM + n0 + tx];
        __syncthreads();
        #pragma unroll
        for (int i = 0; i < 4; i++) {
            float v = t[tx][ty + 8 * i];
            pa.wt[zoff + (size_t)(n0 + ty + 8 * i) * K_GEMM + k0 + tx] = __float2half_rn(v);
        }
    }
}

// ---------------------------------------------------------------------------
// HMMA fp16 GEMM, 4-stage cp.async pipeline, 2 CTAs/SM, ONE barrier/chunk.
// ---------------------------------------------------------------------------
#define LDP 80
#define TILE_B (128 * LDP)      // 10240
#define STAGE_B (2 * TILE_B)    // 20480 (A | W)
#define NSTAGE 4

template<int MODE>
__global__ void __launch_bounds__(256, 2)
gemm_h_pipe(QkvArgs qa,
            const __half* __restrict__ Ah_,
            const __half* __restrict__ Wbase,
            const float* __restrict__ biasO,
            float* __restrict__ Cout)
{
    extern __shared__ __align__(16) char smem[];
    const uint32_t sb = smem_u32(smem);
    const int z = blockIdx.z;
    const int tid = threadIdx.x;
    const int wid = tid >> 5, lane = tid & 31;
    const int n0 = blockIdx.x * 128, m0 = blockIdx.y * 128;
    const int mw = (wid & 3) * 32;
    const int nw = (wid >> 2) * 64;

    const size_t woff = (MODE == 0 ? (size_t)z : (size_t)3) * N_GEMM * K_GEMM;
    const __half* gW = Wbase + woff + (size_t)n0 * K_GEMM;
    const __half* gA = (MODE == 0 ? qa.A[z] : Ah_) + (size_t)m0 * K_GEMM;

    float acc[2][8][4];
    #pragma unroll
    for (int mi = 0; mi < 2; mi++)
        #pragma unroll
        for (int ni = 0; ni < 8; ni++)
            #pragma unroll
            for (int r = 0; r < 4; r++) acc[mi][ni][r] = 0.f;

    const int row_[2] = { tid >> 2, (tid + 256) >> 2 };
    const int cc_[2]  = { tid & 3, (tid + 256) & 3 };

    auto issue_chunk = [&](int c) {
        uint32_t base = sb + (c & (NSTAGE - 1)) * STAGE_B;
        int k0 = c * 32;
        #pragma unroll
        for (int t = 0; t < 2; t++) {
            int row = row_[t], cc = cc_[t];
            uint32_t so = row * LDP + cc * 16;
            size_t go = (size_t)row * K_GEMM + k0 + cc * 8;
            CP_ASYNC16(base + 0 * TILE_B + so, gA + go);
            CP_ASYNC16(base + 1 * TILE_B + so, gW + go);
        }
    };

    const uint32_t a_row = mw + (lane & 15);
    const uint32_t a_kadd = (lane >> 4) << 4;
    const uint32_t b_rowbase = nw + (lane & 7) + (((lane >> 4) & 1) << 3);
    const uint32_t b_kadd = ((lane >> 3) & 1) << 4;

    const int NCHUNK = K_GEMM / 32;   // 32
    issue_chunk(0); CP_COMMIT();
    issue_chunk(1); CP_COMMIT();
    issue_chunk(2); CP_COMMIT();

    for (int c = 0; c < NCHUNK; c++) {
        if (c + 3 <= NCHUNK - 1) { CP_WAIT(2); }
        else if (c + 2 <= NCHUNK - 1) { CP_WAIT(1); }
        else { CP_WAIT(0); }
        __syncthreads();     // single barrier per chunk

        const uint32_t stg = sb + (c & (NSTAGE - 1)) * STAGE_B;
        const uint32_t sA = stg, sW = stg + TILE_B;

        #pragma unroll
        for (int s = 0; s < 2; s++) {
            const uint32_t kb = s * 32;
            uint32_t af[2][4];
            #pragma unroll
            for (int mi = 0; mi < 2; mi++)
                LDSM4(af[mi][0], af[mi][1], af[mi][2], af[mi][3],
                      sA + (a_row + mi * 16) * LDP + kb + a_kadd);
            uint32_t bf[8][2];
            #pragma unroll
            for (int g = 0; g < 4; g++)
                LDSM4(bf[2*g][0], bf[2*g][1], bf[2*g+1][0], bf[2*g+1][1],
                      sW + (b_rowbase + g * 16) * LDP + kb + b_kadd);
            #pragma unroll
            for (int mi = 0; mi < 2; mi++)
                #pragma unroll
                for (int ni = 0; ni < 8; ni++)
                    MMAH(acc[mi][ni], af[mi], bf[ni]);
        }
        // Issue into stage (c+3)%4 — disjoint from stage c being read this
        // iteration; overwrite of stage c%4 (at c+4) is ordered by the next
        // iteration's top barrier.
        if (c + 3 < NCHUNK) { issue_chunk(c + 3); CP_COMMIT(); }
    }

    // ---- epilogue ----
    const float* bias = (MODE == 0) ? qa.bias[z] : biasO;
    const int erow = m0 + mw + (lane >> 2);
    const int ecol0 = n0 + nw + (lane & 3) * 2;
    #pragma unroll
    for (int mi = 0; mi < 2; mi++) {
        #pragma unroll
        for (int ni = 0; ni < 8; ni++) {
            int col = ecol0 + ni * 8;
            float b0 = bias[col], b1 = bias[col + 1];
            int r0 = erow + mi * 16;
            float v00 = acc[mi][ni][0] + b0, v01 = acc[mi][ni][1] + b1;
            float v10 = acc[mi][ni][2] + b0, v11 = acc[mi][ni][3] + b1;
            if (MODE == 1) {
                float2 w0 = { v00, v01 }, w1 = { v10, v11 };
                *(float2*)&Cout[(size_t)r0 * N_GEMM + col] = w0;
                *(float2*)&Cout[(size_t)(r0 + 8) * N_GEMM + col] = w1;
            } else {
                __half* Co = qa.O[z];
                *(uint32_t*)&Co[(size_t)r0 * N_GEMM + col] = pack_h2(v00, v01);
                *(uint32_t*)&Co[(size_t)(r0 + 8) * N_GEMM + col] = pack_h2(v10, v11);
            }
        }
    }
}

// ---------------------------------------------------------------------------
// HMMA fp16 flash attention, causal, online softmax (alpha folded into ex2),
// 3-stage cp.async K/V ring, ONE barrier/tile, 2 CTAs/SM, heavy-CTA-first.
// SMEM/CTA = 3 x 18432 = 55296.
// ---------------------------------------------------------------------------
#define LDK 144
#define AT_STAGE 18432
#define OF_K 0
#define OF_V 9216

__global__ void __launch_bounds__(256, 2)
flash_attn_mma(const __half* __restrict__ Qh, const __half* __restrict__ Kh,
               const __half* __restrict__ Vh, __half* __restrict__ Zh)
{
    extern __shared__ __align__(16) char sm[];
    const uint32_t sb = smem_u32(sm);
    const int tid = threadIdx.x, wid = tid >> 5, lane = tid & 31;
    const int b = blockIdx.z, h = blockIdx.y;
    const int qt = gridDim.x - 1 - blockIdx.x;      // heavy CTAs first
    const int q0 = qt * 128;
    const size_t hb = (size_t)b * S_ * HD_ + h * DH_;

    const uint32_t arow = wid * 16 + (lane & 15);
    const uint32_t akadd = (lane >> 4) << 4;

    // Stage Q through stage-0 region via cp.async, ldmatrix into registers.
    #pragma unroll
    for (int t = 0; t < 4; t++) {
        int idx = tid + t * 256; int row = idx >> 3, cc = idx & 7;
        CP_ASYNC16(sb + row * LDK + cc * 16,
                   Qh + hb + (size_t)(q0 + row) * HD_ + cc * 8);
    }
    CP_COMMIT(); CP_WAIT(0);
    __syncthreads();
    uint32_t q[4][4];
    #pragma unroll
    for (int ks = 0; ks < 4; ks++)
        LDSM4(q[ks][0], q[ks][1], q[ks][2], q[ks][3],
              sb + arow * LDK + ks * 32 + akadd);
    __syncthreads();   // all warps done reading Q; stage 0 free

    auto issue_tile = [&](int kt) {
        uint32_t base = sb + (kt % 3) * AT_STAGE;
        int k0 = kt * 64;
        #pragma unroll
        for (int t = 0; t < 2; t++) {
            int idx = tid + t * 256; int row = idx >> 3, cc = idx & 7;
            size_t g = hb + (size_t)(k0 + row) * HD_ + cc * 8;
            uint32_t so = row * LDK + cc * 16;
            CP_ASYNC16(base + OF_K + so, Kh + g);
            CP_ASYNC16(base + OF_V + so, Vh + g);
        }
    };

    float o[8][4];
    #pragma unroll
    for (int i = 0; i < 8; i++)
        #pragma unroll
        for (int j = 0; j < 4; j++) o[i][j] = 0.f;
    float m0 = -1e30f, m1 = -1e30f, l0 = 0.f, l1 = 0.f;

    const uint32_t browbase = (lane & 7) + (((lane >> 4) & 1) << 3);
    const uint32_t bkadd = ((lane >> 3) & 1) << 4;
    const uint32_t vrow = lane & 15;
    const uint32_t vnadd = (lane >> 4) << 4;
    const float alpha = 0.125f * 1.4426950408889634f;   // 1/sqrt(64) * log2(e)
    const int rowg = q0 + wid * 16 + (lane >> 2);

    const int nt = 2 * qt + 2;    // >= 2 always
    issue_tile(0); CP_COMMIT();
    issue_tile(1); CP_COMMIT();

    for (int kt = 0; kt < nt; kt++) {
        if (kt + 1 < nt) { CP_WAIT(1); } else { CP_WAIT(0); }
        __syncthreads();       // single barrier per tile
        const uint32_t stg = sb + (kt % 3) * AT_STAGE;
        const int k0 = kt * 64;

        // S = Q K^T (raw scores; alpha applied inside ex2)
        float s[8][4];
        #pragma unroll
        for (int i = 0; i < 8; i++)
            #pragma unroll
            for (int j = 0; j < 4; j++) s[i][j] = 0.f;
        #pragma unroll
        for (int ks = 0; ks < 4; ks++) {
            uint32_t kf_[8][2];
            #pragma unroll
            for (int g = 0; g < 4; g++)
                LDSM4(kf_[2*g][0], kf_[2*g][1], kf_[2*g+1][0], kf_[2*g+1][1],
                      stg + OF_K + (browbase + g * 16) * LDK + ks * 32 + bkadd);
            #pragma unroll
            for (int ni = 0; ni < 8; ni++)
                MMAH(s[ni], q[ks], kf_[ni]);
        }

        // causal mask (raw domain; no scaling here)
        if (k0 + 63 > q0 + wid * 16) {
            #pragma unroll
            for (int ni = 0; ni < 8; ni++) {
                int colg = k0 + ni * 8 + (lane & 3) * 2;
                if (colg     > rowg    ) s[ni][0] = -1e30f;
                if (colg + 1 > rowg    ) s[ni][1] = -1e30f;
                if (colg     > rowg + 8) s[ni][2] = -1e30f;
                if (colg + 1 > rowg + 8) s[ni][3] = -1e30f;
            }
        }

        // online softmax (max in raw domain)
        float mx0 = m0, mx1 = m1;
        #pragma unroll
        for (int ni = 0; ni < 8; ni++) {
            mx0 = fmaxf(mx0, fmaxf(s[ni][0], s[ni][1]));
            mx1 = fmaxf(mx1, fmaxf(s[ni][2], s[ni][3]));
        }
        mx0 = fmaxf(mx0, __shfl_xor_sync(0xffffffffu, mx0, 1));
        mx0 = fmaxf(mx0, __shfl_xor_sync(0xffffffffu, mx0, 2));
        mx1 = fmaxf(mx1, __shfl_xor_sync(0xffffffffu, mx1, 1));
        mx1 = fmaxf(mx1, __shfl_xor_sync(0xffffffffu, mx1, 2));

        const float mxa0 = mx0 * alpha, mxa1 = mx1 * alpha;
        float sc0 = ex2f(fmaf(m0, alpha, -mxa0));
        float sc1 = ex2f(fmaf(m1, alpha, -mxa1));
        l0 *= sc0; l1 *= sc1;
        #pragma unroll
        for (int ni = 0; ni < 8; ni++) {
            o[ni][0] *= sc0; o[ni][1] *= sc0;
            o[ni][2] *= sc1; o[ni][3] *= sc1;
        }
        m0 = mx0; m1 = mx1;

        // PV: P built per kf slice via single FFMA + ex2
        float rs0 = 0.f, rs1 = 0.f;
        #pragma unroll
        for (int kf = 0; kf < 4; kf++) {
            uint32_t p[4];
            #pragma unroll
            for (int j = 0; j < 2; j++) {
                int ni = 2 * kf + j;
                float p0 = ex2f(fmaf(s[ni][0], alpha, -mxa0));
                float p1 = ex2f(fmaf(s[ni][1], alpha, -mxa0));
                float p2 = ex2f(fmaf(s[ni][2], alpha, -mxa1));
                float p3 = ex2f(fmaf(s[ni][3], alpha, -mxa1));
                rs0 += p0 + p1; rs1 += p2 + p3;
                p[j * 2 + 0] = pack_h2(p0, p1);
                p[j * 2 + 1] = pack_h2(p2, p3);
            }
            uint32_t vf[8][2];
            #pragma unroll
            for (int g = 0; g < 4; g++)
                LDSM4T(vf[2*g][0], vf[2*g][1], vf[2*g+1][0], vf[2*g+1][1],
                       stg + OF_V + (kf * 16 + vrow) * LDK + g * 32 + vnadd);
            #pragma unroll
            for (int nd = 0; nd < 8; nd++)
                MMAH(o[nd], p, vf[nd]);
        }
        l0 += rs0; l1 += rs1;

        // Issue into stage (kt+2)%3 — disjoint from the stage read this tile;
        // overwrite of stage kt%3 (at kt+3) is ordered by the next top barrier.
        if (kt + 2 < nt) { issue_tile(kt + 2); CP_COMMIT(); }
    }

    // finalize
    l0 += __shfl_xor_sync(0xffffffffu, l0, 1);
    l0 += __shfl_xor_sync(0xffffffffu, l0, 2);
    l1 += __shfl_xor_sync(0xffffffffu, l1, 1);
    l1 += __shfl_xor_sync(0xffffffffu, l1, 2);
    const float inv0 = 1.f / l0, inv1 = 1.f / l1;

    const size_t z0 = hb + (size_t)rowg * HD_;
    const size_t z1 = z0 + (size_t)8 * HD_;
    #pragma unroll
    for (int nd = 0; nd < 8; nd++) {
        int col = nd * 8 + (lane & 3) * 2;
        *(uint32_t*)&Zh[z0 + col] = pack_h2(o[nd][0] * inv0, o[nd][1] * inv0);
        *(uint32_t*)&Zh[z1 + col] = pack_h2(o[nd][2] * inv1, o[nd][3] * inv1);
    }
}

// ---------------------------------------------------------------------------
// Launch
// ---------------------------------------------------------------------------
extern "C" void kernel_launch(void* const* d_in, const int* in_sizes, int n_in,
                              void* d_out, int out_size)
{
    const float* query = (const float*)d_in[0];
    const float* key_  = (const float*)d_in[1];
    const float* value = (const float*)d_in[2];
    const float* WQ = (const float*)d_in[4];
    const float* bQ = (const float*)d_in[5];
    const float* WK = (const float*)d_in[6];
    const float* bK = (const float*)d_in[7];
    const float* WV = (const float*)d_in[8];
    const float* bV = (const float*)d_in[9];
    const float* WO = (const float*)d_in[10];
    const float* bO = (const float*)d_in[11];
    float* out = (float*)d_out;

    __half *zh, *wt, *ih, *qh, *kh, *vh;
    cudaGetSymbolAddress((void**)&zh, g_Zh);
    cudaGetSymbolAddress((void**)&wt, g_Wt);
    cudaGetSymbolAddress((void**)&ih, g_Ih);
    cudaGetSymbolAddress((void**)&qh, g_Qh);
    cudaGetSymbolAddress((void**)&kh, g_Kh);
    cudaGetSymbolAddress((void**)&vh, g_Vh);

    const size_t MK = (size_t)M_ * K_GEMM;

    PrepCvtArgs pc;
    pc.x[0] = query; pc.x[1] = key_; pc.x[2] = value;
    pc.o[0] = ih; pc.o[1] = ih + MK; pc.o[2] = ih + 2 * MK;
    pc.W[0] = WQ; pc.W[1] = WK; pc.W[2] = WV; pc.W[3] = WO;
    pc.wt = wt;

    QkvArgs qa;
    qa.A[0] = ih; qa.A[1] = ih + MK; qa.A[2] = ih + 2 * MK;
    qa.bias[0] = bQ; qa.bias[1] = bK; qa.bias[2] = bV;
    qa.O[0] = qh; qa.O[1] = kh; qa.O[2] = vh;

    const int GEMM_SMEM = NSTAGE * STAGE_B;   // 81920
    const int ATTN_SMEM = 3 * AT_STAGE;       // 55296
    cudaFuncSetAttribute(gemm_h_pipe<0>,
                         cudaFuncAttributeMaxDynamicSharedMemorySize, GEMM_SMEM);
    cudaFuncSetAttribute(gemm_h_pipe<1>,
                         cudaFuncAttributeMaxDynamicSharedMemorySize, GEMM_SMEM);
    cudaFuncSetAttribute(flash_attn_mma,
                         cudaFuncAttributeMaxDynamicSharedMemorySize, ATTN_SMEM);

    // 1. Fused input-convert + weight-prep (one launch)
    prep_all_kernel<<<CVT_BLOCKS + 4 * 1024, 256>>>(pc);

    // 2. QKV projections (one launch, grid.z = 3)
    gemm_h_pipe<0><<<dim3(N_GEMM / 128, M_ / 128, 3), 256, GEMM_SMEM>>>(
        qa, nullptr, wt, nullptr, nullptr);

    // 3. Flash attention
    flash_attn_mma<<<dim3(S_ / 128, H_, B_), 256, ATTN_SMEM>>>(
        qh, kh, vh, zh);

    // 4. Output projection -> fp32 out
    gemm_h_pipe<1><<<dim3(N_GEMM / 128, M_ / 128, 1), 256, GEMM_SMEM>>>(
        qa, zh, wt, bO, out);
}

// round 12
// speedup vs baseline: 2.8296x; 1.1219x over previous
#include <cuda_runtime.h>
#include <cuda_fp16.h>
#include <cstdint>

// Problem constants
#define B_  2
#define S_  2048
#define E_  1024
#define H_  16
#define DH_ 64
#define HD_ 1024          // H*Dh
#define M_  (B_*S_)       // 4096 rows for all GEMMs
#define K_GEMM 1024
#define N_GEMM 1024

// ---------------------------------------------------------------------------
// Scratch (no cudaMalloc allowed)
// ---------------------------------------------------------------------------
__device__ __half g_Zh[M_ * K_GEMM];            // attention output
__device__ __half g_Wt[4 * N_GEMM * K_GEMM];    // 4 transposed weights [N][K]
__device__ __half g_Qh[M_ * HD_];
__device__ __half g_Kh[M_ * HD_];
__device__ __half g_Vh[M_ * HD_];

struct QkvArgs {
    const float* A[3];     // fp32 inputs (converted inline in MODE 0)
    const float* bias[3];
    __half* O[3];
};
struct PrepArgs { const float* W[4]; };

__device__ __forceinline__ uint32_t smem_u32(const void* p) {
    uint32_t a;
    asm("{ .reg .u64 t; cvta.to.shared.u64 t, %1; cvt.u32.u64 %0, t; }" : "=r"(a) : "l"(p));
    return a;
}
__device__ __forceinline__ float ex2f(float x) {
    float y;
    asm("ex2.approx.ftz.f32 %0, %1;" : "=f"(y) : "f"(x));
    return y;
}
__device__ __forceinline__ uint32_t pack_h2(float a, float b) {
    __half2 t = __floats2half2_rn(a, b);
    return *reinterpret_cast<uint32_t*>(&t);
}
__device__ __forceinline__ uint4 cvt8h(float4 a, float4 b) {
    uint4 r;
    r.x = pack_h2(a.x, a.y); r.y = pack_h2(a.z, a.w);
    r.z = pack_h2(b.x, b.y); r.w = pack_h2(b.z, b.w);
    return r;
}

#define CP_ASYNC16(dst, src) \
    asm volatile("cp.async.cg.shared.global [%0], [%1], 16;" :: "r"(dst), "l"(src))
#define CP_COMMIT() asm volatile("cp.async.commit_group;" ::: "memory")
#define CP_WAIT(n)  asm volatile("cp.async.wait_group %0;" :: "n"(n) : "memory")

#define LDSM4(r0, r1, r2, r3, addr) \
    asm volatile("ldmatrix.sync.aligned.m8n8.x4.shared.b16 {%0,%1,%2,%3}, [%4];" \
                 : "=r"(r0), "=r"(r1), "=r"(r2), "=r"(r3) : "r"(addr))
#define LDSM4T(r0, r1, r2, r3, addr) \
    asm volatile("ldmatrix.sync.aligned.m8n8.x4.trans.shared.b16 {%0,%1,%2,%3}, [%4];" \
                 : "=r"(r0), "=r"(r1), "=r"(r2), "=r"(r3) : "r"(addr))
#define MMAH(d, a, b) \
    asm volatile("mma.sync.aligned.m16n8k16.row.col.f32.f16.f16.f32 " \
                 "{%0,%1,%2,%3}, {%4,%5,%6,%7}, {%8,%9}, {%0,%1,%2,%3};" \
                 : "+f"((d)[0]), "+f"((d)[1]), "+f"((d)[2]), "+f"((d)[3]) \
                 : "r"((a)[0]), "r"((a)[1]), "r"((a)[2]), "r"((a)[3]), \
                   "r"((b)[0]), "r"((b)[1]))

// ---------------------------------------------------------------------------
// Weight prep (batched): W[K][N] fp32 -> Wt[z] [N][K] fp16 (transpose)
// grid 4096, block (32,8)
// ---------------------------------------------------------------------------
__global__ void __launch_bounds__(256)
prep_w_kernel(PrepArgs pa, __half* __restrict__ wt)
{
    __shared__ float t[32][33];
    int pid = blockIdx.x;
    int z = pid >> 10;
    int idx = pid & 1023;
    int n0 = (idx & 31) * 32, k0 = (idx >> 5) * 32;
    int tx = threadIdx.x, ty = threadIdx.y;
    const float* W = pa.W[z];
    const size_t zoff = (size_t)z * N_GEMM * K_GEMM;
    #pragma unroll
    for (int i = 0; i < 4; i++)
        t[ty + 8 * i][tx] = W[(size_t)(k0 + ty + 8 * i) * N_GEMM + n0 + tx];
    __syncthreads();
    #pragma unroll
    for (int i = 0; i < 4; i++) {
        float v = t[tx][ty + 8 * i];
        wt[zoff + (size_t)(n0 + ty + 8 * i) * K_GEMM + k0 + tx] = __float2half_rn(v);
    }
}

// ---------------------------------------------------------------------------
// HMMA fp16 GEMM, 3-stage ring, 2 CTAs/SM, ONE barrier/chunk.
//  MODE 0 (QKV, grid.z=3): A = fp32, converted inline (LDG->cvt->STS ring);
//                          W via cp.async. Out fp16 qa.O[z] + bias.
//  MODE 1 (O-proj): A (fp16) and W both via cp.async. Out fp32 + biasO.
// CTA 128x128, BK=32, 8 warps (4M x 2N).
// ---------------------------------------------------------------------------
#define LDP 80
#define TILE_B (128 * LDP)      // 10240
#define STAGE_B (2 * TILE_B)    // 20480 (A | W)
#define NSTAGE 3

template<int MODE>
__global__ void __launch_bounds__(256, 2)
gemm_h_pipe(QkvArgs qa,
            const __half* __restrict__ Ah_,
            const __half* __restrict__ Wbase,
            const float* __restrict__ biasO,
            float* __restrict__ Cout)
{
    extern __shared__ __align__(16) char smem[];
    const uint32_t sb = smem_u32(smem);
    const int z = blockIdx.z;
    const int tid = threadIdx.x;
    const int wid = tid >> 5, lane = tid & 31;
    const int n0 = blockIdx.x * 128, m0 = blockIdx.y * 128;
    const int mw = (wid & 3) * 32;
    const int nw = (wid >> 2) * 64;

    const size_t woff = (MODE == 0 ? (size_t)z : (size_t)3) * N_GEMM * K_GEMM;
    const __half* gW = Wbase + woff + (size_t)n0 * K_GEMM;
    const float* gAf = (MODE == 0) ? qa.A[z] + (size_t)m0 * K_GEMM : nullptr;
    const __half* gAh = (MODE == 1) ? Ah_ + (size_t)m0 * K_GEMM : nullptr;

    float acc[2][8][4];
    #pragma unroll
    for (int mi = 0; mi < 2; mi++)
        #pragma unroll
        for (int ni = 0; ni < 8; ni++)
            #pragma unroll
            for (int r = 0; r < 4; r++) acc[mi][ni][r] = 0.f;

    const int row_[2] = { tid >> 2, (tid + 256) >> 2 };
    const int cc_[2]  = { tid & 3, (tid + 256) & 3 };

    float4 pfA[2][2];   // MODE 0: fp32 A prefetch registers

    auto ldgA = [&](int c) {
        if (MODE == 0) {
            int k0 = c * 32;
            #pragma unroll
            for (int t = 0; t < 2; t++) {
                size_t go = (size_t)row_[t] * K_GEMM + k0 + cc_[t] * 8;
                pfA[t][0] = *(const float4*)&gAf[go];
                pfA[t][1] = *(const float4*)&gAf[go + 4];
            }
        }
    };
    auto stsA = [&](int c) {
        if (MODE == 0) {
            uint32_t base = sb + (c % NSTAGE) * STAGE_B;
            #pragma unroll
            for (int t = 0; t < 2; t++) {
                uint32_t so = row_[t] * LDP + cc_[t] * 16;
                *(uint4*)(smem + (base - sb) + so) = cvt8h(pfA[t][0], pfA[t][1]);
            }
        }
    };
    auto cpChunk = [&](int c) {     // W always; A too in MODE 1
        uint32_t base = sb + (c % NSTAGE) * STAGE_B;
        int k0 = c * 32;
        #pragma unroll
        for (int t = 0; t < 2; t++) {
            uint32_t so = row_[t] * LDP + cc_[t] * 16;
            size_t go = (size_t)row_[t] * K_GEMM + k0 + cc_[t] * 8;
            if (MODE == 1) CP_ASYNC16(base + 0 * TILE_B + so, gAh + go);
            CP_ASYNC16(base + 1 * TILE_B + so, gW + go);
        }
        CP_COMMIT();
    };

    const uint32_t a_row = mw + (lane & 15);
    const uint32_t a_kadd = (lane >> 4) << 4;
    const uint32_t b_rowbase = nw + (lane & 7) + (((lane >> 4) & 1) << 3);
    const uint32_t b_kadd = ((lane >> 3) & 1) << 4;

    const int NCHUNK = K_GEMM / 32;   // 32
    // Prologue: 2 chunks in flight
    ldgA(0);
    cpChunk(0);
    cpChunk(1);
    stsA(0);
    ldgA(1);

    for (int c = 0; c < NCHUNK; c++) {
        if (c + 1 < NCHUNK) { CP_WAIT(1); } else { CP_WAIT(0); }
        __syncthreads();     // stage c fully visible (STS + cp.async)

        const uint32_t stg = sb + (c % NSTAGE) * STAGE_B;
        const uint32_t sA = stg, sW = stg + TILE_B;

        #pragma unroll
        for (int s = 0; s < 2; s++) {
            const uint32_t kb = s * 32;
            uint32_t af[2][4];
            #pragma unroll
            for (int mi = 0; mi < 2; mi++)
                LDSM4(af[mi][0], af[mi][1], af[mi][2], af[mi][3],
                      sA + (a_row + mi * 16) * LDP + kb + a_kadd);
            uint32_t bf[8][2];
            #pragma unroll
            for (int g = 0; g < 4; g++)
                LDSM4(bf[2*g][0], bf[2*g][1], bf[2*g+1][0], bf[2*g+1][1],
                      sW + (b_rowbase + g * 16) * LDP + kb + b_kadd);
            #pragma unroll
            for (int mi = 0; mi < 2; mi++)
                #pragma unroll
                for (int ni = 0; ni < 8; ni++)
                    MMAH(acc[mi][ni], af[mi], bf[ni]);
        }
        // Fill stage (c+1) A (STS, disjoint from c) and stage (c+2) W (cp.async)
        if (c + 1 < NCHUNK) stsA(c + 1);
        if (c + 2 < NCHUNK) { ldgA(c + 2); cpChunk(c + 2); }
    }

    // ---- epilogue ----
    const float* bias = (MODE == 0) ? qa.bias[z] : biasO;
    const int erow = m0 + mw + (lane >> 2);
    const int ecol0 = n0 + nw + (lane & 3) * 2;
    #pragma unroll
    for (int mi = 0; mi < 2; mi++) {
        #pragma unroll
        for (int ni = 0; ni < 8; ni++) {
            int col = ecol0 + ni * 8;
            float b0 = bias[col], b1 = bias[col + 1];
            int r0 = erow + mi * 16;
            float v00 = acc[mi][ni][0] + b0, v01 = acc[mi][ni][1] + b1;
            float v10 = acc[mi][ni][2] + b0, v11 = acc[mi][ni][3] + b1;
            if (MODE == 1) {
                float2 w0 = { v00, v01 }, w1 = { v10, v11 };
                *(float2*)&Cout[(size_t)r0 * N_GEMM + col] = w0;
                *(float2*)&Cout[(size_t)(r0 + 8) * N_GEMM + col] = w1;
            } else {
                __half* Co = qa.O[z];
                *(uint32_t*)&Co[(size_t)r0 * N_GEMM + col] = pack_h2(v00, v01);
                *(uint32_t*)&Co[(size_t)(r0 + 8) * N_GEMM + col] = pack_h2(v10, v11);
            }
        }
    }
}

// ---------------------------------------------------------------------------
// HMMA fp16 flash attention, causal, online softmax (alpha folded into ex2),
// 3-stage cp.async K/V ring, ONE barrier/tile, 2 CTAs/SM, heavy-CTA-first,
// warp-vote rescale skip.
// ---------------------------------------------------------------------------
#define LDK 144
#define AT_STAGE 18432
#define OF_K 0
#define OF_V 9216

__global__ void __launch_bounds__(256, 2)
flash_attn_mma(const __half* __restrict__ Qh, const __half* __restrict__ Kh,
               const __half* __restrict__ Vh, __half* __restrict__ Zh)
{
    extern __shared__ __align__(16) char sm[];
    const uint32_t sb = smem_u32(sm);
    const int tid = threadIdx.x, wid = tid >> 5, lane = tid & 31;
    const int b = blockIdx.z, h = blockIdx.y;
    const int qt = gridDim.x - 1 - blockIdx.x;      // heavy CTAs first
    const int q0 = qt * 128;
    const size_t hb = (size_t)b * S_ * HD_ + h * DH_;

    const uint32_t arow = wid * 16 + (lane & 15);
    const uint32_t akadd = (lane >> 4) << 4;

    // Stage Q through stage-0 region via cp.async, ldmatrix into registers.
    #pragma unroll
    for (int t = 0; t < 4; t++) {
        int idx = tid + t * 256; int row = idx >> 3, cc = idx & 7;
        CP_ASYNC16(sb + row * LDK + cc * 16,
                   Qh + hb + (size_t)(q0 + row) * HD_ + cc * 8);
    }
    CP_COMMIT(); CP_WAIT(0);
    __syncthreads();
    uint32_t q[4][4];
    #pragma unroll
    for (int ks = 0; ks < 4; ks++)
        LDSM4(q[ks][0], q[ks][1], q[ks][2], q[ks][3],
              sb + arow * LDK + ks * 32 + akadd);
    __syncthreads();   // all warps done reading Q; stage 0 free

    auto issue_tile = [&](int kt) {
        uint32_t base = sb + (kt % 3) * AT_STAGE;
        int k0 = kt * 64;
        #pragma unroll
        for (int t = 0; t < 2; t++) {
            int idx = tid + t * 256; int row = idx >> 3, cc = idx & 7;
            size_t g = hb + (size_t)(k0 + row) * HD_ + cc * 8;
            uint32_t so = row * LDK + cc * 16;
            CP_ASYNC16(base + OF_K + so, Kh + g);
            CP_ASYNC16(base + OF_V + so, Vh + g);
        }
    };

    float o[8][4];
    #pragma unroll
    for (int i = 0; i < 8; i++)
        #pragma unroll
        for (int j = 0; j < 4; j++) o[i][j] = 0.f;
    float m0 = -1e30f, m1 = -1e30f, l0 = 0.f, l1 = 0.f;

    const uint32_t browbase = (lane & 7) + (((lane >> 4) & 1) << 3);
    const uint32_t bkadd = ((lane >> 3) & 1) << 4;
    const uint32_t vrow = lane & 15;
    const uint32_t vnadd = (lane >> 4) << 4;
    const float alpha = 0.125f * 1.4426950408889634f;   // 1/sqrt(64) * log2(e)
    const int rowg = q0 + wid * 16 + (lane >> 2);

    const int nt = 2 * qt + 2;    // >= 2 always
    issue_tile(0); CP_COMMIT();
    issue_tile(1); CP_COMMIT();

    for (int kt = 0; kt < nt; kt++) {
        if (kt + 1 < nt) { CP_WAIT(1); } else { CP_WAIT(0); }
        __syncthreads();       // single barrier per tile
        const uint32_t stg = sb + (kt % 3) * AT_STAGE;
        const int k0 = kt * 64;

        // S = Q K^T (raw scores; alpha applied inside ex2)
        float s[8][4];
        #pragma unroll
        for (int i = 0; i < 8; i++)
            #pragma unroll
            for (int j = 0; j < 4; j++) s[i][j] = 0.f;
        #pragma unroll
        for (int ks = 0; ks < 4; ks++) {
            uint32_t kf_[8][2];
            #pragma unroll
            for (int g = 0; g < 4; g++)
                LDSM4(kf_[2*g][0], kf_[2*g][1], kf_[2*g+1][0], kf_[2*g+1][1],
                      stg + OF_K + (browbase + g * 16) * LDK + ks * 32 + bkadd);
            #pragma unroll
            for (int ni = 0; ni < 8; ni++)
                MMAH(s[ni], q[ks], kf_[ni]);
        }

        // causal mask (raw domain)
        if (k0 + 63 > q0 + wid * 16) {
            #pragma unroll
            for (int ni = 0; ni < 8; ni++) {
                int colg = k0 + ni * 8 + (lane & 3) * 2;
                if (colg     > rowg    ) s[ni][0] = -1e30f;
                if (colg + 1 > rowg    ) s[ni][1] = -1e30f;
                if (colg     > rowg + 8) s[ni][2] = -1e30f;
                if (colg + 1 > rowg + 8) s[ni][3] = -1e30f;
            }
        }

        // online softmax (max in raw domain)
        float mx0 = m0, mx1 = m1;
        #pragma unroll
        for (int ni = 0; ni < 8; ni++) {
            mx0 = fmaxf(mx0, fmaxf(s[ni][0], s[ni][1]));
            mx1 = fmaxf(mx1, fmaxf(s[ni][2], s[ni][3]));
        }
        mx0 = fmaxf(mx0, __shfl_xor_sync(0xffffffffu, mx0, 1));
        mx0 = fmaxf(mx0, __shfl_xor_sync(0xffffffffu, mx0, 2));
        mx1 = fmaxf(mx1, __shfl_xor_sync(0xffffffffu, mx1, 1));
        mx1 = fmaxf(mx1, __shfl_xor_sync(0xffffffffu, mx1, 2));

        // warp-vote rescale skip: if no lane's max grew, sc == 1 exactly
        if (__any_sync(0xffffffffu, (mx0 > m0) || (mx1 > m1))) {
            float sc0 = ex2f((m0 - mx0) * alpha);
            float sc1 = ex2f((m1 - mx1) * alpha);
            l0 *= sc0; l1 *= sc1;
            #pragma unroll
            for (int ni = 0; ni < 8; ni++) {
                o[ni][0] *= sc0; o[ni][1] *= sc0;
                o[ni][2] *= sc1; o[ni][3] *= sc1;
            }
            m0 = mx0; m1 = mx1;
        }
        const float mxa0 = m0 * alpha, mxa1 = m1 * alpha;

        // PV: P built per kf slice via single FFMA + ex2
        float rs0 = 0.f, rs1 = 0.f;
        #pragma unroll
        for (int kf = 0; kf < 4; kf++) {
            uint32_t p[4];
            #pragma unroll
            for (int j = 0; j < 2; j++) {
                int ni = 2 * kf + j;
                float p0 = ex2f(fmaf(s[ni][0], alpha, -mxa0));
                float p1 = ex2f(fmaf(s[ni][1], alpha, -mxa0));
                float p2 = ex2f(fmaf(s[ni][2], alpha, -mxa1));
                float p3 = ex2f(fmaf(s[ni][3], alpha, -mxa1));
                rs0 += p0 + p1; rs1 += p2 + p3;
                p[j * 2 + 0] = pack_h2(p0, p1);
                p[j * 2 + 1] = pack_h2(p2, p3);
            }
            uint32_t vf[8][2];
            #pragma unroll
            for (int g = 0; g < 4; g++)
                LDSM4T(vf[2*g][0], vf[2*g][1], vf[2*g+1][0], vf[2*g+1][1],
                       stg + OF_V + (kf * 16 + vrow) * LDK + g * 32 + vnadd);
            #pragma unroll
            for (int nd = 0; nd < 8; nd++)
                MMAH(o[nd], p, vf[nd]);
        }
        l0 += rs0; l1 += rs1;

        if (kt + 2 < nt) { issue_tile(kt + 2); CP_COMMIT(); }
    }

    // finalize
    l0 += __shfl_xor_sync(0xffffffffu, l0, 1);
    l0 += __shfl_xor_sync(0xffffffffu, l0, 2);
    l1 += __shfl_xor_sync(0xffffffffu, l1, 1);
    l1 += __shfl_xor_sync(0xffffffffu, l1, 2);
    const float inv0 = 1.f / l0, inv1 = 1.f / l1;

    const size_t z0 = hb + (size_t)rowg * HD_;
    const size_t z1 = z0 + (size_t)8 * HD_;
    #pragma unroll
    for (int nd = 0; nd < 8; nd++) {
        int col = nd * 8 + (lane & 3) * 2;
        *(uint32_t*)&Zh[z0 + col] = pack_h2(o[nd][0] * inv0, o[nd][1] * inv0);
        *(uint32_t*)&Zh[z1 + col] = pack_h2(o[nd][2] * inv1, o[nd][3] * inv1);
    }
}

// ---------------------------------------------------------------------------
// Launch
// ---------------------------------------------------------------------------
extern "C" void kernel_launch(void* const* d_in, const int* in_sizes, int n_in,
                              void* d_out, int out_size)
{
    const float* query = (const float*)d_in[0];
    const float* key_  = (const float*)d_in[1];
    const float* value = (const float*)d_in[2];
    const float* WQ = (const float*)d_in[4];
    const float* bQ = (const float*)d_in[5];
    const float* WK = (const float*)d_in[6];
    const float* bK = (const float*)d_in[7];
    const float* WV = (const float*)d_in[8];
    const float* bV = (const float*)d_in[9];
    const float* WO = (const float*)d_in[10];
    const float* bO = (const float*)d_in[11];
    float* out = (float*)d_out;

    __half *zh, *wt, *qh, *kh, *vh;
    cudaGetSymbolAddress((void**)&zh, g_Zh);
    cudaGetSymbolAddress((void**)&wt, g_Wt);
    cudaGetSymbolAddress((void**)&qh, g_Qh);
    cudaGetSymbolAddress((void**)&kh, g_Kh);
    cudaGetSymbolAddress((void**)&vh, g_Vh);

    PrepArgs pp;
    pp.W[0] = WQ; pp.W[1] = WK; pp.W[2] = WV; pp.W[3] = WO;

    QkvArgs qa;
    qa.A[0] = query; qa.A[1] = key_; qa.A[2] = value;
    qa.bias[0] = bQ; qa.bias[1] = bK; qa.bias[2] = bV;
    qa.O[0] = qh; qa.O[1] = kh; qa.O[2] = vh;

    const int GEMM_SMEM = NSTAGE * STAGE_B;   // 61440
    const int ATTN_SMEM = 3 * AT_STAGE;       // 55296
    cudaFuncSetAttribute(gemm_h_pipe<0>,
                         cudaFuncAttributeMaxDynamicSharedMemorySize, GEMM_SMEM);
    cudaFuncSetAttribute(gemm_h_pipe<1>,
                         cudaFuncAttributeMaxDynamicSharedMemorySize, GEMM_SMEM);
    cudaFuncSetAttribute(flash_attn_mma,
                         cudaFuncAttributeMaxDynamicSharedMemorySize, ATTN_SMEM);

    // 1. Weight prep only (inputs converted inline in gemm<0>)
    prep_w_kernel<<<4096, dim3(32, 8)>>>(pp, wt);

    // 2. QKV projections (one launch, grid.z = 3), fp32 A converted inline
    gemm_h_pipe<0><<<dim3(N_GEMM / 128, M_ / 128, 3), 256, GEMM_SMEM>>>(
        qa, nullptr, wt, nullptr, nullptr);

    // 3. Flash attention
    flash_attn_mma<<<dim3(S_ / 128, H_, B_), 256, ATTN_SMEM>>>(
        qh, kh, vh, zh);

    // 4. Output projection -> fp32 out
    gemm_h_pipe<1><<<dim3(N_GEMM / 128, M_ / 128, 1), 256, GEMM_SMEM>>>(
        qa, zh, wt, bO, out);
}

// round 14
// speedup vs baseline: 2.8388x; 1.0033x over previous
#include <cuda_runtime.h>
#include <cuda_fp16.h>
#include <cstdint>

// Problem constants
#define B_  2
#define S_  2048
#define E_  1024
#define H_  16
#define DH_ 64
#define HD_ 1024          // H*Dh
#define M_  (B_*S_)       // 4096 rows for all GEMMs
#define K_GEMM 1024
#define N_GEMM 1024

// ---------------------------------------------------------------------------
// Scratch (no cudaMalloc allowed)
// ---------------------------------------------------------------------------
__device__ __half g_Zh[M_ * K_GEMM];            // attention output
__device__ __half g_Wt[4 * N_GEMM * K_GEMM];    // 4 transposed weights [N][K]
__device__ __half g_Qh[M_ * HD_];
__device__ __half g_Kh[M_ * HD_];
__device__ __half g_Vh[M_ * HD_];

struct QkvArgs {
    const float* A[3];     // fp32 inputs (converted inline in MODE 0)
    const float* bias[3];
    __half* O[3];
};
struct PrepArgs { const float* W[4]; };

__device__ __forceinline__ uint32_t smem_u32(const void* p) {
    uint32_t a;
    asm("{ .reg .u64 t; cvta.to.shared.u64 t, %1; cvt.u32.u64 %0, t; }" : "=r"(a) : "l"(p));
    return a;
}
__device__ __forceinline__ float ex2f(float x) {
    float y;
    asm("ex2.approx.ftz.f32 %0, %1;" : "=f"(y) : "f"(x));
    return y;
}
__device__ __forceinline__ uint32_t pack_h2(float a, float b) {
    __half2 t = __floats2half2_rn(a, b);
    return *reinterpret_cast<uint32_t*>(&t);
}
__device__ __forceinline__ uint4 cvt8h(float4 a, float4 b) {
    uint4 r;
    r.x = pack_h2(a.x, a.y); r.y = pack_h2(a.z, a.w);
    r.z = pack_h2(b.x, b.y); r.w = pack_h2(b.z, b.w);
    return r;
}

#define CP_ASYNC16(dst, src) \
    asm volatile("cp.async.cg.shared.global [%0], [%1], 16;" :: "r"(dst), "l"(src))
#define CP_COMMIT() asm volatile("cp.async.commit_group;" ::: "memory")
#define CP_WAIT(n)  asm volatile("cp.async.wait_group %0;" :: "n"(n) : "memory")

#define LDSM4(r0, r1, r2, r3, addr) \
    asm volatile("ldmatrix.sync.aligned.m8n8.x4.shared.b16 {%0,%1,%2,%3}, [%4];" \
                 : "=r"(r0), "=r"(r1), "=r"(r2), "=r"(r3) : "r"(addr))
#define LDSM4T(r0, r1, r2, r3, addr) \
    asm volatile("ldmatrix.sync.aligned.m8n8.x4.trans.shared.b16 {%0,%1,%2,%3}, [%4];" \
                 : "=r"(r0), "=r"(r1), "=r"(r2), "=r"(r3) : "r"(addr))
#define MMAH(d, a, b) \
    asm volatile("mma.sync.aligned.m16n8k16.row.col.f32.f16.f16.f32 " \
                 "{%0,%1,%2,%3}, {%4,%5,%6,%7}, {%8,%9}, {%0,%1,%2,%3};" \
                 : "+f"((d)[0]), "+f"((d)[1]), "+f"((d)[2]), "+f"((d)[3]) \
                 : "r"((a)[0]), "r"((a)[1]), "r"((a)[2]), "r"((a)[3]), \
                   "r"((b)[0]), "r"((b)[1]))

// ---------------------------------------------------------------------------
// Weight prep (batched): W[K][N] fp32 -> Wt[z] [N][K] fp16 (transpose)
// grid 4096, block (32,8)
// ---------------------------------------------------------------------------
__global__ void __launch_bounds__(256)
prep_w_kernel(PrepArgs pa, __half* __restrict__ wt)
{
    __shared__ float t[32][33];
    int pid = blockIdx.x;
    int z = pid >> 10;
    int idx = pid & 1023;
    int n0 = (idx & 31) * 32, k0 = (idx >> 5) * 32;
    int tx = threadIdx.x, ty = threadIdx.y;
    const float* W = pa.W[z];
    const size_t zoff = (size_t)z * N_GEMM * K_GEMM;
    #pragma unroll
    for (int i = 0; i < 4; i++)
        t[ty + 8 * i][tx] = W[(size_t)(k0 + ty + 8 * i) * N_GEMM + n0 + tx];
    __syncthreads();
    #pragma unroll
    for (int i = 0; i < 4; i++) {
        float v = t[tx][ty + 8 * i];
        wt[zoff + (size_t)(n0 + ty + 8 * i) * K_GEMM + k0 + tx] = __float2half_rn(v);
    }
}

// ---------------------------------------------------------------------------
// HMMA fp16 GEMM, 3-stage ring, 2 CTAs/SM, ONE barrier/chunk,
// SMEM-staged coalesced epilogue (16B-aligned pad strides).
// ---------------------------------------------------------------------------
#define LDP 80
#define TILE_B (128 * LDP)      // 10240
#define STAGE_B (2 * TILE_B)    // 20480 (A | W)
#define NSTAGE 3
#define EPI_LDH 272             // fp16 epilogue row stride (256 data + 16 pad, 16B-aligned)
#define EPI_LDF 528             // fp32 epilogue row stride (512 data + 16 pad, 16B-aligned)

template<int MODE>
__global__ void __launch_bounds__(256, 2)
gemm_h_pipe(QkvArgs qa,
            const __half* __restrict__ Ah_,
            const __half* __restrict__ Wbase,
            const float* __restrict__ biasO,
            float* __restrict__ Cout)
{
    extern __shared__ __align__(16) char smem[];
    const uint32_t sb = smem_u32(smem);
    const int z = blockIdx.z;
    const int tid = threadIdx.x;
    const int wid = tid >> 5, lane = tid & 31;
    const int n0 = blockIdx.x * 128, m0 = blockIdx.y * 128;
    const int mw = (wid & 3) * 32;
    const int nw = (wid >> 2) * 64;

    const size_t woff = (MODE == 0 ? (size_t)z : (size_t)3) * N_GEMM * K_GEMM;
    const __half* gW = Wbase + woff + (size_t)n0 * K_GEMM;
    const float* gAf = (MODE == 0) ? qa.A[z] + (size_t)m0 * K_GEMM : nullptr;
    const __half* gAh = (MODE == 1) ? Ah_ + (size_t)m0 * K_GEMM : nullptr;

    float acc[2][8][4];
    #pragma unroll
    for (int mi = 0; mi < 2; mi++)
        #pragma unroll
        for (int ni = 0; ni < 8; ni++)
            #pragma unroll
            for (int r = 0; r < 4; r++) acc[mi][ni][r] = 0.f;

    const int row_[2] = { tid >> 2, (tid + 256) >> 2 };
    const int cc_[2]  = { tid & 3, (tid + 256) & 3 };

    float4 pfA[2][2];   // MODE 0: fp32 A prefetch registers

    auto ldgA = [&](int c) {
        if (MODE == 0) {
            int k0 = c * 32;
            #pragma unroll
            for (int t = 0; t < 2; t++) {
                size_t go = (size_t)row_[t] * K_GEMM + k0 + cc_[t] * 8;
                pfA[t][0] = *(const float4*)&gAf[go];
                pfA[t][1] = *(const float4*)&gAf[go + 4];
            }
        }
    };
    auto stsA = [&](int c) {
        if (MODE == 0) {
            uint32_t base = (c % NSTAGE) * STAGE_B;
            #pragma unroll
            for (int t = 0; t < 2; t++) {
                uint32_t so = row_[t] * LDP + cc_[t] * 16;
                *(uint4*)(smem + base + so) = cvt8h(pfA[t][0], pfA[t][1]);
            }
        }
    };
    auto cpChunk = [&](int c) {     // W always; A too in MODE 1
        uint32_t base = sb + (c % NSTAGE) * STAGE_B;
        int k0 = c * 32;
        #pragma unroll
        for (int t = 0; t < 2; t++) {
            uint32_t so = row_[t] * LDP + cc_[t] * 16;
            size_t go = (size_t)row_[t] * K_GEMM + k0 + cc_[t] * 8;
            if (MODE == 1) CP_ASYNC16(base + 0 * TILE_B + so, gAh + go);
            CP_ASYNC16(base + 1 * TILE_B + so, gW + go);
        }
        CP_COMMIT();
    };

    const uint32_t a_row = mw + (lane & 15);
    const uint32_t a_kadd = (lane >> 4) << 4;
    const uint32_t b_rowbase = nw + (lane & 7) + (((lane >> 4) & 1) << 3);
    const uint32_t b_kadd = ((lane >> 3) & 1) << 4;

    const int NCHUNK = K_GEMM / 32;   // 32
    ldgA(0);
    cpChunk(0);
    cpChunk(1);
    stsA(0);
    ldgA(1);

    for (int c = 0; c < NCHUNK; c++) {
        if (c + 1 < NCHUNK) { CP_WAIT(1); } else { CP_WAIT(0); }
        __syncthreads();

        const uint32_t stg = sb + (c % NSTAGE) * STAGE_B;
        const uint32_t sA = stg, sW = stg + TILE_B;

        #pragma unroll
        for (int s = 0; s < 2; s++) {
            const uint32_t kb = s * 32;
            uint32_t af[2][4];
            #pragma unroll
            for (int mi = 0; mi < 2; mi++)
                LDSM4(af[mi][0], af[mi][1], af[mi][2], af[mi][3],
                      sA + (a_row + mi * 16) * LDP + kb + a_kadd);
            uint32_t bf[8][2];
            #pragma unroll
            for (int g = 0; g < 4; g++)
                LDSM4(bf[2*g][0], bf[2*g][1], bf[2*g+1][0], bf[2*g+1][1],
                      sW + (b_rowbase + g * 16) * LDP + kb + b_kadd);
            #pragma unroll
            for (int mi = 0; mi < 2; mi++)
                #pragma unroll
                for (int ni = 0; ni < 8; ni++)
                    MMAH(acc[mi][ni], af[mi], bf[ni]);
        }
        if (c + 1 < NCHUNK) stsA(c + 1);
        if (c + 2 < NCHUNK) { ldgA(c + 2); cpChunk(c + 2); }
    }

    // ---- epilogue: SMEM-staged, coalesced 16B stores ----
    const float* bias = (MODE == 0) ? qa.bias[z] : biasO;
    const int rl = (lane >> 2);            // 0..7
    const int cl = nw + (lane & 3) * 2;    // warp column base

    __syncthreads();   // pipeline SMEM no longer needed

    if (MODE == 0) {
        // stage 128 rows x 256 B fp16 (stride 272)
        #pragma unroll
        for (int mi = 0; mi < 2; mi++) {
            #pragma unroll
            for (int ni = 0; ni < 8; ni++) {
                int col = cl + ni * 8;
                float b0 = bias[n0 + col], b1 = bias[n0 + col + 1];
                int r0l = mw + mi * 16 + rl;
                *(uint32_t*)(smem + r0l * EPI_LDH + col * 2) =
                    pack_h2(acc[mi][ni][0] + b0, acc[mi][ni][1] + b1);
                *(uint32_t*)(smem + (r0l + 8) * EPI_LDH + col * 2) =
                    pack_h2(acc[mi][ni][2] + b0, acc[mi][ni][3] + b1);
            }
        }
        __syncthreads();
        __half* Co = qa.O[z];
        #pragma unroll
        for (int t = 0; t < 8; t++) {
            int idx = tid + t * 256;       // 0..2047
            int row = idx >> 4, seg = idx & 15;
            *(uint4*)&Co[(size_t)(m0 + row) * N_GEMM + n0 + seg * 8] =
                *(uint4*)(smem + row * EPI_LDH + seg * 16);
        }
    } else {
        // fp32: two passes of 64 rows (64 x 528 B = 33792 <= 61440)
        #pragma unroll
        for (int pass = 0; pass < 2; pass++) {
            if (pass) __syncthreads();
            if ((mw >> 6) == pass) {
                int mwl = mw & 63;
                #pragma unroll
                for (int mi = 0; mi < 2; mi++) {
                    #pragma unroll
                    for (int ni = 0; ni < 8; ni++) {
                        int col = cl + ni * 8;
                        float b0 = bias[n0 + col], b1 = bias[n0 + col + 1];
                        int r0l = mwl + mi * 16 + rl;
                        float2 v0 = { acc[mi][ni][0] + b0, acc[mi][ni][1] + b1 };
                        float2 v1 = { acc[mi][ni][2] + b0, acc[mi][ni][3] + b1 };
                        *(float2*)(smem + r0l * EPI_LDF + col * 4) = v0;
                        *(float2*)(smem + (r0l + 8) * EPI_LDF + col * 4) = v1;
                    }
                }
            }
            __syncthreads();
            #pragma unroll
            for (int t = 0; t < 8; t++) {
                int idx = tid + t * 256;   // 0..2047
                int row = idx >> 5, seg = idx & 31;
                *(uint4*)&Cout[(size_t)(m0 + pass * 64 + row) * N_GEMM + n0 + seg * 4] =
                    *(uint4*)(smem + row * EPI_LDF + seg * 16);
            }
        }
    }
}

// ---------------------------------------------------------------------------
// HMMA fp16 flash attention, causal, online softmax (alpha folded into ex2),
// 3-stage cp.async K/V ring, ONE barrier/tile, 2 CTAs/SM, heavy-CTA-first,
// warp-vote rescale skip, SMEM-staged coalesced Z write (aligned stride).
// ---------------------------------------------------------------------------
#define LDK 144
#define AT_STAGE 18432
#define OF_K 0
#define OF_V 9216
#define EPI_LDZ 144     // Z epilogue row stride (128 data + 16 pad, 16B-aligned)

__global__ void __launch_bounds__(256, 2)
flash_attn_mma(const __half* __restrict__ Qh, const __half* __restrict__ Kh,
               const __half* __restrict__ Vh, __half* __restrict__ Zh)
{
    extern __shared__ __align__(16) char sm[];
    const uint32_t sb = smem_u32(sm);
    const int tid = threadIdx.x, wid = tid >> 5, lane = tid & 31;
    const int b = blockIdx.z, h = blockIdx.y;
    const int qt = gridDim.x - 1 - blockIdx.x;      // heavy CTAs first
    const int q0 = qt * 128;
    const size_t hb = (size_t)b * S_ * HD_ + h * DH_;

    const uint32_t arow = wid * 16 + (lane & 15);
    const uint32_t akadd = (lane >> 4) << 4;

    // Stage Q through stage-0 region via cp.async, ldmatrix into registers.
    #pragma unroll
    for (int t = 0; t < 4; t++) {
        int idx = tid + t * 256; int row = idx >> 3, cc = idx & 7;
        CP_ASYNC16(sb + row * LDK + cc * 16,
                   Qh + hb + (size_t)(q0 + row) * HD_ + cc * 8);
    }
    CP_COMMIT(); CP_WAIT(0);
    __syncthreads();
    uint32_t q[4][4];
    #pragma unroll
    for (int ks = 0; ks < 4; ks++)
        LDSM4(q[ks][0], q[ks][1], q[ks][2], q[ks][3],
              sb + arow * LDK + ks * 32 + akadd);
    __syncthreads();   // all warps done reading Q; stage 0 free

    auto issue_tile = [&](int kt) {
        uint32_t base = sb + (kt % 3) * AT_STAGE;
        int k0 = kt * 64;
        #pragma unroll
        for (int t = 0; t < 2; t++) {
            int idx = tid + t * 256; int row = idx >> 3, cc = idx & 7;
            size_t g = hb + (size_t)(k0 + row) * HD_ + cc * 8;
            uint32_t so = row * LDK + cc * 16;
            CP_ASYNC16(base + OF_K + so, Kh + g);
            CP_ASYNC16(base + OF_V + so, Vh + g);
        }
    };

    float o[8][4];
    #pragma unroll
    for (int i = 0; i < 8; i++)
        #pragma unroll
        for (int j = 0; j < 4; j++) o[i][j] = 0.f;
    float m0 = -1e30f, m1 = -1e30f, l0 = 0.f, l1 = 0.f;

    const uint32_t browbase = (lane & 7) + (((lane >> 4) & 1) << 3);
    const uint32_t bkadd = ((lane >> 3) & 1) << 4;
    const uint32_t vrow = lane & 15;
    const uint32_t vnadd = (lane >> 4) << 4;
    const float alpha = 0.125f * 1.4426950408889634f;   // 1/sqrt(64) * log2(e)
    const int rowg = q0 + wid * 16 + (lane >> 2);

    const int nt = 2 * qt + 2;    // >= 2 always
    issue_tile(0); CP_COMMIT();
    issue_tile(1); CP_COMMIT();

    for (int kt = 0; kt < nt; kt++) {
        if (kt + 1 < nt) { CP_WAIT(1); } else { CP_WAIT(0); }
        __syncthreads();       // single barrier per tile
        const uint32_t stg = sb + (kt % 3) * AT_STAGE;
        const int k0 = kt * 64;

        // S = Q K^T (raw scores; alpha applied inside ex2)
        float s[8][4];
        #pragma unroll
        for (int i = 0; i < 8; i++)
            #pragma unroll
            for (int j = 0; j < 4; j++) s[i][j] = 0.f;
        #pragma unroll
        for (int ks = 0; ks < 4; ks++) {
            uint32_t kf_[8][2];
            #pragma unroll
            for (int g = 0; g < 4; g++)
                LDSM4(kf_[2*g][0], kf_[2*g][1], kf_[2*g+1][0], kf_[2*g+1][1],
                      stg + OF_K + (browbase + g * 16) * LDK + ks * 32 + bkadd);
            #pragma unroll
            for (int ni = 0; ni < 8; ni++)
                MMAH(s[ni], q[ks], kf_[ni]);
        }

        // causal mask (raw domain)
        if (k0 + 63 > q0 + wid * 16) {
            #pragma unroll
            for (int ni = 0; ni < 8; ni++) {
                int colg = k0 + ni * 8 + (lane & 3) * 2;
                if (colg     > rowg    ) s[ni][0] = -1e30f;
                if (colg + 1 > rowg    ) s[ni][1] = -1e30f;
                if (colg     > rowg + 8) s[ni][2] = -1e30f;
                if (colg + 1 > rowg + 8) s[ni][3] = -1e30f;
            }
        }

        // online softmax (max in raw domain)
        float mx0 = m0, mx1 = m1;
        #pragma unroll
        for (int ni = 0; ni < 8; ni++) {
            mx0 = fmaxf(mx0, fmaxf(s[ni][0], s[ni][1]));
            mx1 = fmaxf(mx1, fmaxf(s[ni][2], s[ni][3]));
        }
        mx0 = fmaxf(mx0, __shfl_xor_sync(0xffffffffu, mx0, 1));
        mx0 = fmaxf(mx0, __shfl_xor_sync(0xffffffffu, mx0, 2));
        mx1 = fmaxf(mx1, __shfl_xor_sync(0xffffffffu, mx1, 1));
        mx1 = fmaxf(mx1, __shfl_xor_sync(0xffffffffu, mx1, 2));

        // warp-vote rescale skip: if no lane's max grew, sc == 1 exactly
        if (__any_sync(0xffffffffu, (mx0 > m0) || (mx1 > m1))) {
            float sc0 = ex2f((m0 - mx0) * alpha);
            float sc1 = ex2f((m1 - mx1) * alpha);
            l0 *= sc0; l1 *= sc1;
            #pragma unroll
            for (int ni = 0; ni < 8; ni++) {
                o[ni][0] *= sc0; o[ni][1] *= sc0;
                o[ni][2] *= sc1; o[ni][3] *= sc1;
            }
            m0 = mx0; m1 = mx1;
        }
        const float mxa0 = m0 * alpha, mxa1 = m1 * alpha;

        // PV: P built per kf slice via single FFMA + ex2
        float rs0 = 0.f, rs1 = 0.f;
        #pragma unroll
        for (int kf = 0; kf < 4; kf++) {
            uint32_t p[4];
            #pragma unroll
            for (int j = 0; j < 2; j++) {
                int ni = 2 * kf + j;
                float p0 = ex2f(fmaf(s[ni][0], alpha, -mxa0));
                float p1 = ex2f(fmaf(s[ni][1], alpha, -mxa0));
                float p2 = ex2f(fmaf(s[ni][2], alpha, -mxa1));
                float p3 = ex2f(fmaf(s[ni][3], alpha, -mxa1));
                rs0 += p0 + p1; rs1 += p2 + p3;
                p[j * 2 + 0] = pack_h2(p0, p1);
                p[j * 2 + 1] = pack_h2(p2, p3);
            }
            uint32_t vf[8][2];
            #pragma unroll
            for (int g = 0; g < 4; g++)
                LDSM4T(vf[2*g][0], vf[2*g][1], vf[2*g+1][0], vf[2*g+1][1],
                       stg + OF_V + (kf * 16 + vrow) * LDK + g * 32 + vnadd);
            #pragma unroll
            for (int nd = 0; nd < 8; nd++)
                MMAH(o[nd], p, vf[nd]);
        }
        l0 += rs0; l1 += rs1;

        if (kt + 2 < nt) { issue_tile(kt + 2); CP_COMMIT(); }
    }

    // finalize
    l0 += __shfl_xor_sync(0xffffffffu, l0, 1);
    l0 += __shfl_xor_sync(0xffffffffu, l0, 2);
    l1 += __shfl_xor_sync(0xffffffffu, l1, 1);
    l1 += __shfl_xor_sync(0xffffffffu, l1, 2);
    const float inv0 = 1.f / l0, inv1 = 1.f / l1;

    // SMEM-staged coalesced Z write: 128 rows x 128 B (stride 144)
    __syncthreads();   // all warps done with K/V stages
    const int r0l = wid * 16 + (lane >> 2);
    #pragma unroll
    for (int nd = 0; nd < 8; nd++) {
        int col = nd * 8 + (lane & 3) * 2;
        *(uint32_t*)(sm + r0l * EPI_LDZ + col * 2) =
            pack_h2(o[nd][0] * inv0, o[nd][1] * inv0);
        *(uint32_t*)(sm + (r0l + 8) * EPI_LDZ + col * 2) =
            pack_h2(o[nd][2] * inv1, o[nd][3] * inv1);
    }
    __syncthreads();
    #pragma unroll
    for (int t = 0; t < 4; t++) {
        int idx = tid + t * 256;   // 0..1023
        int row = idx >> 3, seg = idx & 7;
        *(uint4*)&Zh[hb + (size_t)(q0 + row) * HD_ + seg * 8] =
            *(uint4*)(sm + row * EPI_LDZ + seg * 16);
    }
}

// ---------------------------------------------------------------------------
// Launch
// ---------------------------------------------------------------------------
extern "C" void kernel_launch(void* const* d_in, const int* in_sizes, int n_in,
                              void* d_out, int out_size)
{
    const float* query = (const float*)d_in[0];
    const float* key_  = (const float*)d_in[1];
    const float* value = (const float*)d_in[2];
    const float* WQ = (const float*)d_in[4];
    const float* bQ = (const float*)d_in[5];
    const float* WK = (const float*)d_in[6];
    const float* bK = (const float*)d_in[7];
    const float* WV = (const float*)d_in[8];
    const float* bV = (const float*)d_in[9];
    const float* WO = (const float*)d_in[10];
    const float* bO = (const float*)d_in[11];
    float* out = (float*)d_out;

    __half *zh, *wt, *qh, *kh, *vh;
    cudaGetSymbolAddress((void**)&zh, g_Zh);
    cudaGetSymbolAddress((void**)&wt, g_Wt);
    cudaGetSymbolAddress((void**)&qh, g_Qh);
    cudaGetSymbolAddress((void**)&kh, g_Kh);
    cudaGetSymbolAddress((void**)&vh, g_Vh);

    PrepArgs pp;
    pp.W[0] = WQ; pp.W[1] = WK; pp.W[2] = WV; pp.W[3] = WO;

    QkvArgs qa;
    qa.A[0] = query; qa.A[1] = key_; qa.A[2] = value;
    qa.bias[0] = bQ; qa.bias[1] = bK; qa.bias[2] = bV;
    qa.O[0] = qh; qa.O[1] = kh; qa.O[2] = vh;

    const int GEMM_SMEM = NSTAGE * STAGE_B;   // 61440
    const int ATTN_SMEM = 3 * AT_STAGE;       // 55296
    cudaFuncSetAttribute(gemm_h_pipe<0>,
                         cudaFuncAttributeMaxDynamicSharedMemorySize, GEMM_SMEM);
    cudaFuncSetAttribute(gemm_h_pipe<1>,
                         cudaFuncAttributeMaxDynamicSharedMemorySize, GEMM_SMEM);
    cudaFuncSetAttribute(flash_attn_mma,
                         cudaFuncAttributeMaxDynamicSharedMemorySize, ATTN_SMEM);

    // 1. Weight prep only (inputs converted inline in gemm<0>)
    prep_w_kernel<<<4096, dim3(32, 8)>>>(pp, wt);

    // 2. QKV projections (one launch, grid.z = 3), fp32 A converted inline
    gemm_h_pipe<0><<<dim3(N_GEMM / 128, M_ / 128, 3), 256, GEMM_SMEM>>>(
        qa, nullptr, wt, nullptr, nullptr);

    // 3. Flash attention
    flash_attn_mma<<<dim3(S_ / 128, H_, B_), 256, ATTN_SMEM>>>(
        qh, kh, vh, zh);

    // 4. Output projection -> fp32 out
    gemm_h_pipe<1><<<dim3(N_GEMM / 128, M_ / 128, 1), 256, GEMM_SMEM>>>(
        qa, zh, wt, bO, out);
}

// round 15
// speedup vs baseline: 2.9364x; 1.0344x over previous
#include <cuda_runtime.h>
#include <cuda_fp16.h>
#include <cstdint>

// Problem constants
#define B_  2
#define S_  2048
#define E_  1024
#define H_  16
#define DH_ 64
#define HD_ 1024          // H*Dh
#define M_  (B_*S_)       // 4096 rows for all GEMMs
#define K_GEMM 1024
#define N_GEMM 1024

// ---------------------------------------------------------------------------
// Scratch (no cudaMalloc allowed)
// ---------------------------------------------------------------------------
__device__ __half g_Zh[M_ * K_GEMM];            // attention output
__device__ __half g_Wt[4 * N_GEMM * K_GEMM];    // 4 transposed weights [N][K]
__device__ __half g_Qh[M_ * HD_];
__device__ __half g_Kh[M_ * HD_];
__device__ __half g_Vh[M_ * HD_];

struct QkvArgs {
    const float* A[3];     // fp32 inputs (converted inline in MODE 0)
    const float* bias[3];
    __half* O[3];
};
struct PrepArgs { const float* W[4]; };

__device__ __forceinline__ uint32_t smem_u32(const void* p) {
    uint32_t a;
    asm("{ .reg .u64 t; cvta.to.shared.u64 t, %1; cvt.u32.u64 %0, t; }" : "=r"(a) : "l"(p));
    return a;
}
__device__ __forceinline__ float ex2f(float x) {
    float y;
    asm("ex2.approx.ftz.f32 %0, %1;" : "=f"(y) : "f"(x));
    return y;
}
__device__ __forceinline__ uint32_t pack_h2(float a, float b) {
    __half2 t = __floats2half2_rn(a, b);
    return *reinterpret_cast<uint32_t*>(&t);
}
__device__ __forceinline__ uint4 cvt8h(float4 a, float4 b) {
    uint4 r;
    r.x = pack_h2(a.x, a.y); r.y = pack_h2(a.z, a.w);
    r.z = pack_h2(b.x, b.y); r.w = pack_h2(b.z, b.w);
    return r;
}

#define CP_ASYNC16(dst, src) \
    asm volatile("cp.async.cg.shared.global [%0], [%1], 16;" :: "r"(dst), "l"(src))
#define CP_COMMIT() asm volatile("cp.async.commit_group;" ::: "memory")
#define CP_WAIT(n)  asm volatile("cp.async.wait_group %0;" :: "n"(n) : "memory")

#define LDSM4(r0, r1, r2, r3, addr) \
    asm volatile("ldmatrix.sync.aligned.m8n8.x4.shared.b16 {%0,%1,%2,%3}, [%4];" \
                 : "=r"(r0), "=r"(r1), "=r"(r2), "=r"(r3) : "r"(addr))
#define LDSM4T(r0, r1, r2, r3, addr) \
    asm volatile("ldmatrix.sync.aligned.m8n8.x4.trans.shared.b16 {%0,%1,%2,%3}, [%4];" \
                 : "=r"(r0), "=r"(r1), "=r"(r2), "=r"(r3) : "r"(addr))
#define MMAH(d, a, b) \
    asm volatile("mma.sync.aligned.m16n8k16.row.col.f32.f16.f16.f32 " \
                 "{%0,%1,%2,%3}, {%4,%5,%6,%7}, {%8,%9}, {%0,%1,%2,%3};" \
                 : "+f"((d)[0]), "+f"((d)[1]), "+f"((d)[2]), "+f"((d)[3]) \
                 : "r"((a)[0]), "r"((a)[1]), "r"((a)[2]), "r"((a)[3]), \
                   "r"((b)[0]), "r"((b)[1]))

// ---------------------------------------------------------------------------
// Weight prep (batched): W[K][N] fp32 -> Wt[z] [N][K] fp16 (transpose)
// grid 4096, block (32,8)
// ---------------------------------------------------------------------------
__global__ void __launch_bounds__(256)
prep_w_kernel(PrepArgs pa, __half* __restrict__ wt)
{
    __shared__ float t[32][33];
    int pid = blockIdx.x;
    int z = pid >> 10;
    int idx = pid & 1023;
    int n0 = (idx & 31) * 32, k0 = (idx >> 5) * 32;
    int tx = threadIdx.x, ty = threadIdx.y;
    const float* W = pa.W[z];
    const size_t zoff = (size_t)z * N_GEMM * K_GEMM;
    #pragma unroll
    for (int i = 0; i < 4; i++)
        t[ty + 8 * i][tx] = W[(size_t)(k0 + ty + 8 * i) * N_GEMM + n0 + tx];
    __syncthreads();
    #pragma unroll
    for (int i = 0; i < 4; i++) {
        float v = t[tx][ty + 8 * i];
        wt[zoff + (size_t)(n0 + ty + 8 * i) * K_GEMM + k0 + tx] = __float2half_rn(v);
    }
}

// ---------------------------------------------------------------------------
// HMMA fp16 GEMM, 3-stage ring, 2 CTAs/SM, ONE barrier/chunk,
// SMEM-staged coalesced epilogue. (unchanged from R14)
// ---------------------------------------------------------------------------
#define LDP 80
#define TILE_B (128 * LDP)      // 10240
#define STAGE_B (2 * TILE_B)    // 20480 (A | W)
#define NSTAGE 3
#define EPI_LDH 272
#define EPI_LDF 528

template<int MODE>
__global__ void __launch_bounds__(256, 2)
gemm_h_pipe(QkvArgs qa,
            const __half* __restrict__ Ah_,
            const __half* __restrict__ Wbase,
            const float* __restrict__ biasO,
            float* __restrict__ Cout)
{
    extern __shared__ __align__(16) char smem[];
    const uint32_t sb = smem_u32(smem);
    const int z = blockIdx.z;
    const int tid = threadIdx.x;
    const int wid = tid >> 5, lane = tid & 31;
    const int n0 = blockIdx.x * 128, m0 = blockIdx.y * 128;
    const int mw = (wid & 3) * 32;
    const int nw = (wid >> 2) * 64;

    const size_t woff = (MODE == 0 ? (size_t)z : (size_t)3) * N_GEMM * K_GEMM;
    const __half* gW = Wbase + woff + (size_t)n0 * K_GEMM;
    const float* gAf = (MODE == 0) ? qa.A[z] + (size_t)m0 * K_GEMM : nullptr;
    const __half* gAh = (MODE == 1) ? Ah_ + (size_t)m0 * K_GEMM : nullptr;

    float acc[2][8][4];
    #pragma unroll
    for (int mi = 0; mi < 2; mi++)
        #pragma unroll
        for (int ni = 0; ni < 8; ni++)
            #pragma unroll
            for (int r = 0; r < 4; r++) acc[mi][ni][r] = 0.f;

    const int row_[2] = { tid >> 2, (tid + 256) >> 2 };
    const int cc_[2]  = { tid & 3, (tid + 256) & 3 };

    float4 pfA[2][2];

    auto ldgA = [&](int c) {
        if (MODE == 0) {
            int k0 = c * 32;
            #pragma unroll
            for (int t = 0; t < 2; t++) {
                size_t go = (size_t)row_[t] * K_GEMM + k0 + cc_[t] * 8;
                pfA[t][0] = *(const float4*)&gAf[go];
                pfA[t][1] = *(const float4*)&gAf[go + 4];
            }
        }
    };
    auto stsA = [&](int c) {
        if (MODE == 0) {
            uint32_t base = (c % NSTAGE) * STAGE_B;
            #pragma unroll
            for (int t = 0; t < 2; t++) {
                uint32_t so = row_[t] * LDP + cc_[t] * 16;
                *(uint4*)(smem + base + so) = cvt8h(pfA[t][0], pfA[t][1]);
            }
        }
    };
    auto cpChunk = [&](int c) {
        uint32_t base = sb + (c % NSTAGE) * STAGE_B;
        int k0 = c * 32;
        #pragma unroll
        for (int t = 0; t < 2; t++) {
            uint32_t so = row_[t] * LDP + cc_[t] * 16;
            size_t go = (size_t)row_[t] * K_GEMM + k0 + cc_[t] * 8;
            if (MODE == 1) CP_ASYNC16(base + 0 * TILE_B + so, gAh + go);
            CP_ASYNC16(base + 1 * TILE_B + so, gW + go);
        }
        CP_COMMIT();
    };

    const uint32_t a_row = mw + (lane & 15);
    const uint32_t a_kadd = (lane >> 4) << 4;
    const uint32_t b_rowbase = nw + (lane & 7) + (((lane >> 4) & 1) << 3);
    const uint32_t b_kadd = ((lane >> 3) & 1) << 4;

    const int NCHUNK = K_GEMM / 32;
    ldgA(0);
    cpChunk(0);
    cpChunk(1);
    stsA(0);
    ldgA(1);

    for (int c = 0; c < NCHUNK; c++) {
        if (c + 1 < NCHUNK) { CP_WAIT(1); } else { CP_WAIT(0); }
        __syncthreads();

        const uint32_t stg = sb + (c % NSTAGE) * STAGE_B;
        const uint32_t sA = stg, sW = stg + TILE_B;

        #pragma unroll
        for (int s = 0; s < 2; s++) {
            const uint32_t kb = s * 32;
            uint32_t af[2][4];
            #pragma unroll
            for (int mi = 0; mi < 2; mi++)
                LDSM4(af[mi][0], af[mi][1], af[mi][2], af[mi][3],
                      sA + (a_row + mi * 16) * LDP + kb + a_kadd);
            uint32_t bf[8][2];
            #pragma unroll
            for (int g = 0; g < 4; g++)
                LDSM4(bf[2*g][0], bf[2*g][1], bf[2*g+1][0], bf[2*g+1][1],
                      sW + (b_rowbase + g * 16) * LDP + kb + b_kadd);
            #pragma unroll
            for (int mi = 0; mi < 2; mi++)
                #pragma unroll
                for (int ni = 0; ni < 8; ni++)
                    MMAH(acc[mi][ni], af[mi], bf[ni]);
        }
        if (c + 1 < NCHUNK) stsA(c + 1);
        if (c + 2 < NCHUNK) { ldgA(c + 2); cpChunk(c + 2); }
    }

    // ---- epilogue: SMEM-staged, coalesced 16B stores ----
    const float* bias = (MODE == 0) ? qa.bias[z] : biasO;
    const int rl = (lane >> 2);
    const int cl = nw + (lane & 3) * 2;

    __syncthreads();

    if (MODE == 0) {
        #pragma unroll
        for (int mi = 0; mi < 2; mi++) {
            #pragma unroll
            for (int ni = 0; ni < 8; ni++) {
                int col = cl + ni * 8;
                float b0 = bias[n0 + col], b1 = bias[n0 + col + 1];
                int r0l = mw + mi * 16 + rl;
                *(uint32_t*)(smem + r0l * EPI_LDH + col * 2) =
                    pack_h2(acc[mi][ni][0] + b0, acc[mi][ni][1] + b1);
                *(uint32_t*)(smem + (r0l + 8) * EPI_LDH + col * 2) =
                    pack_h2(acc[mi][ni][2] + b0, acc[mi][ni][3] + b1);
            }
        }
        __syncthreads();
        __half* Co = qa.O[z];
        #pragma unroll
        for (int t = 0; t < 8; t++) {
            int idx = tid + t * 256;
            int row = idx >> 4, seg = idx & 15;
            *(uint4*)&Co[(size_t)(m0 + row) * N_GEMM + n0 + seg * 8] =
                *(uint4*)(smem + row * EPI_LDH + seg * 16);
        }
    } else {
        #pragma unroll
        for (int pass = 0; pass < 2; pass++) {
            if (pass) __syncthreads();
            if ((mw >> 6) == pass) {
                int mwl = mw & 63;
                #pragma unroll
                for (int mi = 0; mi < 2; mi++) {
                    #pragma unroll
                    for (int ni = 0; ni < 8; ni++) {
                        int col = cl + ni * 8;
                        float b0 = bias[n0 + col], b1 = bias[n0 + col + 1];
                        int r0l = mwl + mi * 16 + rl;
                        float2 v0 = { acc[mi][ni][0] + b0, acc[mi][ni][1] + b1 };
                        float2 v1 = { acc[mi][ni][2] + b0, acc[mi][ni][3] + b1 };
                        *(float2*)(smem + r0l * EPI_LDF + col * 4) = v0;
                        *(float2*)(smem + (r0l + 8) * EPI_LDF + col * 4) = v1;
                    }
                }
            }
            __syncthreads();
            #pragma unroll
            for (int t = 0; t < 8; t++) {
                int idx = tid + t * 256;
                int row = idx >> 5, seg = idx & 31;
                *(uint4*)&Cout[(size_t)(m0 + pass * 64 + row) * N_GEMM + n0 + seg * 4] =
                    *(uint4*)(smem + row * EPI_LDF + seg * 16);
            }
        }
    }
}

// ---------------------------------------------------------------------------
// HMMA fp16 flash attention, causal. Q-TILE 64 ROWS, 128 threads (4 warps),
// 4 CTAs/SM -> halved critical chain per CTA. 3-stage cp.async K/V ring,
// ONE barrier/tile, heavy-CTA-first, warp-vote rescale skip, coalesced Z.
// grid (S/64 = 32, H, B) = 1024 CTAs. SMEM/CTA = 3 x 18432 = 55296.
// ---------------------------------------------------------------------------
#define LDK 144
#define AT_STAGE 18432
#define OF_K 0
#define OF_V 9216
#define EPI_LDZ 144

__global__ void __launch_bounds__(128, 4)
flash_attn_mma(const __half* __restrict__ Qh, const __half* __restrict__ Kh,
               const __half* __restrict__ Vh, __half* __restrict__ Zh)
{
    extern __shared__ __align__(16) char sm[];
    const uint32_t sb = smem_u32(sm);
    const int tid = threadIdx.x, wid = tid >> 5, lane = tid & 31;
    const int b = blockIdx.z, h = blockIdx.y;
    const int qt = gridDim.x - 1 - blockIdx.x;      // heavy CTAs first
    const int q0 = qt * 64;
    const size_t hb = (size_t)b * S_ * HD_ + h * DH_;

    const uint32_t arow = wid * 16 + (lane & 15);
    const uint32_t akadd = (lane >> 4) << 4;

    // Stage Q (64 rows x 128B) through stage-0 region via cp.async.
    #pragma unroll
    for (int t = 0; t < 4; t++) {
        int idx = tid + t * 128; int row = idx >> 3, cc = idx & 7;
        CP_ASYNC16(sb + row * LDK + cc * 16,
                   Qh + hb + (size_t)(q0 + row) * HD_ + cc * 8);
    }
    CP_COMMIT(); CP_WAIT(0);
    __syncthreads();
    uint32_t q[4][4];
    #pragma unroll
    for (int ks = 0; ks < 4; ks++)
        LDSM4(q[ks][0], q[ks][1], q[ks][2], q[ks][3],
              sb + arow * LDK + ks * 32 + akadd);
    __syncthreads();   // all warps done reading Q; stage 0 free

    auto issue_tile = [&](int kt) {
        uint32_t base = sb + (kt % 3) * AT_STAGE;
        int k0 = kt * 64;
        #pragma unroll
        for (int t = 0; t < 4; t++) {
            int idx = tid + t * 128; int row = idx >> 3, cc = idx & 7;
            size_t g = hb + (size_t)(k0 + row) * HD_ + cc * 8;
            uint32_t so = row * LDK + cc * 16;
            CP_ASYNC16(base + OF_K + so, Kh + g);
            CP_ASYNC16(base + OF_V + so, Vh + g);
        }
    };

    float o[8][4];
    #pragma unroll
    for (int i = 0; i < 8; i++)
        #pragma unroll
        for (int j = 0; j < 4; j++) o[i][j] = 0.f;
    float m0 = -1e30f, m1 = -1e30f, l0 = 0.f, l1 = 0.f;

    const uint32_t browbase = (lane & 7) + (((lane >> 4) & 1) << 3);
    const uint32_t bkadd = ((lane >> 3) & 1) << 4;
    const uint32_t vrow = lane & 15;
    const uint32_t vnadd = (lane >> 4) << 4;
    const float alpha = 0.125f * 1.4426950408889634f;   // 1/sqrt(64) * log2(e)
    const int rowg = q0 + wid * 16 + (lane >> 2);

    const int nt = qt + 1;    // 64-key tiles (>= 1)
    issue_tile(0); CP_COMMIT();
    if (nt > 1) { issue_tile(1); CP_COMMIT(); }
    else        { CP_COMMIT(); }   // keep group count consistent

    for (int kt = 0; kt < nt; kt++) {
        if (kt + 1 < nt) { CP_WAIT(1); } else { CP_WAIT(0); }
        __syncthreads();       // single barrier per tile
        const uint32_t stg = sb + (kt % 3) * AT_STAGE;
        const int k0 = kt * 64;

        // S = Q K^T (raw scores; alpha applied inside ex2)
        float s[8][4];
        #pragma unroll
        for (int i = 0; i < 8; i++)
            #pragma unroll
            for (int j = 0; j < 4; j++) s[i][j] = 0.f;
        #pragma unroll
        for (int ks = 0; ks < 4; ks++) {
            uint32_t kf_[8][2];
            #pragma unroll
            for (int g = 0; g < 4; g++)
                LDSM4(kf_[2*g][0], kf_[2*g][1], kf_[2*g+1][0], kf_[2*g+1][1],
                      stg + OF_K + (browbase + g * 16) * LDK + ks * 32 + bkadd);
            #pragma unroll
            for (int ni = 0; ni < 8; ni++)
                MMAH(s[ni], q[ks], kf_[ni]);
        }

        // causal mask (raw domain)
        if (k0 + 63 > q0 + wid * 16) {
            #pragma unroll
            for (int ni = 0; ni < 8; ni++) {
                int colg = k0 + ni * 8 + (lane & 3) * 2;
                if (colg     > rowg    ) s[ni][0] = -1e30f;
                if (colg + 1 > rowg    ) s[ni][1] = -1e30f;
                if (colg     > rowg + 8) s[ni][2] = -1e30f;
                if (colg + 1 > rowg + 8) s[ni][3] = -1e30f;
            }
        }

        // online softmax (max in raw domain)
        float mx0 = m0, mx1 = m1;
        #pragma unroll
        for (int ni = 0; ni < 8; ni++) {
            mx0 = fmaxf(mx0, fmaxf(s[ni][0], s[ni][1]));
            mx1 = fmaxf(mx1, fmaxf(s[ni][2], s[ni][3]));
        }
        mx0 = fmaxf(mx0, __shfl_xor_sync(0xffffffffu, mx0, 1));
        mx0 = fmaxf(mx0, __shfl_xor_sync(0xffffffffu, mx0, 2));
        mx1 = fmaxf(mx1, __shfl_xor_sync(0xffffffffu, mx1, 1));
        mx1 = fmaxf(mx1, __shfl_xor_sync(0xffffffffu, mx1, 2));

        // warp-vote rescale skip: if no lane's max grew, sc == 1 exactly
        if (__any_sync(0xffffffffu, (mx0 > m0) || (mx1 > m1))) {
            float sc0 = ex2f((m0 - mx0) * alpha);
            float sc1 = ex2f((m1 - mx1) * alpha);
            l0 *= sc0; l1 *= sc1;
            #pragma unroll
            for (int ni = 0; ni < 8; ni++) {
                o[ni][0] *= sc0; o[ni][1] *= sc0;
                o[ni][2] *= sc1; o[ni][3] *= sc1;
            }
            m0 = mx0; m1 = mx1;
        }
        const float mxa0 = m0 * alpha, mxa1 = m1 * alpha;

        // PV: P built per kf slice via single FFMA + ex2
        float rs0 = 0.f, rs1 = 0.f;
        #pragma unroll
        for (int kf = 0; kf < 4; kf++) {
            uint32_t p[4];
            #pragma unroll
            for (int j = 0; j < 2; j++) {
                int ni = 2 * kf + j;
                float p0 = ex2f(fmaf(s[ni][0], alpha, -mxa0));
                float p1 = ex2f(fmaf(s[ni][1], alpha, -mxa0));
                float p2 = ex2f(fmaf(s[ni][2], alpha, -mxa1));
                float p3 = ex2f(fmaf(s[ni][3], alpha, -mxa1));
                rs0 += p0 + p1; rs1 += p2 + p3;
                p[j * 2 + 0] = pack_h2(p0, p1);
                p[j * 2 + 1] = pack_h2(p2, p3);
            }
            uint32_t vf[8][2];
            #pragma unroll
            for (int g = 0; g < 4; g++)
                LDSM4T(vf[2*g][0], vf[2*g][1], vf[2*g+1][0], vf[2*g+1][1],
                       stg + OF_V + (kf * 16 + vrow) * LDK + g * 32 + vnadd);
            #pragma unroll
            for (int nd = 0; nd < 8; nd++)
                MMAH(o[nd], p, vf[nd]);
        }
        l0 += rs0; l1 += rs1;

        if (kt + 2 < nt) { issue_tile(kt + 2); CP_COMMIT(); }
    }

    // finalize
    l0 += __shfl_xor_sync(0xffffffffu, l0, 1);
    l0 += __shfl_xor_sync(0xffffffffu, l0, 2);
    l1 += __shfl_xor_sync(0xffffffffu, l1, 1);
    l1 += __shfl_xor_sync(0xffffffffu, l1, 2);
    const float inv0 = 1.f / l0, inv1 = 1.f / l1;

    // SMEM-staged coalesced Z write: 64 rows x 128 B (stride 144)
    __syncthreads();
    const int r0l = wid * 16 + (lane >> 2);
    #pragma unroll
    for (int nd = 0; nd < 8; nd++) {
        int col = nd * 8 + (lane & 3) * 2;
        *(uint32_t*)(sm + r0l * EPI_LDZ + col * 2) =
            pack_h2(o[nd][0] * inv0, o[nd][1] * inv0);
        *(uint32_t*)(sm + (r0l + 8) * EPI_LDZ + col * 2) =
            pack_h2(o[nd][2] * inv1, o[nd][3] * inv1);
    }
    __syncthreads();
    #pragma unroll
    for (int t = 0; t < 4; t++) {
        int idx = tid + t * 128;   // 0..511
        int row = idx >> 3, seg = idx & 7;
        *(uint4*)&Zh[hb + (size_t)(q0 + row) * HD_ + seg * 8] =
            *(uint4*)(sm + row * EPI_LDZ + seg * 16);
    }
}

// ---------------------------------------------------------------------------
// Launch
// ---------------------------------------------------------------------------
extern "C" void kernel_launch(void* const* d_in, const int* in_sizes, int n_in,
                              void* d_out, int out_size)
{
    const float* query = (const float*)d_in[0];
    const float* key_  = (const float*)d_in[1];
    const float* value = (const float*)d_in[2];
    const float* WQ = (const float*)d_in[4];
    const float* bQ = (const float*)d_in[5];
    const float* WK = (const float*)d_in[6];
    const float* bK = (const float*)d_in[7];
    const float* WV = (const float*)d_in[8];
    const float* bV = (const float*)d_in[9];
    const float* WO = (const float*)d_in[10];
    const float* bO = (const float*)d_in[11];
    float* out = (float*)d_out;

    __half *zh, *wt, *qh, *kh, *vh;
    cudaGetSymbolAddress((void**)&zh, g_Zh);
    cudaGetSymbolAddress((void**)&wt, g_Wt);
    cudaGetSymbolAddress((void**)&qh, g_Qh);
    cudaGetSymbolAddress((void**)&kh, g_Kh);
    cudaGetSymbolAddress((void**)&vh, g_Vh);

    PrepArgs pp;
    pp.W[0] = WQ; pp.W[1] = WK; pp.W[2] = WV; pp.W[3] = WO;

    QkvArgs qa;
    qa.A[0] = query; qa.A[1] = key_; qa.A[2] = value;
    qa.bias[0] = bQ; qa.bias[1] = bK; qa.bias[2] = bV;
    qa.O[0] = qh; qa.O[1] = kh; qa.O[2] = vh;

    const int GEMM_SMEM = NSTAGE * STAGE_B;   // 61440
    const int ATTN_SMEM = 3 * AT_STAGE;       // 55296
    cudaFuncSetAttribute(gemm_h_pipe<0>,
                         cudaFuncAttributeMaxDynamicSharedMemorySize, GEMM_SMEM);
    cudaFuncSetAttribute(gemm_h_pipe<1>,
                         cudaFuncAttributeMaxDynamicSharedMemorySize, GEMM_SMEM);
    cudaFuncSetAttribute(flash_attn_mma,
                         cudaFuncAttributeMaxDynamicSharedMemorySize, ATTN_SMEM);

    // 1. Weight prep only (inputs converted inline in gemm<0>)
    prep_w_kernel<<<4096, dim3(32, 8)>>>(pp, wt);

    // 2. QKV projections (one launch, grid.z = 3), fp32 A converted inline
    gemm_h_pipe<0><<<dim3(N_GEMM / 128, M_ / 128, 3), 256, GEMM_SMEM>>>(
        qa, nullptr, wt, nullptr, nullptr);

    // 3. Flash attention (64-row q-tiles, 4 CTAs/SM)
    flash_attn_mma<<<dim3(S_ / 64, H_, B_), 128, ATTN_SMEM>>>(
        qh, kh, vh, zh);

    // 4. Output projection -> fp32 out
    gemm_h_pipe<1><<<dim3(N_GEMM / 128, M_ / 128, 1), 256, GEMM_SMEM>>>(
        qa, zh, wt, bO, out);
}

// round 16
// speedup vs baseline: 2.9594x; 1.0078x over previous
#include <cuda_runtime.h>
#include <cuda_fp16.h>
#include <cstdint>

// Problem constants
#define B_  2
#define S_  2048
#define E_  1024
#define H_  16
#define DH_ 64
#define HD_ 1024          // H*Dh
#define M_  (B_*S_)       // 4096 rows for all GEMMs
#define K_GEMM 1024
#define N_GEMM 1024

// ---------------------------------------------------------------------------
// Scratch (no cudaMalloc allowed)
// ---------------------------------------------------------------------------
__device__ __half g_Zh[M_ * K_GEMM];            // attention output
__device__ __half g_Wt[4 * N_GEMM * K_GEMM];    // 4 transposed weights [N][K]
__device__ __half g_Qh[M_ * HD_];
__device__ __half g_Kh[M_ * HD_];
__device__ __half g_Vh[M_ * HD_];

struct QkvArgs {
    const float* A[3];     // fp32 inputs (converted inline in MODE 0)
    const float* bias[3];
    __half* O[3];
};
struct PrepArgs { const float* W[4]; };

__device__ __forceinline__ uint32_t smem_u32(const void* p) {
    uint32_t a;
    asm("{ .reg .u64 t; cvta.to.shared.u64 t, %1; cvt.u32.u64 %0, t; }" : "=r"(a) : "l"(p));
    return a;
}
__device__ __forceinline__ float ex2f(float x) {
    float y;
    asm("ex2.approx.ftz.f32 %0, %1;" : "=f"(y) : "f"(x));
    return y;
}
__device__ __forceinline__ uint32_t pack_h2(float a, float b) {
    __half2 t = __floats2half2_rn(a, b);
    return *reinterpret_cast<uint32_t*>(&t);
}
__device__ __forceinline__ uint4 cvt8h(float4 a, float4 b) {
    uint4 r;
    r.x = pack_h2(a.x, a.y); r.y = pack_h2(a.z, a.w);
    r.z = pack_h2(b.x, b.y); r.w = pack_h2(b.z, b.w);
    return r;
}

#define CP_ASYNC16(dst, src) \
    asm volatile("cp.async.cg.shared.global [%0], [%1], 16;" :: "r"(dst), "l"(src))
#define CP_COMMIT() asm volatile("cp.async.commit_group;" ::: "memory")
#define CP_WAIT(n)  asm volatile("cp.async.wait_group %0;" :: "n"(n) : "memory")

#define LDSM4(r0, r1, r2, r3, addr) \
    asm volatile("ldmatrix.sync.aligned.m8n8.x4.shared.b16 {%0,%1,%2,%3}, [%4];" \
                 : "=r"(r0), "=r"(r1), "=r"(r2), "=r"(r3) : "r"(addr))
#define LDSM4T(r0, r1, r2, r3, addr) \
    asm volatile("ldmatrix.sync.aligned.m8n8.x4.trans.shared.b16 {%0,%1,%2,%3}, [%4];" \
                 : "=r"(r0), "=r"(r1), "=r"(r2), "=r"(r3) : "r"(addr))
#define MMAH(d, a, b) \
    asm volatile("mma.sync.aligned.m16n8k16.row.col.f32.f16.f16.f32 " \
                 "{%0,%1,%2,%3}, {%4,%5,%6,%7}, {%8,%9}, {%0,%1,%2,%3};" \
                 : "+f"((d)[0]), "+f"((d)[1]), "+f"((d)[2]), "+f"((d)[3]) \
                 : "r"((a)[0]), "r"((a)[1]), "r"((a)[2]), "r"((a)[3]), \
                   "r"((b)[0]), "r"((b)[1]))

// ---------------------------------------------------------------------------
// Weight prep (batched): W[K][N] fp32 -> Wt[z] [N][K] fp16 (transpose)
// grid 4096, block (32,8)
// ---------------------------------------------------------------------------
__global__ void __launch_bounds__(256)
prep_w_kernel(PrepArgs pa, __half* __restrict__ wt)
{
    __shared__ float t[32][33];
    int pid = blockIdx.x;
    int z = pid >> 10;
    int idx = pid & 1023;
    int n0 = (idx & 31) * 32, k0 = (idx >> 5) * 32;
    int tx = threadIdx.x, ty = threadIdx.y;
    const float* W = pa.W[z];
    const size_t zoff = (size_t)z * N_GEMM * K_GEMM;
    #pragma unroll
    for (int i = 0; i < 4; i++)
        t[ty + 8 * i][tx] = W[(size_t)(k0 + ty + 8 * i) * N_GEMM + n0 + tx];
    __syncthreads();
    #pragma unroll
    for (int i = 0; i < 4; i++) {
        float v = t[tx][ty + 8 * i];
        wt[zoff + (size_t)(n0 + ty + 8 * i) * K_GEMM + k0 + tx] = __float2half_rn(v);
    }
}

// ---------------------------------------------------------------------------
// HMMA fp16 GEMM, 3-stage ring, 2 CTAs/SM, ONE barrier/chunk,
// SMEM-staged coalesced epilogue. (unchanged from R14)
// ---------------------------------------------------------------------------
#define LDP 80
#define TILE_B (128 * LDP)      // 10240
#define STAGE_B (2 * TILE_B)    // 20480 (A | W)
#define NSTAGE 3
#define EPI_LDH 272
#define EPI_LDF 528

template<int MODE>
__global__ void __launch_bounds__(256, 2)
gemm_h_pipe(QkvArgs qa,
            const __half* __restrict__ Ah_,
            const __half* __restrict__ Wbase,
            const float* __restrict__ biasO,
            float* __restrict__ Cout)
{
    extern __shared__ __align__(16) char smem[];
    const uint32_t sb = smem_u32(smem);
    const int z = blockIdx.z;
    const int tid = threadIdx.x;
    const int wid = tid >> 5, lane = tid & 31;
    const int n0 = blockIdx.x * 128, m0 = blockIdx.y * 128;
    const int mw = (wid & 3) * 32;
    const int nw = (wid >> 2) * 64;

    const size_t woff = (MODE == 0 ? (size_t)z : (size_t)3) * N_GEMM * K_GEMM;
    const __half* gW = Wbase + woff + (size_t)n0 * K_GEMM;
    const float* gAf = (MODE == 0) ? qa.A[z] + (size_t)m0 * K_GEMM : nullptr;
    const __half* gAh = (MODE == 1) ? Ah_ + (size_t)m0 * K_GEMM : nullptr;

    float acc[2][8][4];
    #pragma unroll
    for (int mi = 0; mi < 2; mi++)
        #pragma unroll
        for (int ni = 0; ni < 8; ni++)
            #pragma unroll
            for (int r = 0; r < 4; r++) acc[mi][ni][r] = 0.f;

    const int row_[2] = { tid >> 2, (tid + 256) >> 2 };
    const int cc_[2]  = { tid & 3, (tid + 256) & 3 };

    float4 pfA[2][2];

    auto ldgA = [&](int c) {
        if (MODE == 0) {
            int k0 = c * 32;
            #pragma unroll
            for (int t = 0; t < 2; t++) {
                size_t go = (size_t)row_[t] * K_GEMM + k0 + cc_[t] * 8;
                pfA[t][0] = *(const float4*)&gAf[go];
                pfA[t][1] = *(const float4*)&gAf[go + 4];
            }
        }
    };
    auto stsA = [&](int c) {
        if (MODE == 0) {
            uint32_t base = (c % NSTAGE) * STAGE_B;
            #pragma unroll
            for (int t = 0; t < 2; t++) {
                uint32_t so = row_[t] * LDP + cc_[t] * 16;
                *(uint4*)(smem + base + so) = cvt8h(pfA[t][0], pfA[t][1]);
            }
        }
    };
    auto cpChunk = [&](int c) {
        uint32_t base = sb + (c % NSTAGE) * STAGE_B;
        int k0 = c * 32;
        #pragma unroll
        for (int t = 0; t < 2; t++) {
            uint32_t so = row_[t] * LDP + cc_[t] * 16;
            size_t go = (size_t)row_[t] * K_GEMM + k0 + cc_[t] * 8;
            if (MODE == 1) CP_ASYNC16(base + 0 * TILE_B + so, gAh + go);
            CP_ASYNC16(base + 1 * TILE_B + so, gW + go);
        }
        CP_COMMIT();
    };

    const uint32_t a_row = mw + (lane & 15);
    const uint32_t a_kadd = (lane >> 4) << 4;
    const uint32_t b_rowbase = nw + (lane & 7) + (((lane >> 4) & 1) << 3);
    const uint32_t b_kadd = ((lane >> 3) & 1) << 4;

    const int NCHUNK = K_GEMM / 32;
    ldgA(0);
    cpChunk(0);
    cpChunk(1);
    stsA(0);
    ldgA(1);

    for (int c = 0; c < NCHUNK; c++) {
        if (c + 1 < NCHUNK) { CP_WAIT(1); } else { CP_WAIT(0); }
        __syncthreads();

        const uint32_t stg = sb + (c % NSTAGE) * STAGE_B;
        const uint32_t sA = stg, sW = stg + TILE_B;

        #pragma unroll
        for (int s = 0; s < 2; s++) {
            const uint32_t kb = s * 32;
            uint32_t af[2][4];
            #pragma unroll
            for (int mi = 0; mi < 2; mi++)
                LDSM4(af[mi][0], af[mi][1], af[mi][2], af[mi][3],
                      sA + (a_row + mi * 16) * LDP + kb + a_kadd);
            uint32_t bf[8][2];
            #pragma unroll
            for (int g = 0; g < 4; g++)
                LDSM4(bf[2*g][0], bf[2*g][1], bf[2*g+1][0], bf[2*g+1][1],
                      sW + (b_rowbase + g * 16) * LDP + kb + b_kadd);
            #pragma unroll
            for (int mi = 0; mi < 2; mi++)
                #pragma unroll
                for (int ni = 0; ni < 8; ni++)
                    MMAH(acc[mi][ni], af[mi], bf[ni]);
        }
        if (c + 1 < NCHUNK) stsA(c + 1);
        if (c + 2 < NCHUNK) { ldgA(c + 2); cpChunk(c + 2); }
    }

    // ---- epilogue: SMEM-staged, coalesced 16B stores ----
    const float* bias = (MODE == 0) ? qa.bias[z] : biasO;
    const int rl = (lane >> 2);
    const int cl = nw + (lane & 3) * 2;

    __syncthreads();

    if (MODE == 0) {
        #pragma unroll
        for (int mi = 0; mi < 2; mi++) {
            #pragma unroll
            for (int ni = 0; ni < 8; ni++) {
                int col = cl + ni * 8;
                float b0 = bias[n0 + col], b1 = bias[n0 + col + 1];
                int r0l = mw + mi * 16 + rl;
                *(uint32_t*)(smem + r0l * EPI_LDH + col * 2) =
                    pack_h2(acc[mi][ni][0] + b0, acc[mi][ni][1] + b1);
                *(uint32_t*)(smem + (r0l + 8) * EPI_LDH + col * 2) =
                    pack_h2(acc[mi][ni][2] + b0, acc[mi][ni][3] + b1);
            }
        }
        __syncthreads();
        __half* Co = qa.O[z];
        #pragma unroll
        for (int t = 0; t < 8; t++) {
            int idx = tid + t * 256;
            int row = idx >> 4, seg = idx & 15;
            *(uint4*)&Co[(size_t)(m0 + row) * N_GEMM + n0 + seg * 8] =
                *(uint4*)(smem + row * EPI_LDH + seg * 16);
        }
    } else {
        #pragma unroll
        for (int pass = 0; pass < 2; pass++) {
            if (pass) __syncthreads();
            if ((mw >> 6) == pass) {
                int mwl = mw & 63;
                #pragma unroll
                for (int mi = 0; mi < 2; mi++) {
                    #pragma unroll
                    for (int ni = 0; ni < 8; ni++) {
                        int col = cl + ni * 8;
                        float b0 = bias[n0 + col], b1 = bias[n0 + col + 1];
                        int r0l = mwl + mi * 16 + rl;
                        float2 v0 = { acc[mi][ni][0] + b0, acc[mi][ni][1] + b1 };
                        float2 v1 = { acc[mi][ni][2] + b0, acc[mi][ni][3] + b1 };
                        *(float2*)(smem + r0l * EPI_LDF + col * 4) = v0;
                        *(float2*)(smem + (r0l + 8) * EPI_LDF + col * 4) = v1;
                    }
                }
            }
            __syncthreads();
            #pragma unroll
            for (int t = 0; t < 8; t++) {
                int idx = tid + t * 256;
                int row = idx >> 5, seg = idx & 31;
                *(uint4*)&Cout[(size_t)(m0 + pass * 64 + row) * N_GEMM + n0 + seg * 4] =
                    *(uint4*)(smem + row * EPI_LDF + seg * 16);
            }
        }
    }
}

// ---------------------------------------------------------------------------
// HMMA fp16 flash attention, causal. Q-TILE 64 ROWS, 128 threads (4 warps),
// 4 CTAs/SM -> halved critical chain per CTA. 3-stage cp.async K/V ring,
// ONE barrier/tile, heavy-CTA-first, warp-vote rescale skip, coalesced Z.
// grid (S/64 = 32, H, B) = 1024 CTAs. SMEM/CTA = 3 x 18432 = 55296.
// ---------------------------------------------------------------------------
#define LDK 144
#define AT_STAGE 18432
#define OF_K 0
#define OF_V 9216
#define EPI_LDZ 144

__global__ void __launch_bounds__(128, 4)
flash_attn_mma(const __half* __restrict__ Qh, const __half* __restrict__ Kh,
               const __half* __restrict__ Vh, __half* __restrict__ Zh)
{
    extern __shared__ __align__(16) char sm[];
    const uint32_t sb = smem_u32(sm);
    const int tid = threadIdx.x, wid = tid >> 5, lane = tid & 31;
    const int b = blockIdx.z, h = blockIdx.y;
    const int qt = gridDim.x - 1 - blockIdx.x;      // heavy CTAs first
    const int q0 = qt * 64;
    const size_t hb = (size_t)b * S_ * HD_ + h * DH_;

    const uint32_t arow = wid * 16 + (lane & 15);
    const uint32_t akadd = (lane >> 4) << 4;

    // Stage Q (64 rows x 128B) through stage-0 region via cp.async.
    #pragma unroll
    for (int t = 0; t < 4; t++) {
        int idx = tid + t * 128; int row = idx >> 3, cc = idx & 7;
        CP_ASYNC16(sb + row * LDK + cc * 16,
                   Qh + hb + (size_t)(q0 + row) * HD_ + cc * 8);
    }
    CP_COMMIT(); CP_WAIT(0);
    __syncthreads();
    uint32_t q[4][4];
    #pragma unroll
    for (int ks = 0; ks < 4; ks++)
        LDSM4(q[ks][0], q[ks][1], q[ks][2], q[ks][3],
              sb + arow * LDK + ks * 32 + akadd);
    __syncthreads();   // all warps done reading Q; stage 0 free

    auto issue_tile = [&](int kt) {
        uint32_t base = sb + (kt % 3) * AT_STAGE;
        int k0 = kt * 64;
        #pragma unroll
        for (int t = 0; t < 4; t++) {
            int idx = tid + t * 128; int row = idx >> 3, cc = idx & 7;
            size_t g = hb + (size_t)(k0 + row) * HD_ + cc * 8;
            uint32_t so = row * LDK + cc * 16;
            CP_ASYNC16(base + OF_K + so, Kh + g);
            CP_ASYNC16(base + OF_V + so, Vh + g);
        }
    };

    float o[8][4];
    #pragma unroll
    for (int i = 0; i < 8; i++)
        #pragma unroll
        for (int j = 0; j < 4; j++) o[i][j] = 0.f;
    float m0 = -1e30f, m1 = -1e30f, l0 = 0.f, l1 = 0.f;

    const uint32_t browbase = (lane & 7) + (((lane >> 4) & 1) << 3);
    const uint32_t bkadd = ((lane >> 3) & 1) << 4;
    const uint32_t vrow = lane & 15;
    const uint32_t vnadd = (lane >> 4) << 4;
    const float alpha = 0.125f * 1.4426950408889634f;   // 1/sqrt(64) * log2(e)
    const int rowg = q0 + wid * 16 + (lane >> 2);

    const int nt = qt + 1;    // 64-key tiles (>= 1)
    issue_tile(0); CP_COMMIT();
    if (nt > 1) { issue_tile(1); CP_COMMIT(); }
    else        { CP_COMMIT(); }   // keep group count consistent

    for (int kt = 0; kt < nt; kt++) {
        if (kt + 1 < nt) { CP_WAIT(1); } else { CP_WAIT(0); }
        __syncthreads();       // single barrier per tile
        const uint32_t stg = sb + (kt % 3) * AT_STAGE;
        const int k0 = kt * 64;

        // S = Q K^T (raw scores; alpha applied inside ex2)
        float s[8][4];
        #pragma unroll
        for (int i = 0; i < 8; i++)
            #pragma unroll
            for (int j = 0; j < 4; j++) s[i][j] = 0.f;
        #pragma unroll
        for (int ks = 0; ks < 4; ks++) {
            uint32_t kf_[8][2];
            #pragma unroll
            for (int g = 0; g < 4; g++)
                LDSM4(kf_[2*g][0], kf_[2*g][1], kf_[2*g+1][0], kf_[2*g+1][1],
                      stg + OF_K + (browbase + g * 16) * LDK + ks * 32 + bkadd);
            #pragma unroll
            for (int ni = 0; ni < 8; ni++)
                MMAH(s[ni], q[ks], kf_[ni]);
        }

        // causal mask (raw domain)
        if (k0 + 63 > q0 + wid * 16) {
            #pragma unroll
            for (int ni = 0; ni < 8; ni++) {
                int colg = k0 + ni * 8 + (lane & 3) * 2;
                if (colg     > rowg    ) s[ni][0] = -1e30f;
                if (colg + 1 > rowg    ) s[ni][1] = -1e30f;
                if (colg     > rowg + 8) s[ni][2] = -1e30f;
                if (colg + 1 > rowg + 8) s[ni][3] = -1e30f;
            }
        }

        // online softmax (max in raw domain)
        float mx0 = m0, mx1 = m1;
        #pragma unroll
        for (int ni = 0; ni < 8; ni++) {
            mx0 = fmaxf(mx0, fmaxf(s[ni][0], s[ni][1]));
            mx1 = fmaxf(mx1, fmaxf(s[ni][2], s[ni][3]));
        }
        mx0 = fmaxf(mx0, __shfl_xor_sync(0xffffffffu, mx0, 1));
        mx0 = fmaxf(mx0, __shfl_xor_sync(0xffffffffu, mx0, 2));
        mx1 = fmaxf(mx1, __shfl_xor_sync(0xffffffffu, mx1, 1));
        mx1 = fmaxf(mx1, __shfl_xor_sync(0xffffffffu, mx1, 2));

        // warp-vote rescale skip: if no lane's max grew, sc == 1 exactly
        if (__any_sync(0xffffffffu, (mx0 > m0) || (mx1 > m1))) {
            float sc0 = ex2f((m0 - mx0) * alpha);
            float sc1 = ex2f((m1 - mx1) * alpha);
            l0 *= sc0; l1 *= sc1;
            #pragma unroll
            for (int ni = 0; ni < 8; ni++) {
                o[ni][0] *= sc0; o[ni][1] *= sc0;
                o[ni][2] *= sc1; o[ni][3] *= sc1;
            }
            m0 = mx0; m1 = mx1;
        }
        const float mxa0 = m0 * alpha, mxa1 = m1 * alpha;

        // PV: P built per kf slice via single FFMA + ex2
        float rs0 = 0.f, rs1 = 0.f;
        #pragma unroll
        for (int kf = 0; kf < 4; kf++) {
            uint32_t p[4];
            #pragma unroll
            for (int j = 0; j < 2; j++) {
                int ni = 2 * kf + j;
                float p0 = ex2f(fmaf(s[ni][0], alpha, -mxa0));
                float p1 = ex2f(fmaf(s[ni][1], alpha, -mxa0));
                float p2 = ex2f(fmaf(s[ni][2], alpha, -mxa1));
                float p3 = ex2f(fmaf(s[ni][3], alpha, -mxa1));
                rs0 += p0 + p1; rs1 += p2 + p3;
                p[j * 2 + 0] = pack_h2(p0, p1);
                p[j * 2 + 1] = pack_h2(p2, p3);
            }
            uint32_t vf[8][2];
            #pragma unroll
            for (int g = 0; g < 4; g++)
                LDSM4T(vf[2*g][0], vf[2*g][1], vf[2*g+1][0], vf[2*g+1][1],
                       stg + OF_V + (kf * 16 + vrow) * LDK + g * 32 + vnadd);
            #pragma unroll
            for (int nd = 0; nd < 8; nd++)
                MMAH(o[nd], p, vf[nd]);
        }
        l0 += rs0; l1 += rs1;

        if (kt + 2 < nt) { issue_tile(kt + 2); CP_COMMIT(); }
    }

    // finalize
    l0 += __shfl_xor_sync(0xffffffffu, l0, 1);
    l0 += __shfl_xor_sync(0xffffffffu, l0, 2);
    l1 += __shfl_xor_sync(0xffffffffu, l1, 1);
    l1 += __shfl_xor_sync(0xffffffffu, l1, 2);
    const float inv0 = 1.f / l0, inv1 = 1.f / l1;

    // SMEM-staged coalesced Z write: 64 rows x 128 B (stride 144)
    __syncthreads();
    const int r0l = wid * 16 + (lane >> 2);
    #pragma unroll
    for (int nd = 0; nd < 8; nd++) {
        int col = nd * 8 + (lane & 3) * 2;
        *(uint32_t*)(sm + r0l * EPI_LDZ + col * 2) =
            pack_h2(o[nd][0] * inv0, o[nd][1] * inv0);
        *(uint32_t*)(sm + (r0l + 8) * EPI_LDZ + col * 2) =
            pack_h2(o[nd][2] * inv1, o[nd][3] * inv1);
    }
    __syncthreads();
    #pragma unroll
    for (int t = 0; t < 4; t++) {
        int idx = tid + t * 128;   // 0..511
        int row = idx >> 3, seg = idx & 7;
        *(uint4*)&Zh[hb + (size_t)(q0 + row) * HD_ + seg * 8] =
            *(uint4*)(sm + row * EPI_LDZ + seg * 16);
    }
}

// ---------------------------------------------------------------------------
// Launch
// ---------------------------------------------------------------------------
extern "C" void kernel_launch(void* const* d_in, const int* in_sizes, int n_in,
                              void* d_out, int out_size)
{
    const float* query = (const float*)d_in[0];
    const float* key_  = (const float*)d_in[1];
    const float* value = (const float*)d_in[2];
    const float* WQ = (const float*)d_in[4];
    const float* bQ = (const float*)d_in[5];
    const float* WK = (const float*)d_in[6];
    const float* bK = (const float*)d_in[7];
    const float* WV = (const float*)d_in[8];
    const float* bV = (const float*)d_in[9];
    const float* WO = (const float*)d_in[10];
    const float* bO = (const float*)d_in[11];
    float* out = (float*)d_out;

    __half *zh, *wt, *qh, *kh, *vh;
    cudaGetSymbolAddress((void**)&zh, g_Zh);
    cudaGetSymbolAddress((void**)&wt, g_Wt);
    cudaGetSymbolAddress((void**)&qh, g_Qh);
    cudaGetSymbolAddress((void**)&kh, g_Kh);
    cudaGetSymbolAddress((void**)&vh, g_Vh);

    PrepArgs pp;
    pp.W[0] = WQ; pp.W[1] = WK; pp.W[2] = WV; pp.W[3] = WO;

    QkvArgs qa;
    qa.A[0] = query; qa.A[1] = key_; qa.A[2] = value;
    qa.bias[0] = bQ; qa.bias[1] = bK; qa.bias[2] = bV;
    qa.O[0] = qh; qa.O[1] = kh; qa.O[2] = vh;

    const int GEMM_SMEM = NSTAGE * STAGE_B;   // 61440
    const int ATTN_SMEM = 3 * AT_STAGE;       // 55296
    cudaFuncSetAttribute(gemm_h_pipe<0>,
                         cudaFuncAttributeMaxDynamicSharedMemorySize, GEMM_SMEM);
    cudaFuncSetAttribute(gemm_h_pipe<1>,
                         cudaFuncAttributeMaxDynamicSharedMemorySize, GEMM_SMEM);
    cudaFuncSetAttribute(flash_attn_mma,
                         cudaFuncAttributeMaxDynamicSharedMemorySize, ATTN_SMEM);

    // 1. Weight prep only (inputs converted inline in gemm<0>)
    prep_w_kernel<<<4096, dim3(32, 8)>>>(pp, wt);

    // 2. QKV projections (one launch, grid.z = 3), fp32 A converted inline
    gemm_h_pipe<0><<<dim3(N_GEMM / 128, M_ / 128, 3), 256, GEMM_SMEM>>>(
        qa, nullptr, wt, nullptr, nullptr);

    // 3. Flash attention (64-row q-tiles, 4 CTAs/SM)
    flash_attn_mma<<<dim3(S_ / 64, H_, B_), 128, ATTN_SMEM>>>(
        qh, kh, vh, zh);

    // 4. Output projection -> fp32 out
    gemm_h_pipe<1><<<dim3(N_GEMM / 128, M_ / 128, 1), 256, GEMM_SMEM>>>(
        qa, zh, wt, bO, out);
}